// round 12
// baseline (speedup 1.0000x reference)
#include <cuda_runtime.h>
#include <math.h>

#define NP 160000
#define NN 10000
#define FD 32
#define NH 7
#define NC 224
#define NRBF 50

// ---------------- scratch (device globals: allocation-free) ----------------
__device__ float g_hedgeR[NP * FD];         // row-major [p][f]
__device__ float g_logits[NP * NH];
__device__ float g_att[NP * NH];
__device__ float g_dir[NP * 3];
__device__ float g_xmix[NP * NC];
__device__ int   g_counts[NN];
__device__ int   g_cursor[NN];
__device__ int   g_offsets[NN + 1];
__device__ int   g_order[NP];
__device__ int   g_bsum[40];
__device__ int   g_boff[40];

// pre-split edge weights: float2(hi, lo), tf32-rounded fp32 bit patterns
__device__ float2 g_w1[64 * 56];
__device__ float2 g_w2a[64 * 32];
__device__ float2 g_w2b[56 * 32];
__device__ float2 g_w3[32 * 32];
__device__ float2 g_w4[32 * 8];

__device__ __forceinline__ float siluf(float z) { return z / (1.0f + __expf(-z)); }
__device__ __forceinline__ float ftanh(float z) {
    float e = __expf(2.0f * z);
    return 1.0f - __fdividef(2.0f, e + 1.0f);
}

// tf32 helpers
__device__ __forceinline__ void split_tf32(float f, unsigned& hi, unsigned& lo) {
    asm("cvt.rna.tf32.f32 %0, %1;" : "=r"(hi) : "f"(f));
    float rem = f - __uint_as_float(hi);
    asm("cvt.rna.tf32.f32 %0, %1;" : "=r"(lo) : "f"(rem));
}
__device__ __forceinline__ void mma_tf32(float c[4], const unsigned a[4], const unsigned b[2]) {
    asm("mma.sync.aligned.m16n8k8.row.col.f32.tf32.tf32.f32 "
        "{%0,%1,%2,%3}, {%4,%5,%6,%7}, {%8,%9}, {%0,%1,%2,%3};"
        : "+f"(c[0]), "+f"(c[1]), "+f"(c[2]), "+f"(c[3])
        : "r"(a[0]), "r"(a[1]), "r"(a[2]), "r"(a[3]), "r"(b[0]), "r"(b[1]));
}
__device__ __forceinline__ void load_a_split(const float* base, int stride, int r0,
                                             int kg, int grp, int tg,
                                             unsigned Ah[4], unsigned Al[4]) {
    float a0 = base[(r0 + grp) * stride + kg + tg];
    float a1 = base[(r0 + grp + 8) * stride + kg + tg];
    float a2 = base[(r0 + grp) * stride + kg + tg + 4];
    float a3 = base[(r0 + grp + 8) * stride + kg + tg + 4];
    split_tf32(a0, Ah[0], Al[0]);
    split_tf32(a1, Ah[1], Al[1]);
    split_tf32(a2, Ah[2], Al[2]);
    split_tf32(a3, Ah[3], Al[3]);
}
__device__ __forceinline__ void mma3v(float C[4], const unsigned Ah[4], const unsigned Al[4],
                                      const unsigned Bh[2], const unsigned Bl[2]) {
    mma_tf32(C, Ah, Bh);
    mma_tf32(C, Ah, Bl);
    mma_tf32(C, Al, Bh);
}

// ---------------- weight pre-split prep ----------------
__device__ __forceinline__ float2 sp2(float v) {
    unsigned hi, lo; split_tf32(v, hi, lo);
    return make_float2(__uint_as_float(hi), __uint_as_float(lo));
}
__global__ void wsplit_kernel(const float* __restrict__ wmlp, const float* __restrict__ we1,
                              const float* __restrict__ we2,  const float* __restrict__ watt) {
    int t = blockIdx.x * 256 + threadIdx.x;
    if (t < 3584) {                       // w1 [64][56]
        int k = t / 56, n = t - k * 56;
        g_w1[t] = sp2((n < NRBF) ? wmlp[k * NRBF + n] : 0.0f);
    } else if (t < 5632) {                // w2a [64][32]
        int i = t - 3584;
        g_w2a[i] = sp2(we1[i]);
    } else if (t < 7424) {                // w2b [56][32]
        int i = t - 5632;
        int k = i >> 5, n = i & 31;
        float v = (k < NRBF) ? we1[(64 + k) * FD + n]
                : ((k == NRBF) ? we1[114 * FD + n] : 0.0f);
        g_w2b[i] = sp2(v);
    } else if (t < 8448) {                // w3 [32][32]
        int i = t - 7424;
        g_w3[i] = sp2(we2[i]);
    } else if (t < 8704) {                // w4 [32][8]
        int i = t - 8448;
        int k = i >> 3, n = i & 7;
        g_w4[i] = sp2((n < NH) ? watt[k * NH + n] : 0.0f);
    }
}

// ---------------- CSR build ----------------
__global__ void zero_kernel() {
    int i = blockIdx.x * 256 + threadIdx.x;
    if (i < NN) { g_counts[i] = 0; g_cursor[i] = 0; }
}

__global__ void count_kernel(const int* __restrict__ pl) {
    int p = blockIdx.x * 256 + threadIdx.x;
    if (p < NP) atomicAdd(&g_counts[pl[p]], 1);
}

// multi-block scan: 40 blocks x 256
__global__ void scan1_kernel() {
    __shared__ int sh[256];
    int b = blockIdx.x, t = threadIdx.x, idx = b * 256 + t;
    int v = (idx < NN) ? g_counts[idx] : 0;
    sh[t] = v;
    __syncthreads();
    #pragma unroll
    for (int off = 1; off < 256; off <<= 1) {
        int a = (t >= off) ? sh[t - off] : 0;
        __syncthreads();
        sh[t] += a;
        __syncthreads();
    }
    if (idx < NN) g_offsets[idx + 1] = sh[t];
    if (t == 255) g_bsum[b] = sh[255];
    if (b == 0 && t == 0) g_offsets[0] = 0;
}
__global__ void scan2_kernel() {   // 1 block, 64 threads
    __shared__ int sh[64];
    int t = threadIdx.x;
    int v = (t < 40) ? g_bsum[t] : 0;
    sh[t] = v;
    __syncthreads();
    #pragma unroll
    for (int off = 1; off < 64; off <<= 1) {
        int a = (t >= off) ? sh[t - off] : 0;
        __syncthreads();
        sh[t] += a;
        __syncthreads();
    }
    if (t < 40) g_boff[t] = sh[t] - v;   // exclusive of own block
}
__global__ void scan3_kernel() {
    int b = blockIdx.x, idx = b * 256 + threadIdx.x;
    if (idx < NN) g_offsets[idx + 1] += g_boff[b];
}

__global__ void scatter_kernel(const int* __restrict__ pl) {
    int p = blockIdx.x * 256 + threadIdx.x;
    if (p < NP) {
        int i = pl[p];
        int pos = g_offsets[i] + atomicAdd(&g_cursor[i], 1);
        g_order[pos] = p;
    }
}

// ---------------- edge model: tensor-core MLP, fused stage1+2a ------------
#define ACTS 68
#define FBS  60
__global__ void __launch_bounds__(128, 3) edge_kernel(
    const float* __restrict__ h, const float* __restrict__ x,
    const int* __restrict__ pl,
    const float* __restrict__ bmlp, const float* __restrict__ be1,
    const float* __restrict__ be2,  const float* __restrict__ batt)
{
    extern __shared__ float smem[];
    float* act  = smem;                    // [128][68]
    float* fbuf = act + 128 * ACTS;        // [128][60]
    float* dvec = fbuf + 128 * FBS;        // [128]
    float* s_bm = dvec + 128;              // [56]
    float* s_b1 = s_bm + 56;               // [32]
    float* s_b2 = s_b1 + 32;               // [32]
    float* s_ba = s_b2 + 32;               // [8]

    int tid = threadIdx.x;
    int p0 = blockIdx.x * 128;

    if (tid < 56) s_bm[tid] = (tid < NRBF) ? bmlp[tid] : 0.0f;
    if (tid < 32) { s_b1[tid] = be1[tid]; s_b2[tid] = be2[tid]; }
    if (tid < 8)  s_ba[tid] = (tid < NH) ? batt[tid] : 0.0f;

    // stage h_cat + d + dir: thread per pair
    {
        int m = tid, p = p0 + m;
        int i = pl[p], j = pl[NP + p];
        const float4* si = (const float4*)(h + i * FD);
        const float4* sj = (const float4*)(h + j * FD);
        float4* dst = (float4*)(act + m * ACTS);
        #pragma unroll
        for (int q = 0; q < 8; q++) dst[q] = si[q];
        #pragma unroll
        for (int q = 0; q < 8; q++) dst[8 + q] = sj[q];

        float r0 = x[j*3]   - x[i*3];
        float r1 = x[j*3+1] - x[i*3+1];
        float r2 = x[j*3+2] - x[i*3+2];
        float d = sqrtf(r0*r0 + r1*r1 + r2*r2);
        float inv = 1.0f / (d + 1e-5f);
        g_dir[p*3]   = r0 * inv;
        g_dir[p*3+1] = r1 * inv;
        g_dir[p*3+2] = r2 * inv;
        dvec[m] = d;
    }
    __syncthreads();

    int lane = tid & 31, wid = tid >> 5;
    int grp = lane >> 2, tg = lane & 3;
    int rt0 = wid * 16, rt1 = wid * 16 + 64;
    unsigned Ah[2][4], Al[2][4];

    float C2[2][4][4];
    #pragma unroll
    for (int mt = 0; mt < 2; mt++)
        #pragma unroll
        for (int nt = 0; nt < 4; nt++)
            #pragma unroll
            for (int q = 0; q < 4; q++) C2[mt][nt][q] = 0.0f;

    // ======== fused: C1 = h_cat@w1 and C2 += h_cat@w2a ====
    {
        float C1[2][7][4];
        #pragma unroll
        for (int mt = 0; mt < 2; mt++)
            #pragma unroll
            for (int nt = 0; nt < 7; nt++)
                #pragma unroll
                for (int q = 0; q < 4; q++) C1[mt][nt][q] = 0.0f;
        #pragma unroll
        for (int k8 = 0; k8 < 8; k8++) {
            int kg = k8 * 8;
            load_a_split(act, ACTS, rt0, kg, grp, tg, Ah[0], Al[0]);
            load_a_split(act, ACTS, rt1, kg, grp, tg, Ah[1], Al[1]);
            #pragma unroll
            for (int nt = 0; nt < 7; nt++) {
                float2 b0 = __ldg(&g_w1[(kg + tg) * 56 + nt * 8 + grp]);
                float2 b1 = __ldg(&g_w1[(kg + tg + 4) * 56 + nt * 8 + grp]);
                unsigned Bh[2] = { __float_as_uint(b0.x), __float_as_uint(b1.x) };
                unsigned Bl[2] = { __float_as_uint(b0.y), __float_as_uint(b1.y) };
                mma3v(C1[0][nt], Ah[0], Al[0], Bh, Bl);
                mma3v(C1[1][nt], Ah[1], Al[1], Bh, Bl);
            }
            #pragma unroll
            for (int nt = 0; nt < 4; nt++) {
                float2 b0 = __ldg(&g_w2a[(kg + tg) * 32 + nt * 8 + grp]);
                float2 b1 = __ldg(&g_w2a[(kg + tg + 4) * 32 + nt * 8 + grp]);
                unsigned Bh[2] = { __float_as_uint(b0.x), __float_as_uint(b1.x) };
                unsigned Bl[2] = { __float_as_uint(b0.y), __float_as_uint(b1.y) };
                mma3v(C2[0][nt], Ah[0], Al[0], Bh, Bl);
                mma3v(C2[1][nt], Ah[1], Al[1], Bh, Bl);
            }
        }
        // stage-1 epilogue: fbuf = [rbf(d)*(C1+bm) | d | 0]
        #pragma unroll
        for (int mt = 0; mt < 2; mt++) {
            int rr = (mt == 0) ? rt0 : rt1;
            float dlo = dvec[rr + grp], dhi = dvec[rr + grp + 8];
            #pragma unroll
            for (int nt = 0; nt < 7; nt++) {
                #pragma unroll
                for (int half = 0; half < 2; half++) {
                    int n = nt * 8 + 2 * tg + half;
                    float clo = C1[mt][nt][half], chi = C1[mt][nt][2 + half];
                    float ce = (float)n * (5.0f / 49.0f);
                    float vlo, vhi;
                    if (n < NRBF) {
                        float glo = __expf(-10.0f * (dlo - ce) * (dlo - ce));
                        float ghi = __expf(-10.0f * (dhi - ce) * (dhi - ce));
                        vlo = glo * (clo + s_bm[n]);
                        vhi = ghi * (chi + s_bm[n]);
                    } else if (n == NRBF) { vlo = dlo; vhi = dhi; }
                    else { vlo = 0.0f; vhi = 0.0f; }
                    fbuf[(rr + grp) * FBS + n] = vlo;
                    fbuf[(rr + grp + 8) * FBS + n] = vhi;
                }
            }
        }
    }
    __syncwarp();

    // ======== stage 2b: C2 += fbuf @ w2b ========
    {
        #pragma unroll
        for (int k8 = 0; k8 < 7; k8++) {
            int kg = k8 * 8;
            load_a_split(fbuf, FBS, rt0, kg, grp, tg, Ah[0], Al[0]);
            load_a_split(fbuf, FBS, rt1, kg, grp, tg, Ah[1], Al[1]);
            #pragma unroll
            for (int nt = 0; nt < 4; nt++) {
                float2 b0 = __ldg(&g_w2b[(kg + tg) * 32 + nt * 8 + grp]);
                float2 b1 = __ldg(&g_w2b[(kg + tg + 4) * 32 + nt * 8 + grp]);
                unsigned Bh[2] = { __float_as_uint(b0.x), __float_as_uint(b1.x) };
                unsigned Bl[2] = { __float_as_uint(b0.y), __float_as_uint(b1.y) };
                mma3v(C2[0][nt], Ah[0], Al[0], Bh, Bl);
                mma3v(C2[1][nt], Ah[1], Al[1], Bh, Bl);
            }
        }
        #pragma unroll
        for (int mt = 0; mt < 2; mt++) {
            int rr = (mt == 0) ? rt0 : rt1;
            #pragma unroll
            for (int nt = 0; nt < 4; nt++) {
                #pragma unroll
                for (int half = 0; half < 2; half++) {
                    int n = nt * 8 + 2 * tg + half;
                    act[(rr + grp) * ACTS + n] = siluf(C2[mt][nt][half] + s_b1[n]);
                    act[(rr + grp + 8) * ACTS + n] = siluf(C2[mt][nt][2 + half] + s_b1[n]);
                }
            }
        }
    }
    __syncwarp();

    // ======== stage 3: a3[128x32] = act[:,0..31] @ w3 ========
    {
        float C3[2][4][4];
        #pragma unroll
        for (int mt = 0; mt < 2; mt++)
            #pragma unroll
            for (int nt = 0; nt < 4; nt++)
                #pragma unroll
                for (int q = 0; q < 4; q++) C3[mt][nt][q] = 0.0f;
        #pragma unroll
        for (int k8 = 0; k8 < 4; k8++) {
            int kg = k8 * 8;
            load_a_split(act, ACTS, rt0, kg, grp, tg, Ah[0], Al[0]);
            load_a_split(act, ACTS, rt1, kg, grp, tg, Ah[1], Al[1]);
            #pragma unroll
            for (int nt = 0; nt < 4; nt++) {
                float2 b0 = __ldg(&g_w3[(kg + tg) * 32 + nt * 8 + grp]);
                float2 b1 = __ldg(&g_w3[(kg + tg + 4) * 32 + nt * 8 + grp]);
                unsigned Bh[2] = { __float_as_uint(b0.x), __float_as_uint(b1.x) };
                unsigned Bl[2] = { __float_as_uint(b0.y), __float_as_uint(b1.y) };
                mma3v(C3[0][nt], Ah[0], Al[0], Bh, Bl);
                mma3v(C3[1][nt], Ah[1], Al[1], Bh, Bl);
            }
        }
        #pragma unroll
        for (int mt = 0; mt < 2; mt++) {
            int rr = (mt == 0) ? rt0 : rt1;
            int plo = p0 + rr + grp, phi = plo + 8;
            #pragma unroll
            for (int nt = 0; nt < 4; nt++) {
                int n = nt * 8 + 2 * tg;
                float a0 = C3[mt][nt][0] + s_b2[n], a1 = C3[mt][nt][1] + s_b2[n + 1];
                float a2 = C3[mt][nt][2] + s_b2[n], a3v = C3[mt][nt][3] + s_b2[n + 1];
                fbuf[(rr + grp) * FBS + n] = a0;     fbuf[(rr + grp) * FBS + n + 1] = a1;
                fbuf[(rr + grp + 8) * FBS + n] = a2; fbuf[(rr + grp + 8) * FBS + n + 1] = a3v;
                *(float2*)(g_hedgeR + plo * FD + n) = make_float2(a0, a1);
                *(float2*)(g_hedgeR + phi * FD + n) = make_float2(a2, a3v);
            }
        }
    }
    __syncwarp();

    // ======== stage 4: logits[128x7] = celu(a3 @ w4 + b_att) ========
    {
        float C4[2][4];
        #pragma unroll
        for (int mt = 0; mt < 2; mt++)
            #pragma unroll
            for (int q = 0; q < 4; q++) C4[mt][q] = 0.0f;
        #pragma unroll
        for (int k8 = 0; k8 < 4; k8++) {
            int kg = k8 * 8;
            load_a_split(fbuf, FBS, rt0, kg, grp, tg, Ah[0], Al[0]);
            load_a_split(fbuf, FBS, rt1, kg, grp, tg, Ah[1], Al[1]);
            float2 b0 = __ldg(&g_w4[(kg + tg) * 8 + grp]);
            float2 b1 = __ldg(&g_w4[(kg + tg + 4) * 8 + grp]);
            unsigned Bh[2] = { __float_as_uint(b0.x), __float_as_uint(b1.x) };
            unsigned Bl[2] = { __float_as_uint(b0.y), __float_as_uint(b1.y) };
            mma3v(C4[0], Ah[0], Al[0], Bh, Bl);
            mma3v(C4[1], Ah[1], Al[1], Bh, Bl);
        }
        #pragma unroll
        for (int mt = 0; mt < 2; mt++) {
            int rr = (mt == 0) ? rt0 : rt1;
            int plo = p0 + rr + grp, phi = plo + 8;
            #pragma unroll
            for (int half = 0; half < 2; half++) {
                int n = 2 * tg + half;
                if (n < NH) {
                    float zlo = C4[mt][half] + s_ba[n];
                    float zhi = C4[mt][2 + half] + s_ba[n];
                    g_logits[plo * NH + n] = (zlo > 0.0f) ? zlo : 2.0f * (__expf(0.5f * zlo) - 1.0f);
                    g_logits[phi * NH + n] = (zhi > 0.0f) ? zhi : 2.0f * (__expf(0.5f * zhi) - 1.0f);
                }
            }
        }
    }
}

// ---------------- scatter softmax: single-gather register path ------------
__global__ void __launch_bounds__(256) softmax_kernel() {
    int node = blockIdx.x * 8 + (threadIdx.x >> 5);
    int lane = threadIdx.x & 31;
    int s = g_offsets[node], e = g_offsets[node + 1];
    int cnt = e - s;
    const unsigned FULL = 0xffffffffu;

    if (cnt <= 32) {
        if (cnt == 0) return;
        bool have = lane < cnt;
        int p = g_order[s + (have ? lane : 0)];
        float lg[NH];
        #pragma unroll
        for (int k = 0; k < NH; k++) lg[k] = g_logits[p * NH + k];

        float mx[NH], ex[NH], sm[NH];
        #pragma unroll
        for (int k = 0; k < NH; k++) {
            mx[k] = have ? lg[k] : -1e30f;
            #pragma unroll
            for (int off = 16; off; off >>= 1)
                mx[k] = fmaxf(mx[k], __shfl_xor_sync(FULL, mx[k], off));
            ex[k] = have ? __expf(lg[k] - mx[k]) : 0.0f;
            sm[k] = ex[k];
            #pragma unroll
            for (int off = 16; off; off >>= 1)
                sm[k] += __shfl_xor_sync(FULL, sm[k], off);
        }
        if (have) {
            #pragma unroll
            for (int k = 0; k < NH; k++)
                g_att[p * NH + k] = ex[k] / sm[k];
        }
    } else {
        float mx[NH];
        #pragma unroll
        for (int k = 0; k < NH; k++) mx[k] = -1e30f;
        for (int idx = s + lane; idx < e; idx += 32) {
            int p = g_order[idx];
            #pragma unroll
            for (int k = 0; k < NH; k++) mx[k] = fmaxf(mx[k], g_logits[p * NH + k]);
        }
        #pragma unroll
        for (int k = 0; k < NH; k++)
            #pragma unroll
            for (int off = 16; off; off >>= 1)
                mx[k] = fmaxf(mx[k], __shfl_xor_sync(FULL, mx[k], off));

        float sm[NH];
        #pragma unroll
        for (int k = 0; k < NH; k++) sm[k] = 0.0f;
        for (int idx = s + lane; idx < e; idx += 32) {
            int p = g_order[idx];
            #pragma unroll
            for (int k = 0; k < NH; k++) sm[k] += __expf(g_logits[p * NH + k] - mx[k]);
        }
        #pragma unroll
        for (int k = 0; k < NH; k++)
            #pragma unroll
            for (int off = 16; off; off >>= 1)
                sm[k] += __shfl_xor_sync(FULL, sm[k], off);

        for (int idx = s + lane; idx < e; idx += 32) {
            int p = g_order[idx];
            #pragma unroll
            for (int k = 0; k < NH; k++)
                g_att[p * NH + k] = __expf(g_logits[p * NH + k] - mx[k]) / sm[k];
        }
    }
}

// ---------------- big GEMM: BM=128, 512 threads, 16 warps, 1 CTA/SM ------
#define SEMS 228
__global__ void __launch_bounds__(512, 1) gemm_kernel(const float* __restrict__ wx) {
    extern __shared__ float sm[];
    float* sem = sm;                 // [128][228]
    float* s_he = sem + 128 * SEMS;  // [128][32]
    float* s_att = s_he + 4096;      // 896

    int tid = threadIdx.x;
    int m0 = blockIdx.x * 128;

    {
        int f = tid & 31, mrow = tid >> 5;   // 0..15
        #pragma unroll
        for (int it = 0; it < 8; it++) {
            int m = mrow + 16 * it;
            s_he[m * 32 + f] = g_hedgeR[(m0 + m) * FD + f];
        }
    }
    for (int t = tid; t < 896; t += 512) s_att[t] = g_att[m0 * NH + t];
    __syncthreads();

    for (int idx = tid; idx < 128 * NC; idx += 512) {
        int m = idx / NC, k = idx - m * NC;
        sem[m * SEMS + k] = s_he[m * 32 + k / 7] * s_att[m * 7 + (k % 7)];
    }
    __syncthreads();

    int lane = tid & 31, wid = tid >> 5;
    int wm = wid & 3;              // 0..3 : M offset 32*wm
    int wn = wid >> 2;             // 0..3 : N offset 56*wn
    int grp = lane >> 2, tg = lane & 3;

    float C[2][7][4];
    #pragma unroll
    for (int mt = 0; mt < 2; mt++)
        #pragma unroll
        for (int nt = 0; nt < 7; nt++)
            #pragma unroll
            for (int q = 0; q < 4; q++) C[mt][nt][q] = 0.0f;

    for (int kt = 0; kt < 4; kt++) {
        #pragma unroll
        for (int k8 = 0; k8 < 7; k8++) {
            int kg = kt * 56 + k8 * 8;

            unsigned Ah[2][4], Al[2][4];
            #pragma unroll
            for (int mt = 0; mt < 2; mt++)
                load_a_split(sem, SEMS, wm * 32 + mt * 16, kg, grp, tg, Ah[mt], Al[mt]);

            #pragma unroll
            for (int nt = 0; nt < 7; nt++) {
                int n0 = wn * 56 + nt * 8;
                float b0 = __ldg(&wx[(kg + tg) * NC + n0 + grp]);
                float b1 = __ldg(&wx[(kg + tg + 4) * NC + n0 + grp]);
                unsigned Bh[2], Bl[2];
                split_tf32(b0, Bh[0], Bl[0]);
                split_tf32(b1, Bh[1], Bl[1]);
                #pragma unroll
                for (int mt = 0; mt < 2; mt++) {
                    mma_tf32(C[mt][nt], Ah[mt], Bh);
                    mma_tf32(C[mt][nt], Ah[mt], Bl);
                    mma_tf32(C[mt][nt], Al[mt], Bh);
                }
            }
        }
    }

    #pragma unroll
    for (int mt = 0; mt < 2; mt++) {
        int rbase = m0 + wm * 32 + mt * 16 + grp;
        #pragma unroll
        for (int nt = 0; nt < 7; nt++) {
            int n0 = wn * 56 + nt * 8 + 2 * tg;
            float2 lo2 = make_float2(ftanh(C[mt][nt][0]), ftanh(C[mt][nt][1]));
            float2 hi2 = make_float2(ftanh(C[mt][nt][2]), ftanh(C[mt][nt][3]));
            *(float2*)(g_xmix + rbase * NC + n0) = lo2;
            *(float2*)(g_xmix + (rbase + 8) * NC + n0) = hi2;
        }
    }
}

// ---------------- per-node aggregation + node/velocity MLPs ----------------
__global__ void __launch_bounds__(256) node_kernel(
    const float* __restrict__ h, const float* __restrict__ x, const float* __restrict__ v,
    const float* __restrict__ w_p1, const float* __restrict__ b_p1,
    const float* __restrict__ w_p2, const float* __restrict__ b_p2,
    const float* __restrict__ w_n1, const float* __restrict__ b_n1,
    const float* __restrict__ w_n2, const float* __restrict__ b_n2,
    const float* __restrict__ w_v1, const float* __restrict__ b_v1,
    const float* __restrict__ w_v2, const float* __restrict__ w_vmix,
    float* __restrict__ out)
{
    __shared__ float sh[8 * 448];
    int wid = threadIdx.x >> 5, lane = threadIdx.x & 31;
    float* ws = sh + wid * 448;
    int node = blockIdx.x * 8 + wid;
    int s = g_offsets[node], e = g_offsets[node + 1];

    const unsigned FULL = 0xffffffffu;

    float acch[NH] = {0,0,0,0,0,0,0};
    float cb0[7] = {0,0,0,0,0,0,0};
    float cb1[7] = {0,0,0,0,0,0,0};
    float cb2[7] = {0,0,0,0,0,0,0};

    int idx = s;
    for (; idx + 3 < e; idx += 4) {
        int p[4];
        #pragma unroll
        for (int u = 0; u < 4; u++) p[u] = g_order[idx + u];
        float he[4], at[4], dv[4];
        #pragma unroll
        for (int u = 0; u < 4; u++) {
            he[u] = g_hedgeR[p[u] * FD + lane];
            at[u] = (lane < NH) ? g_att[p[u] * NH + lane] : 0.0f;
            dv[u] = (lane < 3) ? g_dir[p[u] * 3 + lane] : 0.0f;
        }
        float dd[4][3];
        #pragma unroll
        for (int u = 0; u < 4; u++) {
            dd[u][0] = __shfl_sync(FULL, dv[u], 0);
            dd[u][1] = __shfl_sync(FULL, dv[u], 1);
            dd[u][2] = __shfl_sync(FULL, dv[u], 2);
        }
        #pragma unroll
        for (int k = 0; k < NH; k++)
            #pragma unroll
            for (int u = 0; u < 4; u++)
                acch[k] += he[u] * __shfl_sync(FULL, at[u], k);
        #pragma unroll
        for (int j = 0; j < 7; j++) {
            #pragma unroll
            for (int u = 0; u < 4; u++) {
                float xm = g_xmix[p[u] * NC + lane + 32 * j];
                cb0[j] += dd[u][0] * xm;
                cb1[j] += dd[u][1] * xm;
                cb2[j] += dd[u][2] * xm;
            }
        }
    }
    for (; idx < e; idx++) {
        int p0 = g_order[idx];
        float he0 = g_hedgeR[p0 * FD + lane];
        float at0 = (lane < NH) ? g_att[p0 * NH + lane] : 0.0f;
        float dv0 = (lane < 3) ? g_dir[p0 * 3 + lane] : 0.0f;
        float d00 = __shfl_sync(FULL, dv0, 0), d01 = __shfl_sync(FULL, dv0, 1), d02 = __shfl_sync(FULL, dv0, 2);
        #pragma unroll
        for (int k = 0; k < NH; k++)
            acch[k] += he0 * __shfl_sync(FULL, at0, k);
        #pragma unroll
        for (int j = 0; j < 7; j++) {
            float xm0 = g_xmix[p0 * NC + lane + 32 * j];
            cb0[j] += d00 * xm0;
            cb1[j] += d01 * xm0;
            cb2[j] += d02 * xm0;
        }
    }

    #pragma unroll
    for (int k = 0; k < NH; k++) ws[224 + lane * NH + k] = acch[k];

    float rden = 1.0f / fmaxf((float)(e - s), 1.0f);
    float vp0 = 0, vp1 = 0, vp2 = 0;
    #pragma unroll
    for (int j = 0; j < 7; j++) {
        int c = lane + 32 * j;
        float m0 = cb0[j] * rden, m1 = cb1[j] * rden, m2 = cb2[j] * rden;
        ws[c] = m0*m0 + m1*m1 + m2*m2;
        float wv = __ldg(&w_vmix[c]);
        vp0 += wv * m0; vp1 += wv * m1; vp2 += wv * m2;
    }
    #pragma unroll
    for (int off = 16; off; off >>= 1) {
        vp0 += __shfl_xor_sync(FULL, vp0, off);
        vp1 += __shfl_xor_sync(FULL, vp1, off);
        vp2 += __shfl_xor_sync(FULL, vp2, off);
    }
    __syncwarp();

    float o1 = __ldg(&b_p1[lane]);
    for (int c = 0; c < NC; c++) o1 += ws[c] * __ldg(&w_p1[c * 32 + lane]);
    o1 = siluf(o1);
    float o2 = __ldg(&b_p2[lane]);
    for (int c = 0; c < 32; c++)
        o2 += __shfl_sync(FULL, o1, c) * __ldg(&w_p2[c * 32 + lane]);
    float hspat = siluf(o2);

    float hv = h[node * 32 + lane];
    float n1 = __ldg(&b_n1[lane]);
    for (int c = 0; c < 32; c++)
        n1 += __shfl_sync(FULL, hv, c) * __ldg(&w_n1[c * 32 + lane]);
    for (int c = 0; c < NC; c++)
        n1 += ws[224 + c] * __ldg(&w_n1[(32 + c) * 32 + lane]);
    for (int c = 0; c < 32; c++)
        n1 += __shfl_sync(FULL, hspat, c) * __ldg(&w_n1[(256 + c) * 32 + lane]);
    n1 = siluf(n1);
    float n2 = __ldg(&b_n2[lane]);
    for (int c = 0; c < 32; c++)
        n2 += __shfl_sync(FULL, n1, c) * __ldg(&w_n2[c * 32 + lane]);
    float hup = hv + siluf(n2);
    out[node * 32 + lane] = hup;

    float v1 = __ldg(&b_v1[lane]);
    for (int c = 0; c < 32; c++)
        v1 += __shfl_sync(FULL, hv, c) * __ldg(&w_v1[c * 32 + lane]);
    v1 = siluf(v1);
    float sv = v1 * __ldg(&w_v2[lane]);
    #pragma unroll
    for (int off = 16; off; off >>= 1) sv += __shfl_xor_sync(FULL, sv, off);
    float scale = 2.0f / (1.0f + __expf(-sv));

    if (lane < 3) {
        float dv = (lane == 0) ? vp0 : ((lane == 1) ? vp1 : vp2);
        float vu = scale * v[node * 3 + lane] + dv;
        out[NN * 32 + node * 3 + lane] = x[node * 3 + lane] + vu;
        out[NN * 32 + NN * 3 + node * 3 + lane] = vu;
    }
}

// ---------------- launch ----------------
extern "C" void kernel_launch(void* const* d_in, const int* in_sizes, int n_in,
                              void* d_out, int out_size)
{
    const float* h  = (const float*)d_in[0];
    const float* x  = (const float*)d_in[1];
    const float* v  = (const float*)d_in[2];
    const int*   pl = (const int*)d_in[3];

    int edge_smem = (128 * ACTS + 128 * FBS + 128 + 56 + 32 + 32 + 8) * 4;   // ~66.6 KB
    int gemm_smem = (128 * SEMS + 4096 + 896) * 4;                            // ~136.7 KB
    cudaFuncSetAttribute(edge_kernel, cudaFuncAttributeMaxDynamicSharedMemorySize, edge_smem);
    cudaFuncSetAttribute(gemm_kernel, cudaFuncAttributeMaxDynamicSharedMemorySize, gemm_smem);

    zero_kernel<<<(NN + 255) / 256, 256>>>();
    count_kernel<<<(NP + 255) / 256, 256>>>(pl);
    wsplit_kernel<<<34, 256>>>((const float*)d_in[4], (const float*)d_in[6],
                               (const float*)d_in[8], (const float*)d_in[10]);
    edge_kernel<<<NP / 128, 128, edge_smem>>>(
        h, x, pl,
        (const float*)d_in[5], (const float*)d_in[7],
        (const float*)d_in[9], (const float*)d_in[11]);
    scan1_kernel<<<40, 256>>>();
    scan2_kernel<<<1, 64>>>();
    scan3_kernel<<<40, 256>>>();
    scatter_kernel<<<(NP + 255) / 256, 256>>>(pl);
    softmax_kernel<<<NN / 8, 256>>>();
    gemm_kernel<<<NP / 128, 512, gemm_smem>>>((const float*)d_in[23]);

    node_kernel<<<NN / 8, 256>>>(
        h, x, v,
        (const float*)d_in[16], (const float*)d_in[17],   // w_p1, b_p1
        (const float*)d_in[18], (const float*)d_in[19],   // w_p2, b_p2
        (const float*)d_in[12], (const float*)d_in[13],   // w_n1, b_n1
        (const float*)d_in[14], (const float*)d_in[15],   // w_n2, b_n2
        (const float*)d_in[20], (const float*)d_in[21],   // w_v1, b_v1
        (const float*)d_in[22], (const float*)d_in[24],   // w_v2, w_vmix
        (float*)d_out);
}

// round 13
// speedup vs baseline: 1.0817x; 1.0817x over previous
#include <cuda_runtime.h>
#include <math.h>

#define NP 160000
#define NN 10000
#define FD 32
#define NH 7
#define NC 224
#define NRBF 50

// ---------------- scratch (device globals: allocation-free) ----------------
__device__ float g_hedgeR[NP * FD];         // row-major [p][f]
__device__ float g_logits[NP * NH];
__device__ float g_att[NP * NH];
__device__ float g_dir[NP * 3];
__device__ float g_xmix[NP * NC];
__device__ int   g_counts[NN];
__device__ int   g_cursor[NN];
__device__ int   g_offsets[NN + 1];
__device__ int   g_order[NP];
__device__ int   g_bsum[40];
__device__ int   g_boff[40];

// pre-split edge weights: float2(hi, lo), tf32-rounded fp32 bit patterns
__device__ float2 g_w1[64 * 56];
__device__ float2 g_w2a[64 * 32];
__device__ float2 g_w2b[56 * 32];
__device__ float2 g_w3[32 * 32];
__device__ float2 g_w4[32 * 8];

__device__ __forceinline__ float siluf(float z) { return z / (1.0f + __expf(-z)); }
__device__ __forceinline__ float ftanh(float z) {
    float e = __expf(2.0f * z);
    return 1.0f - __fdividef(2.0f, e + 1.0f);
}

// tf32 helpers
__device__ __forceinline__ void split_tf32(float f, unsigned& hi, unsigned& lo) {
    asm("cvt.rna.tf32.f32 %0, %1;" : "=r"(hi) : "f"(f));
    float rem = f - __uint_as_float(hi);
    asm("cvt.rna.tf32.f32 %0, %1;" : "=r"(lo) : "f"(rem));
}
__device__ __forceinline__ void mma_tf32(float c[4], const unsigned a[4], const unsigned b[2]) {
    asm("mma.sync.aligned.m16n8k8.row.col.f32.tf32.tf32.f32 "
        "{%0,%1,%2,%3}, {%4,%5,%6,%7}, {%8,%9}, {%0,%1,%2,%3};"
        : "+f"(c[0]), "+f"(c[1]), "+f"(c[2]), "+f"(c[3])
        : "r"(a[0]), "r"(a[1]), "r"(a[2]), "r"(a[3]), "r"(b[0]), "r"(b[1]));
}
__device__ __forceinline__ void load_a_split(const float* base, int stride, int r0,
                                             int kg, int grp, int tg,
                                             unsigned Ah[4], unsigned Al[4]) {
    float a0 = base[(r0 + grp) * stride + kg + tg];
    float a1 = base[(r0 + grp + 8) * stride + kg + tg];
    float a2 = base[(r0 + grp) * stride + kg + tg + 4];
    float a3 = base[(r0 + grp + 8) * stride + kg + tg + 4];
    split_tf32(a0, Ah[0], Al[0]);
    split_tf32(a1, Ah[1], Al[1]);
    split_tf32(a2, Ah[2], Al[2]);
    split_tf32(a3, Ah[3], Al[3]);
}
__device__ __forceinline__ void mma3v(float C[4], const unsigned Ah[4], const unsigned Al[4],
                                      const unsigned Bh[2], const unsigned Bl[2]) {
    mma_tf32(C, Ah, Bh);
    mma_tf32(C, Ah, Bl);
    mma_tf32(C, Al, Bh);
}

// ---------------- weight pre-split prep ----------------
__device__ __forceinline__ float2 sp2(float v) {
    unsigned hi, lo; split_tf32(v, hi, lo);
    return make_float2(__uint_as_float(hi), __uint_as_float(lo));
}
__global__ void wsplit_kernel(const float* __restrict__ wmlp, const float* __restrict__ we1,
                              const float* __restrict__ we2,  const float* __restrict__ watt) {
    int t = blockIdx.x * 256 + threadIdx.x;
    if (t < 3584) {                       // w1 [64][56]
        int k = t / 56, n = t - k * 56;
        g_w1[t] = sp2((n < NRBF) ? wmlp[k * NRBF + n] : 0.0f);
    } else if (t < 5632) {                // w2a [64][32]
        int i = t - 3584;
        g_w2a[i] = sp2(we1[i]);
    } else if (t < 7424) {                // w2b [56][32]
        int i = t - 5632;
        int k = i >> 5, n = i & 31;
        float v = (k < NRBF) ? we1[(64 + k) * FD + n]
                : ((k == NRBF) ? we1[114 * FD + n] : 0.0f);
        g_w2b[i] = sp2(v);
    } else if (t < 8448) {                // w3 [32][32]
        int i = t - 7424;
        g_w3[i] = sp2(we2[i]);
    } else if (t < 8704) {                // w4 [32][8]
        int i = t - 8448;
        int k = i >> 3, n = i & 7;
        g_w4[i] = sp2((n < NH) ? watt[k * NH + n] : 0.0f);
    }
}

// ---------------- CSR build ----------------
__global__ void zero_kernel() {
    int i = blockIdx.x * 256 + threadIdx.x;
    if (i < NN) { g_counts[i] = 0; g_cursor[i] = 0; }
}

__global__ void count_kernel(const int* __restrict__ pl) {
    int p = blockIdx.x * 256 + threadIdx.x;
    if (p < NP) atomicAdd(&g_counts[pl[p]], 1);
}

// multi-block scan: 40 blocks x 256
__global__ void scan1_kernel() {
    __shared__ int sh[256];
    int b = blockIdx.x, t = threadIdx.x, idx = b * 256 + t;
    int v = (idx < NN) ? g_counts[idx] : 0;
    sh[t] = v;
    __syncthreads();
    #pragma unroll
    for (int off = 1; off < 256; off <<= 1) {
        int a = (t >= off) ? sh[t - off] : 0;
        __syncthreads();
        sh[t] += a;
        __syncthreads();
    }
    if (idx < NN) g_offsets[idx + 1] = sh[t];
    if (t == 255) g_bsum[b] = sh[255];
    if (b == 0 && t == 0) g_offsets[0] = 0;
}
__global__ void scan2_kernel() {   // 1 block, 64 threads
    __shared__ int sh[64];
    int t = threadIdx.x;
    int v = (t < 40) ? g_bsum[t] : 0;
    sh[t] = v;
    __syncthreads();
    #pragma unroll
    for (int off = 1; off < 64; off <<= 1) {
        int a = (t >= off) ? sh[t - off] : 0;
        __syncthreads();
        sh[t] += a;
        __syncthreads();
    }
    if (t < 40) g_boff[t] = sh[t] - v;   // exclusive of own block
}
__global__ void scan3_kernel() {
    int b = blockIdx.x, idx = b * 256 + threadIdx.x;
    if (idx < NN) g_offsets[idx + 1] += g_boff[b];
}

__global__ void scatter_kernel(const int* __restrict__ pl) {
    int p = blockIdx.x * 256 + threadIdx.x;
    if (p < NP) {
        int i = pl[p];
        int pos = g_offsets[i] + atomicAdd(&g_cursor[i], 1);
        g_order[pos] = p;
    }
}

// ---------------- edge model: tensor-core MLP, fused stage1+2a ------------
#define ACTS 68
#define FBS  60
__global__ void __launch_bounds__(128, 3) edge_kernel(
    const float* __restrict__ h, const float* __restrict__ x,
    const int* __restrict__ pl,
    const float* __restrict__ bmlp, const float* __restrict__ be1,
    const float* __restrict__ be2,  const float* __restrict__ batt)
{
    extern __shared__ float smem[];
    float* act  = smem;                    // [128][68]
    float* fbuf = act + 128 * ACTS;        // [128][60]
    float* dvec = fbuf + 128 * FBS;        // [128]
    float* s_bm = dvec + 128;              // [56]
    float* s_b1 = s_bm + 56;               // [32]
    float* s_b2 = s_b1 + 32;               // [32]
    float* s_ba = s_b2 + 32;               // [8]

    int tid = threadIdx.x;
    int p0 = blockIdx.x * 128;

    if (tid < 56) s_bm[tid] = (tid < NRBF) ? bmlp[tid] : 0.0f;
    if (tid < 32) { s_b1[tid] = be1[tid]; s_b2[tid] = be2[tid]; }
    if (tid < 8)  s_ba[tid] = (tid < NH) ? batt[tid] : 0.0f;

    // stage h_cat + d + dir: thread per pair
    {
        int m = tid, p = p0 + m;
        int i = pl[p], j = pl[NP + p];
        const float4* si = (const float4*)(h + i * FD);
        const float4* sj = (const float4*)(h + j * FD);
        float4* dst = (float4*)(act + m * ACTS);
        #pragma unroll
        for (int q = 0; q < 8; q++) dst[q] = si[q];
        #pragma unroll
        for (int q = 0; q < 8; q++) dst[8 + q] = sj[q];

        float r0 = x[j*3]   - x[i*3];
        float r1 = x[j*3+1] - x[i*3+1];
        float r2 = x[j*3+2] - x[i*3+2];
        float d = sqrtf(r0*r0 + r1*r1 + r2*r2);
        float inv = 1.0f / (d + 1e-5f);
        g_dir[p*3]   = r0 * inv;
        g_dir[p*3+1] = r1 * inv;
        g_dir[p*3+2] = r2 * inv;
        dvec[m] = d;
    }
    __syncthreads();

    int lane = tid & 31, wid = tid >> 5;
    int grp = lane >> 2, tg = lane & 3;
    int rt0 = wid * 16, rt1 = wid * 16 + 64;
    unsigned Ah[2][4], Al[2][4];

    float C2[2][4][4];
    #pragma unroll
    for (int mt = 0; mt < 2; mt++)
        #pragma unroll
        for (int nt = 0; nt < 4; nt++)
            #pragma unroll
            for (int q = 0; q < 4; q++) C2[mt][nt][q] = 0.0f;

    // ======== fused: C1 = h_cat@w1 and C2 += h_cat@w2a ====
    {
        float C1[2][7][4];
        #pragma unroll
        for (int mt = 0; mt < 2; mt++)
            #pragma unroll
            for (int nt = 0; nt < 7; nt++)
                #pragma unroll
                for (int q = 0; q < 4; q++) C1[mt][nt][q] = 0.0f;
        #pragma unroll
        for (int k8 = 0; k8 < 8; k8++) {
            int kg = k8 * 8;
            load_a_split(act, ACTS, rt0, kg, grp, tg, Ah[0], Al[0]);
            load_a_split(act, ACTS, rt1, kg, grp, tg, Ah[1], Al[1]);
            #pragma unroll
            for (int nt = 0; nt < 7; nt++) {
                float2 b0 = __ldg(&g_w1[(kg + tg) * 56 + nt * 8 + grp]);
                float2 b1 = __ldg(&g_w1[(kg + tg + 4) * 56 + nt * 8 + grp]);
                unsigned Bh[2] = { __float_as_uint(b0.x), __float_as_uint(b1.x) };
                unsigned Bl[2] = { __float_as_uint(b0.y), __float_as_uint(b1.y) };
                mma3v(C1[0][nt], Ah[0], Al[0], Bh, Bl);
                mma3v(C1[1][nt], Ah[1], Al[1], Bh, Bl);
            }
            #pragma unroll
            for (int nt = 0; nt < 4; nt++) {
                float2 b0 = __ldg(&g_w2a[(kg + tg) * 32 + nt * 8 + grp]);
                float2 b1 = __ldg(&g_w2a[(kg + tg + 4) * 32 + nt * 8 + grp]);
                unsigned Bh[2] = { __float_as_uint(b0.x), __float_as_uint(b1.x) };
                unsigned Bl[2] = { __float_as_uint(b0.y), __float_as_uint(b1.y) };
                mma3v(C2[0][nt], Ah[0], Al[0], Bh, Bl);
                mma3v(C2[1][nt], Ah[1], Al[1], Bh, Bl);
            }
        }
        // stage-1 epilogue: fbuf = [rbf(d)*(C1+bm) | d | 0]
        #pragma unroll
        for (int mt = 0; mt < 2; mt++) {
            int rr = (mt == 0) ? rt0 : rt1;
            float dlo = dvec[rr + grp], dhi = dvec[rr + grp + 8];
            #pragma unroll
            for (int nt = 0; nt < 7; nt++) {
                #pragma unroll
                for (int half = 0; half < 2; half++) {
                    int n = nt * 8 + 2 * tg + half;
                    float clo = C1[mt][nt][half], chi = C1[mt][nt][2 + half];
                    float ce = (float)n * (5.0f / 49.0f);
                    float vlo, vhi;
                    if (n < NRBF) {
                        float glo = __expf(-10.0f * (dlo - ce) * (dlo - ce));
                        float ghi = __expf(-10.0f * (dhi - ce) * (dhi - ce));
                        vlo = glo * (clo + s_bm[n]);
                        vhi = ghi * (chi + s_bm[n]);
                    } else if (n == NRBF) { vlo = dlo; vhi = dhi; }
                    else { vlo = 0.0f; vhi = 0.0f; }
                    fbuf[(rr + grp) * FBS + n] = vlo;
                    fbuf[(rr + grp + 8) * FBS + n] = vhi;
                }
            }
        }
    }
    __syncwarp();

    // ======== stage 2b: C2 += fbuf @ w2b ========
    {
        #pragma unroll
        for (int k8 = 0; k8 < 7; k8++) {
            int kg = k8 * 8;
            load_a_split(fbuf, FBS, rt0, kg, grp, tg, Ah[0], Al[0]);
            load_a_split(fbuf, FBS, rt1, kg, grp, tg, Ah[1], Al[1]);
            #pragma unroll
            for (int nt = 0; nt < 4; nt++) {
                float2 b0 = __ldg(&g_w2b[(kg + tg) * 32 + nt * 8 + grp]);
                float2 b1 = __ldg(&g_w2b[(kg + tg + 4) * 32 + nt * 8 + grp]);
                unsigned Bh[2] = { __float_as_uint(b0.x), __float_as_uint(b1.x) };
                unsigned Bl[2] = { __float_as_uint(b0.y), __float_as_uint(b1.y) };
                mma3v(C2[0][nt], Ah[0], Al[0], Bh, Bl);
                mma3v(C2[1][nt], Ah[1], Al[1], Bh, Bl);
            }
        }
        #pragma unroll
        for (int mt = 0; mt < 2; mt++) {
            int rr = (mt == 0) ? rt0 : rt1;
            #pragma unroll
            for (int nt = 0; nt < 4; nt++) {
                #pragma unroll
                for (int half = 0; half < 2; half++) {
                    int n = nt * 8 + 2 * tg + half;
                    act[(rr + grp) * ACTS + n] = siluf(C2[mt][nt][half] + s_b1[n]);
                    act[(rr + grp + 8) * ACTS + n] = siluf(C2[mt][nt][2 + half] + s_b1[n]);
                }
            }
        }
    }
    __syncwarp();

    // ======== stage 3: a3[128x32] = act[:,0..31] @ w3 ========
    {
        float C3[2][4][4];
        #pragma unroll
        for (int mt = 0; mt < 2; mt++)
            #pragma unroll
            for (int nt = 0; nt < 4; nt++)
                #pragma unroll
                for (int q = 0; q < 4; q++) C3[mt][nt][q] = 0.0f;
        #pragma unroll
        for (int k8 = 0; k8 < 4; k8++) {
            int kg = k8 * 8;
            load_a_split(act, ACTS, rt0, kg, grp, tg, Ah[0], Al[0]);
            load_a_split(act, ACTS, rt1, kg, grp, tg, Ah[1], Al[1]);
            #pragma unroll
            for (int nt = 0; nt < 4; nt++) {
                float2 b0 = __ldg(&g_w3[(kg + tg) * 32 + nt * 8 + grp]);
                float2 b1 = __ldg(&g_w3[(kg + tg + 4) * 32 + nt * 8 + grp]);
                unsigned Bh[2] = { __float_as_uint(b0.x), __float_as_uint(b1.x) };
                unsigned Bl[2] = { __float_as_uint(b0.y), __float_as_uint(b1.y) };
                mma3v(C3[0][nt], Ah[0], Al[0], Bh, Bl);
                mma3v(C3[1][nt], Ah[1], Al[1], Bh, Bl);
            }
        }
        #pragma unroll
        for (int mt = 0; mt < 2; mt++) {
            int rr = (mt == 0) ? rt0 : rt1;
            int plo = p0 + rr + grp, phi = plo + 8;
            #pragma unroll
            for (int nt = 0; nt < 4; nt++) {
                int n = nt * 8 + 2 * tg;
                float a0 = C3[mt][nt][0] + s_b2[n], a1 = C3[mt][nt][1] + s_b2[n + 1];
                float a2 = C3[mt][nt][2] + s_b2[n], a3v = C3[mt][nt][3] + s_b2[n + 1];
                fbuf[(rr + grp) * FBS + n] = a0;     fbuf[(rr + grp) * FBS + n + 1] = a1;
                fbuf[(rr + grp + 8) * FBS + n] = a2; fbuf[(rr + grp + 8) * FBS + n + 1] = a3v;
                *(float2*)(g_hedgeR + plo * FD + n) = make_float2(a0, a1);
                *(float2*)(g_hedgeR + phi * FD + n) = make_float2(a2, a3v);
            }
        }
    }
    __syncwarp();

    // ======== stage 4: logits[128x7] = celu(a3 @ w4 + b_att) ========
    {
        float C4[2][4];
        #pragma unroll
        for (int mt = 0; mt < 2; mt++)
            #pragma unroll
            for (int q = 0; q < 4; q++) C4[mt][q] = 0.0f;
        #pragma unroll
        for (int k8 = 0; k8 < 4; k8++) {
            int kg = k8 * 8;
            load_a_split(fbuf, FBS, rt0, kg, grp, tg, Ah[0], Al[0]);
            load_a_split(fbuf, FBS, rt1, kg, grp, tg, Ah[1], Al[1]);
            float2 b0 = __ldg(&g_w4[(kg + tg) * 8 + grp]);
            float2 b1 = __ldg(&g_w4[(kg + tg + 4) * 8 + grp]);
            unsigned Bh[2] = { __float_as_uint(b0.x), __float_as_uint(b1.x) };
            unsigned Bl[2] = { __float_as_uint(b0.y), __float_as_uint(b1.y) };
            mma3v(C4[0], Ah[0], Al[0], Bh, Bl);
            mma3v(C4[1], Ah[1], Al[1], Bh, Bl);
        }
        #pragma unroll
        for (int mt = 0; mt < 2; mt++) {
            int rr = (mt == 0) ? rt0 : rt1;
            int plo = p0 + rr + grp, phi = plo + 8;
            #pragma unroll
            for (int half = 0; half < 2; half++) {
                int n = 2 * tg + half;
                if (n < NH) {
                    float zlo = C4[mt][half] + s_ba[n];
                    float zhi = C4[mt][2 + half] + s_ba[n];
                    g_logits[plo * NH + n] = (zlo > 0.0f) ? zlo : 2.0f * (__expf(0.5f * zlo) - 1.0f);
                    g_logits[phi * NH + n] = (zhi > 0.0f) ? zhi : 2.0f * (__expf(0.5f * zhi) - 1.0f);
                }
            }
        }
    }
}

// ---------------- scatter softmax: single-gather register path ------------
__global__ void __launch_bounds__(256) softmax_kernel() {
    int node = blockIdx.x * 8 + (threadIdx.x >> 5);
    int lane = threadIdx.x & 31;
    int s = g_offsets[node], e = g_offsets[node + 1];
    int cnt = e - s;
    const unsigned FULL = 0xffffffffu;

    if (cnt <= 32) {
        if (cnt == 0) return;
        bool have = lane < cnt;
        int p = g_order[s + (have ? lane : 0)];
        float lg[NH];
        #pragma unroll
        for (int k = 0; k < NH; k++) lg[k] = g_logits[p * NH + k];

        float mx[NH], ex[NH], sm[NH];
        #pragma unroll
        for (int k = 0; k < NH; k++) {
            mx[k] = have ? lg[k] : -1e30f;
            #pragma unroll
            for (int off = 16; off; off >>= 1)
                mx[k] = fmaxf(mx[k], __shfl_xor_sync(FULL, mx[k], off));
            ex[k] = have ? __expf(lg[k] - mx[k]) : 0.0f;
            sm[k] = ex[k];
            #pragma unroll
            for (int off = 16; off; off >>= 1)
                sm[k] += __shfl_xor_sync(FULL, sm[k], off);
        }
        if (have) {
            #pragma unroll
            for (int k = 0; k < NH; k++)
                g_att[p * NH + k] = ex[k] / sm[k];
        }
    } else {
        float mx[NH];
        #pragma unroll
        for (int k = 0; k < NH; k++) mx[k] = -1e30f;
        for (int idx = s + lane; idx < e; idx += 32) {
            int p = g_order[idx];
            #pragma unroll
            for (int k = 0; k < NH; k++) mx[k] = fmaxf(mx[k], g_logits[p * NH + k]);
        }
        #pragma unroll
        for (int k = 0; k < NH; k++)
            #pragma unroll
            for (int off = 16; off; off >>= 1)
                mx[k] = fmaxf(mx[k], __shfl_xor_sync(FULL, mx[k], off));

        float sm[NH];
        #pragma unroll
        for (int k = 0; k < NH; k++) sm[k] = 0.0f;
        for (int idx = s + lane; idx < e; idx += 32) {
            int p = g_order[idx];
            #pragma unroll
            for (int k = 0; k < NH; k++) sm[k] += __expf(g_logits[p * NH + k] - mx[k]);
        }
        #pragma unroll
        for (int k = 0; k < NH; k++)
            #pragma unroll
            for (int off = 16; off; off >>= 1)
                sm[k] += __shfl_xor_sync(FULL, sm[k], off);

        for (int idx = s + lane; idx < e; idx += 32) {
            int p = g_order[idx];
            #pragma unroll
            for (int k = 0; k < NH; k++)
                g_att[p * NH + k] = __expf(g_logits[p * NH + k] - mx[k]) / sm[k];
        }
    }
}

// ---------------- big GEMM via 3xTF32 mma.sync; BM=64, 2 CTAs/SM ---------
#define SEMS 228
__global__ void __launch_bounds__(256, 2) gemm_kernel(const float* __restrict__ wx) {
    extern __shared__ float sm[];
    float* sem = sm;               // [64][228]
    float* s_he = sem + 64 * SEMS; // [64][32] m-major
    float* s_att = s_he + 2048;    // 448

    int tid = threadIdx.x;
    int m0 = blockIdx.x * 64;

    {
        int f = tid & 31, mrow = tid >> 5;
        #pragma unroll
        for (int it = 0; it < 8; it++) {
            int m = mrow + 8 * it;
            s_he[m * 32 + f] = g_hedgeR[(m0 + m) * FD + f];
        }
    }
    for (int t = tid; t < 448; t += 256) s_att[t] = g_att[m0 * NH + t];
    __syncthreads();

    for (int idx = tid; idx < 64 * NC; idx += 256) {
        int m = idx / NC, k = idx - m * NC;
        sem[m * SEMS + k] = s_he[m * 32 + k / 7] * s_att[m * 7 + (k % 7)];
    }
    __syncthreads();

    int lane = tid & 31, wid = tid >> 5;
    int wm = wid & 1;
    int wn = wid >> 1;
    int grp = lane >> 2, tg = lane & 3;

    float C[2][7][4];
    #pragma unroll
    for (int mt = 0; mt < 2; mt++)
        #pragma unroll
        for (int nt = 0; nt < 7; nt++)
            #pragma unroll
            for (int q = 0; q < 4; q++) C[mt][nt][q] = 0.0f;

    for (int kt = 0; kt < 4; kt++) {
        #pragma unroll
        for (int k8 = 0; k8 < 7; k8++) {
            int kg = kt * 56 + k8 * 8;

            unsigned Ah[2][4], Al[2][4];
            #pragma unroll
            for (int mt = 0; mt < 2; mt++)
                load_a_split(sem, SEMS, wm * 32 + mt * 16, kg, grp, tg, Ah[mt], Al[mt]);

            #pragma unroll
            for (int nt = 0; nt < 7; nt++) {
                int n0 = wn * 56 + nt * 8;
                float b0 = __ldg(&wx[(kg + tg) * NC + n0 + grp]);
                float b1 = __ldg(&wx[(kg + tg + 4) * NC + n0 + grp]);
                unsigned Bh[2], Bl[2];
                split_tf32(b0, Bh[0], Bl[0]);
                split_tf32(b1, Bh[1], Bl[1]);
                #pragma unroll
                for (int mt = 0; mt < 2; mt++) {
                    mma_tf32(C[mt][nt], Ah[mt], Bh);
                    mma_tf32(C[mt][nt], Ah[mt], Bl);
                    mma_tf32(C[mt][nt], Al[mt], Bh);
                }
            }
        }
    }

    #pragma unroll
    for (int mt = 0; mt < 2; mt++) {
        int rbase = m0 + wm * 32 + mt * 16 + grp;
        #pragma unroll
        for (int nt = 0; nt < 7; nt++) {
            int n0 = wn * 56 + nt * 8 + 2 * tg;
            float2 lo2 = make_float2(ftanh(C[mt][nt][0]), ftanh(C[mt][nt][1]));
            float2 hi2 = make_float2(ftanh(C[mt][nt][2]), ftanh(C[mt][nt][3]));
            *(float2*)(g_xmix + rbase * NC + n0) = lo2;
            *(float2*)(g_xmix + (rbase + 8) * NC + n0) = hi2;
        }
    }
}

// ---------------- per-node aggregation + node/velocity MLPs ----------------
__global__ void __launch_bounds__(256) node_kernel(
    const float* __restrict__ h, const float* __restrict__ x, const float* __restrict__ v,
    const float* __restrict__ w_p1, const float* __restrict__ b_p1,
    const float* __restrict__ w_p2, const float* __restrict__ b_p2,
    const float* __restrict__ w_n1, const float* __restrict__ b_n1,
    const float* __restrict__ w_n2, const float* __restrict__ b_n2,
    const float* __restrict__ w_v1, const float* __restrict__ b_v1,
    const float* __restrict__ w_v2, const float* __restrict__ w_vmix,
    float* __restrict__ out)
{
    __shared__ float sh[8 * 448];
    int wid = threadIdx.x >> 5, lane = threadIdx.x & 31;
    float* ws = sh + wid * 448;
    int node = blockIdx.x * 8 + wid;
    int s = g_offsets[node], e = g_offsets[node + 1];

    const unsigned FULL = 0xffffffffu;

    float acch[NH] = {0,0,0,0,0,0,0};
    float cb0[7] = {0,0,0,0,0,0,0};
    float cb1[7] = {0,0,0,0,0,0,0};
    float cb2[7] = {0,0,0,0,0,0,0};

    int idx = s;
    for (; idx + 3 < e; idx += 4) {
        int p[4];
        #pragma unroll
        for (int u = 0; u < 4; u++) p[u] = g_order[idx + u];
        float he[4], at[4], dv[4];
        #pragma unroll
        for (int u = 0; u < 4; u++) {
            he[u] = g_hedgeR[p[u] * FD + lane];
            at[u] = (lane < NH) ? g_att[p[u] * NH + lane] : 0.0f;
            dv[u] = (lane < 3) ? g_dir[p[u] * 3 + lane] : 0.0f;
        }
        float dd[4][3];
        #pragma unroll
        for (int u = 0; u < 4; u++) {
            dd[u][0] = __shfl_sync(FULL, dv[u], 0);
            dd[u][1] = __shfl_sync(FULL, dv[u], 1);
            dd[u][2] = __shfl_sync(FULL, dv[u], 2);
        }
        #pragma unroll
        for (int k = 0; k < NH; k++)
            #pragma unroll
            for (int u = 0; u < 4; u++)
                acch[k] += he[u] * __shfl_sync(FULL, at[u], k);
        #pragma unroll
        for (int j = 0; j < 7; j++) {
            #pragma unroll
            for (int u = 0; u < 4; u++) {
                float xm = g_xmix[p[u] * NC + lane + 32 * j];
                cb0[j] += dd[u][0] * xm;
                cb1[j] += dd[u][1] * xm;
                cb2[j] += dd[u][2] * xm;
            }
        }
    }
    for (; idx < e; idx++) {
        int p0 = g_order[idx];
        float he0 = g_hedgeR[p0 * FD + lane];
        float at0 = (lane < NH) ? g_att[p0 * NH + lane] : 0.0f;
        float dv0 = (lane < 3) ? g_dir[p0 * 3 + lane] : 0.0f;
        float d00 = __shfl_sync(FULL, dv0, 0), d01 = __shfl_sync(FULL, dv0, 1), d02 = __shfl_sync(FULL, dv0, 2);
        #pragma unroll
        for (int k = 0; k < NH; k++)
            acch[k] += he0 * __shfl_sync(FULL, at0, k);
        #pragma unroll
        for (int j = 0; j < 7; j++) {
            float xm0 = g_xmix[p0 * NC + lane + 32 * j];
            cb0[j] += d00 * xm0;
            cb1[j] += d01 * xm0;
            cb2[j] += d02 * xm0;
        }
    }

    #pragma unroll
    for (int k = 0; k < NH; k++) ws[224 + lane * NH + k] = acch[k];

    float rden = 1.0f / fmaxf((float)(e - s), 1.0f);
    float vp0 = 0, vp1 = 0, vp2 = 0;
    #pragma unroll
    for (int j = 0; j < 7; j++) {
        int c = lane + 32 * j;
        float m0 = cb0[j] * rden, m1 = cb1[j] * rden, m2 = cb2[j] * rden;
        ws[c] = m0*m0 + m1*m1 + m2*m2;
        float wv = __ldg(&w_vmix[c]);
        vp0 += wv * m0; vp1 += wv * m1; vp2 += wv * m2;
    }
    #pragma unroll
    for (int off = 16; off; off >>= 1) {
        vp0 += __shfl_xor_sync(FULL, vp0, off);
        vp1 += __shfl_xor_sync(FULL, vp1, off);
        vp2 += __shfl_xor_sync(FULL, vp2, off);
    }
    __syncwarp();

    float o1 = __ldg(&b_p1[lane]);
    for (int c = 0; c < NC; c++) o1 += ws[c] * __ldg(&w_p1[c * 32 + lane]);
    o1 = siluf(o1);
    float o2 = __ldg(&b_p2[lane]);
    for (int c = 0; c < 32; c++)
        o2 += __shfl_sync(FULL, o1, c) * __ldg(&w_p2[c * 32 + lane]);
    float hspat = siluf(o2);

    float hv = h[node * 32 + lane];
    float n1 = __ldg(&b_n1[lane]);
    for (int c = 0; c < 32; c++)
        n1 += __shfl_sync(FULL, hv, c) * __ldg(&w_n1[c * 32 + lane]);
    for (int c = 0; c < NC; c++)
        n1 += ws[224 + c] * __ldg(&w_n1[(32 + c) * 32 + lane]);
    for (int c = 0; c < 32; c++)
        n1 += __shfl_sync(FULL, hspat, c) * __ldg(&w_n1[(256 + c) * 32 + lane]);
    n1 = siluf(n1);
    float n2 = __ldg(&b_n2[lane]);
    for (int c = 0; c < 32; c++)
        n2 += __shfl_sync(FULL, n1, c) * __ldg(&w_n2[c * 32 + lane]);
    float hup = hv + siluf(n2);
    out[node * 32 + lane] = hup;

    float v1 = __ldg(&b_v1[lane]);
    for (int c = 0; c < 32; c++)
        v1 += __shfl_sync(FULL, hv, c) * __ldg(&w_v1[c * 32 + lane]);
    v1 = siluf(v1);
    float sv = v1 * __ldg(&w_v2[lane]);
    #pragma unroll
    for (int off = 16; off; off >>= 1) sv += __shfl_xor_sync(FULL, sv, off);
    float scale = 2.0f / (1.0f + __expf(-sv));

    if (lane < 3) {
        float dv = (lane == 0) ? vp0 : ((lane == 1) ? vp1 : vp2);
        float vu = scale * v[node * 3 + lane] + dv;
        out[NN * 32 + node * 3 + lane] = x[node * 3 + lane] + vu;
        out[NN * 32 + NN * 3 + node * 3 + lane] = vu;
    }
}

// ---------------- launch ----------------
extern "C" void kernel_launch(void* const* d_in, const int* in_sizes, int n_in,
                              void* d_out, int out_size)
{
    const float* h  = (const float*)d_in[0];
    const float* x  = (const float*)d_in[1];
    const float* v  = (const float*)d_in[2];
    const int*   pl = (const int*)d_in[3];

    int edge_smem = (128 * ACTS + 128 * FBS + 128 + 56 + 32 + 32 + 8) * 4;  // ~66.6 KB
    int gemm_smem = (64 * SEMS + 2048 + 448) * 4;                            // ~68.4 KB
    cudaFuncSetAttribute(edge_kernel, cudaFuncAttributeMaxDynamicSharedMemorySize, edge_smem);
    cudaFuncSetAttribute(gemm_kernel, cudaFuncAttributeMaxDynamicSharedMemorySize, gemm_smem);

    zero_kernel<<<(NN + 255) / 256, 256>>>();
    count_kernel<<<(NP + 255) / 256, 256>>>(pl);
    wsplit_kernel<<<34, 256>>>((const float*)d_in[4], (const float*)d_in[6],
                               (const float*)d_in[8], (const float*)d_in[10]);
    edge_kernel<<<NP / 128, 128, edge_smem>>>(
        h, x, pl,
        (const float*)d_in[5], (const float*)d_in[7],
        (const float*)d_in[9], (const float*)d_in[11]);
    scan1_kernel<<<40, 256>>>();
    scan2_kernel<<<1, 64>>>();
    scan3_kernel<<<40, 256>>>();
    scatter_kernel<<<(NP + 255) / 256, 256>>>(pl);
    softmax_kernel<<<NN / 8, 256>>>();
    gemm_kernel<<<NP / 64, 256, gemm_smem>>>((const float*)d_in[23]);

    node_kernel<<<NN / 8, 256>>>(
        h, x, v,
        (const float*)d_in[16], (const float*)d_in[17],   // w_p1, b_p1
        (const float*)d_in[18], (const float*)d_in[19],   // w_p2, b_p2
        (const float*)d_in[12], (const float*)d_in[13],   // w_n1, b_n1
        (const float*)d_in[14], (const float*)d_in[15],   // w_n2, b_n2
        (const float*)d_in[20], (const float*)d_in[21],   // w_v1, b_v1
        (const float*)d_in[22], (const float*)d_in[24],   // w_v2, w_vmix
        (float*)d_out);
}

// round 14
// speedup vs baseline: 1.1356x; 1.0498x over previous
#include <cuda_runtime.h>
#include <math.h>

#define NP 160000
#define NN 10000
#define FD 32
#define NH 7
#define NC 224
#define NRBF 50

// ---------------- scratch (device globals; all per-edge arrays CSR-ordered) --
__device__ float g_hedgeR[NP * FD];
__device__ float g_logits[NP * NH];
__device__ float g_att[NP * NH];
__device__ float g_dir[NP * 3];
__device__ float g_xmix[NP * NC];
__device__ int   g_counts[NN];
__device__ int   g_cursor[NN];
__device__ int   g_offsets[NN + 1];
__device__ int   g_order[NP];
__device__ int   g_bsum[40];
__device__ int   g_boff[40];

// pre-split edge weights: float2(hi, lo), tf32-rounded fp32 bit patterns
__device__ float2 g_w1[64 * 56];
__device__ float2 g_w2a[64 * 32];
__device__ float2 g_w2b[56 * 32];
__device__ float2 g_w3[32 * 32];
__device__ float2 g_w4[32 * 8];

__device__ __forceinline__ float siluf(float z) { return z / (1.0f + __expf(-z)); }
__device__ __forceinline__ float ftanh(float z) {
    float e = __expf(2.0f * z);
    return 1.0f - __fdividef(2.0f, e + 1.0f);
}

// tf32 helpers
__device__ __forceinline__ void split_tf32(float f, unsigned& hi, unsigned& lo) {
    asm("cvt.rna.tf32.f32 %0, %1;" : "=r"(hi) : "f"(f));
    float rem = f - __uint_as_float(hi);
    asm("cvt.rna.tf32.f32 %0, %1;" : "=r"(lo) : "f"(rem));
}
__device__ __forceinline__ void mma_tf32(float c[4], const unsigned a[4], const unsigned b[2]) {
    asm("mma.sync.aligned.m16n8k8.row.col.f32.tf32.tf32.f32 "
        "{%0,%1,%2,%3}, {%4,%5,%6,%7}, {%8,%9}, {%0,%1,%2,%3};"
        : "+f"(c[0]), "+f"(c[1]), "+f"(c[2]), "+f"(c[3])
        : "r"(a[0]), "r"(a[1]), "r"(a[2]), "r"(a[3]), "r"(b[0]), "r"(b[1]));
}
__device__ __forceinline__ void load_a_split(const float* base, int stride, int r0,
                                             int kg, int grp, int tg,
                                             unsigned Ah[4], unsigned Al[4]) {
    float a0 = base[(r0 + grp) * stride + kg + tg];
    float a1 = base[(r0 + grp + 8) * stride + kg + tg];
    float a2 = base[(r0 + grp) * stride + kg + tg + 4];
    float a3 = base[(r0 + grp + 8) * stride + kg + tg + 4];
    split_tf32(a0, Ah[0], Al[0]);
    split_tf32(a1, Ah[1], Al[1]);
    split_tf32(a2, Ah[2], Al[2]);
    split_tf32(a3, Ah[3], Al[3]);
}
__device__ __forceinline__ void mma3v(float C[4], const unsigned Ah[4], const unsigned Al[4],
                                      const unsigned Bh[2], const unsigned Bl[2]) {
    mma_tf32(C, Ah, Bh);
    mma_tf32(C, Ah, Bl);
    mma_tf32(C, Al, Bh);
}

// ---------------- weight pre-split prep ----------------
__device__ __forceinline__ float2 sp2(float v) {
    unsigned hi, lo; split_tf32(v, hi, lo);
    return make_float2(__uint_as_float(hi), __uint_as_float(lo));
}
__global__ void wsplit_kernel(const float* __restrict__ wmlp, const float* __restrict__ we1,
                              const float* __restrict__ we2,  const float* __restrict__ watt) {
    int t = blockIdx.x * 256 + threadIdx.x;
    if (t < 3584) {
        int k = t / 56, n = t - k * 56;
        g_w1[t] = sp2((n < NRBF) ? wmlp[k * NRBF + n] : 0.0f);
    } else if (t < 5632) {
        int i = t - 3584;
        g_w2a[i] = sp2(we1[i]);
    } else if (t < 7424) {
        int i = t - 5632;
        int k = i >> 5, n = i & 31;
        float v = (k < NRBF) ? we1[(64 + k) * FD + n]
                : ((k == NRBF) ? we1[114 * FD + n] : 0.0f);
        g_w2b[i] = sp2(v);
    } else if (t < 8448) {
        int i = t - 7424;
        g_w3[i] = sp2(we2[i]);
    } else if (t < 8704) {
        int i = t - 8448;
        int k = i >> 3, n = i & 7;
        g_w4[i] = sp2((n < NH) ? watt[k * NH + n] : 0.0f);
    }
}

// ---------------- CSR build ----------------
__global__ void zero_kernel() {
    int i = blockIdx.x * 256 + threadIdx.x;
    if (i < NN) { g_counts[i] = 0; g_cursor[i] = 0; }
}

__global__ void count_kernel(const int* __restrict__ pl) {
    int p = blockIdx.x * 256 + threadIdx.x;
    if (p < NP) atomicAdd(&g_counts[pl[p]], 1);
}

__global__ void scan1_kernel() {
    __shared__ int sh[256];
    int b = blockIdx.x, t = threadIdx.x, idx = b * 256 + t;
    int v = (idx < NN) ? g_counts[idx] : 0;
    sh[t] = v;
    __syncthreads();
    #pragma unroll
    for (int off = 1; off < 256; off <<= 1) {
        int a = (t >= off) ? sh[t - off] : 0;
        __syncthreads();
        sh[t] += a;
        __syncthreads();
    }
    if (idx < NN) g_offsets[idx + 1] = sh[t];
    if (t == 255) g_bsum[b] = sh[255];
    if (b == 0 && t == 0) g_offsets[0] = 0;
}
__global__ void scan2_kernel() {
    __shared__ int sh[64];
    int t = threadIdx.x;
    int v = (t < 40) ? g_bsum[t] : 0;
    sh[t] = v;
    __syncthreads();
    #pragma unroll
    for (int off = 1; off < 64; off <<= 1) {
        int a = (t >= off) ? sh[t - off] : 0;
        __syncthreads();
        sh[t] += a;
        __syncthreads();
    }
    if (t < 40) g_boff[t] = sh[t] - v;
}
__global__ void scan3_kernel() {
    int b = blockIdx.x, idx = b * 256 + threadIdx.x;
    if (idx < NN) g_offsets[idx + 1] += g_boff[b];
}

__global__ void scatter_kernel(const int* __restrict__ pl) {
    int p = blockIdx.x * 256 + threadIdx.x;
    if (p < NP) {
        int i = pl[p];
        int pos = g_offsets[i] + atomicAdd(&g_cursor[i], 1);
        g_order[pos] = p;
    }
}

// ---------------- edge model (CSR-permuted): block handles new indices ----
#define ACTS 68
#define FBS  60
__global__ void __launch_bounds__(128, 3) edge_kernel(
    const float* __restrict__ h, const float* __restrict__ x,
    const int* __restrict__ pl,
    const float* __restrict__ bmlp, const float* __restrict__ be1,
    const float* __restrict__ be2,  const float* __restrict__ batt)
{
    extern __shared__ float smem[];
    float* act  = smem;                    // [128][68]
    float* fbuf = act + 128 * ACTS;        // [128][60]
    float* dvec = fbuf + 128 * FBS;        // [128]
    float* s_bm = dvec + 128;              // [56]
    float* s_b1 = s_bm + 56;               // [32]
    float* s_b2 = s_b1 + 32;               // [32]
    float* s_ba = s_b2 + 32;               // [8]

    int tid = threadIdx.x;
    int p0 = blockIdx.x * 128;

    if (tid < 56) s_bm[tid] = (tid < NRBF) ? bmlp[tid] : 0.0f;
    if (tid < 32) { s_b1[tid] = be1[tid]; s_b2[tid] = be2[tid]; }
    if (tid < 8)  s_ba[tid] = (tid < NH) ? batt[tid] : 0.0f;

    // stage h_cat + d + dir at NEW index; pair = g_order[new]
    {
        int m = tid, pnew = p0 + m;
        int porig = g_order[pnew];
        int i = pl[porig], j = pl[NP + porig];
        const float4* si = (const float4*)(h + i * FD);
        const float4* sj = (const float4*)(h + j * FD);
        float4* dst = (float4*)(act + m * ACTS);
        #pragma unroll
        for (int q = 0; q < 8; q++) dst[q] = si[q];
        #pragma unroll
        for (int q = 0; q < 8; q++) dst[8 + q] = sj[q];

        float r0 = x[j*3]   - x[i*3];
        float r1 = x[j*3+1] - x[i*3+1];
        float r2 = x[j*3+2] - x[i*3+2];
        float d = sqrtf(r0*r0 + r1*r1 + r2*r2);
        float inv = 1.0f / (d + 1e-5f);
        g_dir[pnew*3]   = r0 * inv;
        g_dir[pnew*3+1] = r1 * inv;
        g_dir[pnew*3+2] = r2 * inv;
        dvec[m] = d;
    }
    __syncthreads();

    int lane = tid & 31, wid = tid >> 5;
    int grp = lane >> 2, tg = lane & 3;
    int rt0 = wid * 16, rt1 = wid * 16 + 64;
    unsigned Ah[2][4], Al[2][4];

    float C2[2][4][4];
    #pragma unroll
    for (int mt = 0; mt < 2; mt++)
        #pragma unroll
        for (int nt = 0; nt < 4; nt++)
            #pragma unroll
            for (int q = 0; q < 4; q++) C2[mt][nt][q] = 0.0f;

    // ======== fused: C1 = h_cat@w1 and C2 += h_cat@w2a ====
    {
        float C1[2][7][4];
        #pragma unroll
        for (int mt = 0; mt < 2; mt++)
            #pragma unroll
            for (int nt = 0; nt < 7; nt++)
                #pragma unroll
                for (int q = 0; q < 4; q++) C1[mt][nt][q] = 0.0f;
        #pragma unroll
        for (int k8 = 0; k8 < 8; k8++) {
            int kg = k8 * 8;
            load_a_split(act, ACTS, rt0, kg, grp, tg, Ah[0], Al[0]);
            load_a_split(act, ACTS, rt1, kg, grp, tg, Ah[1], Al[1]);
            #pragma unroll
            for (int nt = 0; nt < 7; nt++) {
                float2 b0 = __ldg(&g_w1[(kg + tg) * 56 + nt * 8 + grp]);
                float2 b1 = __ldg(&g_w1[(kg + tg + 4) * 56 + nt * 8 + grp]);
                unsigned Bh[2] = { __float_as_uint(b0.x), __float_as_uint(b1.x) };
                unsigned Bl[2] = { __float_as_uint(b0.y), __float_as_uint(b1.y) };
                mma3v(C1[0][nt], Ah[0], Al[0], Bh, Bl);
                mma3v(C1[1][nt], Ah[1], Al[1], Bh, Bl);
            }
            #pragma unroll
            for (int nt = 0; nt < 4; nt++) {
                float2 b0 = __ldg(&g_w2a[(kg + tg) * 32 + nt * 8 + grp]);
                float2 b1 = __ldg(&g_w2a[(kg + tg + 4) * 32 + nt * 8 + grp]);
                unsigned Bh[2] = { __float_as_uint(b0.x), __float_as_uint(b1.x) };
                unsigned Bl[2] = { __float_as_uint(b0.y), __float_as_uint(b1.y) };
                mma3v(C2[0][nt], Ah[0], Al[0], Bh, Bl);
                mma3v(C2[1][nt], Ah[1], Al[1], Bh, Bl);
            }
        }
        #pragma unroll
        for (int mt = 0; mt < 2; mt++) {
            int rr = (mt == 0) ? rt0 : rt1;
            float dlo = dvec[rr + grp], dhi = dvec[rr + grp + 8];
            #pragma unroll
            for (int nt = 0; nt < 7; nt++) {
                #pragma unroll
                for (int half = 0; half < 2; half++) {
                    int n = nt * 8 + 2 * tg + half;
                    float clo = C1[mt][nt][half], chi = C1[mt][nt][2 + half];
                    float ce = (float)n * (5.0f / 49.0f);
                    float vlo, vhi;
                    if (n < NRBF) {
                        float glo = __expf(-10.0f * (dlo - ce) * (dlo - ce));
                        float ghi = __expf(-10.0f * (dhi - ce) * (dhi - ce));
                        vlo = glo * (clo + s_bm[n]);
                        vhi = ghi * (chi + s_bm[n]);
                    } else if (n == NRBF) { vlo = dlo; vhi = dhi; }
                    else { vlo = 0.0f; vhi = 0.0f; }
                    fbuf[(rr + grp) * FBS + n] = vlo;
                    fbuf[(rr + grp + 8) * FBS + n] = vhi;
                }
            }
        }
    }
    __syncwarp();

    // ======== stage 2b: C2 += fbuf @ w2b ========
    {
        #pragma unroll
        for (int k8 = 0; k8 < 7; k8++) {
            int kg = k8 * 8;
            load_a_split(fbuf, FBS, rt0, kg, grp, tg, Ah[0], Al[0]);
            load_a_split(fbuf, FBS, rt1, kg, grp, tg, Ah[1], Al[1]);
            #pragma unroll
            for (int nt = 0; nt < 4; nt++) {
                float2 b0 = __ldg(&g_w2b[(kg + tg) * 32 + nt * 8 + grp]);
                float2 b1 = __ldg(&g_w2b[(kg + tg + 4) * 32 + nt * 8 + grp]);
                unsigned Bh[2] = { __float_as_uint(b0.x), __float_as_uint(b1.x) };
                unsigned Bl[2] = { __float_as_uint(b0.y), __float_as_uint(b1.y) };
                mma3v(C2[0][nt], Ah[0], Al[0], Bh, Bl);
                mma3v(C2[1][nt], Ah[1], Al[1], Bh, Bl);
            }
        }
        #pragma unroll
        for (int mt = 0; mt < 2; mt++) {
            int rr = (mt == 0) ? rt0 : rt1;
            #pragma unroll
            for (int nt = 0; nt < 4; nt++) {
                #pragma unroll
                for (int half = 0; half < 2; half++) {
                    int n = nt * 8 + 2 * tg + half;
                    act[(rr + grp) * ACTS + n] = siluf(C2[mt][nt][half] + s_b1[n]);
                    act[(rr + grp + 8) * ACTS + n] = siluf(C2[mt][nt][2 + half] + s_b1[n]);
                }
            }
        }
    }
    __syncwarp();

    // ======== stage 3: a3 = act[:,0..31] @ w3 ========
    {
        float C3[2][4][4];
        #pragma unroll
        for (int mt = 0; mt < 2; mt++)
            #pragma unroll
            for (int nt = 0; nt < 4; nt++)
                #pragma unroll
                for (int q = 0; q < 4; q++) C3[mt][nt][q] = 0.0f;
        #pragma unroll
        for (int k8 = 0; k8 < 4; k8++) {
            int kg = k8 * 8;
            load_a_split(act, ACTS, rt0, kg, grp, tg, Ah[0], Al[0]);
            load_a_split(act, ACTS, rt1, kg, grp, tg, Ah[1], Al[1]);
            #pragma unroll
            for (int nt = 0; nt < 4; nt++) {
                float2 b0 = __ldg(&g_w3[(kg + tg) * 32 + nt * 8 + grp]);
                float2 b1 = __ldg(&g_w3[(kg + tg + 4) * 32 + nt * 8 + grp]);
                unsigned Bh[2] = { __float_as_uint(b0.x), __float_as_uint(b1.x) };
                unsigned Bl[2] = { __float_as_uint(b0.y), __float_as_uint(b1.y) };
                mma3v(C3[0][nt], Ah[0], Al[0], Bh, Bl);
                mma3v(C3[1][nt], Ah[1], Al[1], Bh, Bl);
            }
        }
        #pragma unroll
        for (int mt = 0; mt < 2; mt++) {
            int rr = (mt == 0) ? rt0 : rt1;
            int plo = p0 + rr + grp, phi = plo + 8;
            #pragma unroll
            for (int nt = 0; nt < 4; nt++) {
                int n = nt * 8 + 2 * tg;
                float a0 = C3[mt][nt][0] + s_b2[n], a1 = C3[mt][nt][1] + s_b2[n + 1];
                float a2 = C3[mt][nt][2] + s_b2[n], a3v = C3[mt][nt][3] + s_b2[n + 1];
                fbuf[(rr + grp) * FBS + n] = a0;     fbuf[(rr + grp) * FBS + n + 1] = a1;
                fbuf[(rr + grp + 8) * FBS + n] = a2; fbuf[(rr + grp + 8) * FBS + n + 1] = a3v;
                *(float2*)(g_hedgeR + plo * FD + n) = make_float2(a0, a1);
                *(float2*)(g_hedgeR + phi * FD + n) = make_float2(a2, a3v);
            }
        }
    }
    __syncwarp();

    // ======== stage 4: logits = celu(a3 @ w4 + b_att) ========
    {
        float C4[2][4];
        #pragma unroll
        for (int mt = 0; mt < 2; mt++)
            #pragma unroll
            for (int q = 0; q < 4; q++) C4[mt][q] = 0.0f;
        #pragma unroll
        for (int k8 = 0; k8 < 4; k8++) {
            int kg = k8 * 8;
            load_a_split(fbuf, FBS, rt0, kg, grp, tg, Ah[0], Al[0]);
            load_a_split(fbuf, FBS, rt1, kg, grp, tg, Ah[1], Al[1]);
            float2 b0 = __ldg(&g_w4[(kg + tg) * 8 + grp]);
            float2 b1 = __ldg(&g_w4[(kg + tg + 4) * 8 + grp]);
            unsigned Bh[2] = { __float_as_uint(b0.x), __float_as_uint(b1.x) };
            unsigned Bl[2] = { __float_as_uint(b0.y), __float_as_uint(b1.y) };
            mma3v(C4[0], Ah[0], Al[0], Bh, Bl);
            mma3v(C4[1], Ah[1], Al[1], Bh, Bl);
        }
        #pragma unroll
        for (int mt = 0; mt < 2; mt++) {
            int rr = (mt == 0) ? rt0 : rt1;
            int plo = p0 + rr + grp, phi = plo + 8;
            #pragma unroll
            for (int half = 0; half < 2; half++) {
                int n = 2 * tg + half;
                if (n < NH) {
                    float zlo = C4[mt][half] + s_ba[n];
                    float zhi = C4[mt][2 + half] + s_ba[n];
                    g_logits[plo * NH + n] = (zlo > 0.0f) ? zlo : 2.0f * (__expf(0.5f * zlo) - 1.0f);
                    g_logits[phi * NH + n] = (zhi > 0.0f) ? zhi : 2.0f * (__expf(0.5f * zhi) - 1.0f);
                }
            }
        }
    }
}

// ---------------- scatter softmax: contiguous edges, no indirection -------
__global__ void __launch_bounds__(256) softmax_kernel() {
    int node = blockIdx.x * 8 + (threadIdx.x >> 5);
    int lane = threadIdx.x & 31;
    int s = g_offsets[node], e = g_offsets[node + 1];
    int cnt = e - s;
    const unsigned FULL = 0xffffffffu;

    if (cnt <= 32) {
        if (cnt == 0) return;
        bool have = lane < cnt;
        int p = s + (have ? lane : 0);
        float lg[NH];
        #pragma unroll
        for (int k = 0; k < NH; k++) lg[k] = g_logits[p * NH + k];

        float mx[NH], ex[NH], sm[NH];
        #pragma unroll
        for (int k = 0; k < NH; k++) {
            mx[k] = have ? lg[k] : -1e30f;
            #pragma unroll
            for (int off = 16; off; off >>= 1)
                mx[k] = fmaxf(mx[k], __shfl_xor_sync(FULL, mx[k], off));
            ex[k] = have ? __expf(lg[k] - mx[k]) : 0.0f;
            sm[k] = ex[k];
            #pragma unroll
            for (int off = 16; off; off >>= 1)
                sm[k] += __shfl_xor_sync(FULL, sm[k], off);
        }
        if (have) {
            #pragma unroll
            for (int k = 0; k < NH; k++)
                g_att[p * NH + k] = ex[k] / sm[k];
        }
    } else {
        float mx[NH];
        #pragma unroll
        for (int k = 0; k < NH; k++) mx[k] = -1e30f;
        for (int p = s + lane; p < e; p += 32)
            #pragma unroll
            for (int k = 0; k < NH; k++) mx[k] = fmaxf(mx[k], g_logits[p * NH + k]);
        #pragma unroll
        for (int k = 0; k < NH; k++)
            #pragma unroll
            for (int off = 16; off; off >>= 1)
                mx[k] = fmaxf(mx[k], __shfl_xor_sync(FULL, mx[k], off));

        float sm[NH];
        #pragma unroll
        for (int k = 0; k < NH; k++) sm[k] = 0.0f;
        for (int p = s + lane; p < e; p += 32)
            #pragma unroll
            for (int k = 0; k < NH; k++) sm[k] += __expf(g_logits[p * NH + k] - mx[k]);
        #pragma unroll
        for (int k = 0; k < NH; k++)
            #pragma unroll
            for (int off = 16; off; off >>= 1)
                sm[k] += __shfl_xor_sync(FULL, sm[k], off);

        for (int p = s + lane; p < e; p += 32)
            #pragma unroll
            for (int k = 0; k < NH; k++)
                g_att[p * NH + k] = __expf(g_logits[p * NH + k] - mx[k]) / sm[k];
    }
}

// ---------------- big GEMM via 3xTF32 mma.sync; BM=64, 2 CTAs/SM ---------
#define SEMS 228
__global__ void __launch_bounds__(256, 2) gemm_kernel(const float* __restrict__ wx) {
    extern __shared__ float sm[];
    float* sem = sm;               // [64][228]
    float* s_he = sem + 64 * SEMS; // [64][32]
    float* s_att = s_he + 2048;    // 448

    int tid = threadIdx.x;
    int m0 = blockIdx.x * 64;

    {
        int f = tid & 31, mrow = tid >> 5;
        #pragma unroll
        for (int it = 0; it < 8; it++) {
            int m = mrow + 8 * it;
            s_he[m * 32 + f] = g_hedgeR[(m0 + m) * FD + f];
        }
    }
    for (int t = tid; t < 448; t += 256) s_att[t] = g_att[m0 * NH + t];
    __syncthreads();

    for (int idx = tid; idx < 64 * NC; idx += 256) {
        int m = idx / NC, k = idx - m * NC;
        sem[m * SEMS + k] = s_he[m * 32 + k / 7] * s_att[m * 7 + (k % 7)];
    }
    __syncthreads();

    int lane = tid & 31, wid = tid >> 5;
    int wm = wid & 1;
    int wn = wid >> 1;
    int grp = lane >> 2, tg = lane & 3;

    float C[2][7][4];
    #pragma unroll
    for (int mt = 0; mt < 2; mt++)
        #pragma unroll
        for (int nt = 0; nt < 7; nt++)
            #pragma unroll
            for (int q = 0; q < 4; q++) C[mt][nt][q] = 0.0f;

    for (int kt = 0; kt < 4; kt++) {
        #pragma unroll
        for (int k8 = 0; k8 < 7; k8++) {
            int kg = kt * 56 + k8 * 8;

            unsigned Ah[2][4], Al[2][4];
            #pragma unroll
            for (int mt = 0; mt < 2; mt++)
                load_a_split(sem, SEMS, wm * 32 + mt * 16, kg, grp, tg, Ah[mt], Al[mt]);

            #pragma unroll
            for (int nt = 0; nt < 7; nt++) {
                int n0 = wn * 56 + nt * 8;
                float b0 = __ldg(&wx[(kg + tg) * NC + n0 + grp]);
                float b1 = __ldg(&wx[(kg + tg + 4) * NC + n0 + grp]);
                unsigned Bh[2], Bl[2];
                split_tf32(b0, Bh[0], Bl[0]);
                split_tf32(b1, Bh[1], Bl[1]);
                #pragma unroll
                for (int mt = 0; mt < 2; mt++) {
                    mma_tf32(C[mt][nt], Ah[mt], Bh);
                    mma_tf32(C[mt][nt], Ah[mt], Bl);
                    mma_tf32(C[mt][nt], Al[mt], Bh);
                }
            }
        }
    }

    #pragma unroll
    for (int mt = 0; mt < 2; mt++) {
        int rbase = m0 + wm * 32 + mt * 16 + grp;
        #pragma unroll
        for (int nt = 0; nt < 7; nt++) {
            int n0 = wn * 56 + nt * 8 + 2 * tg;
            float2 lo2 = make_float2(ftanh(C[mt][nt][0]), ftanh(C[mt][nt][1]));
            float2 hi2 = make_float2(ftanh(C[mt][nt][2]), ftanh(C[mt][nt][3]));
            *(float2*)(g_xmix + rbase * NC + n0) = lo2;
            *(float2*)(g_xmix + (rbase + 8) * NC + n0) = hi2;
        }
    }
}

// ---------------- per-node aggregation: contiguous streaming edges --------
__global__ void __launch_bounds__(256) node_kernel(
    const float* __restrict__ h, const float* __restrict__ x, const float* __restrict__ v,
    const float* __restrict__ w_p1, const float* __restrict__ b_p1,
    const float* __restrict__ w_p2, const float* __restrict__ b_p2,
    const float* __restrict__ w_n1, const float* __restrict__ b_n1,
    const float* __restrict__ w_n2, const float* __restrict__ b_n2,
    const float* __restrict__ w_v1, const float* __restrict__ b_v1,
    const float* __restrict__ w_v2, const float* __restrict__ w_vmix,
    float* __restrict__ out)
{
    __shared__ float sh[8 * 448];
    int wid = threadIdx.x >> 5, lane = threadIdx.x & 31;
    float* ws = sh + wid * 448;
    int node = blockIdx.x * 8 + wid;
    int s = g_offsets[node], e = g_offsets[node + 1];

    const unsigned FULL = 0xffffffffu;

    float acch[NH] = {0,0,0,0,0,0,0};
    float cb0[7] = {0,0,0,0,0,0,0};
    float cb1[7] = {0,0,0,0,0,0,0};
    float cb2[7] = {0,0,0,0,0,0,0};

    int p = s;
    for (; p + 3 < e; p += 4) {
        float he[4], at[4], dv[4];
        #pragma unroll
        for (int u = 0; u < 4; u++) {
            he[u] = g_hedgeR[(p + u) * FD + lane];
            at[u] = (lane < NH) ? g_att[(p + u) * NH + lane] : 0.0f;
            dv[u] = (lane < 3) ? g_dir[(p + u) * 3 + lane] : 0.0f;
        }
        float dd[4][3];
        #pragma unroll
        for (int u = 0; u < 4; u++) {
            dd[u][0] = __shfl_sync(FULL, dv[u], 0);
            dd[u][1] = __shfl_sync(FULL, dv[u], 1);
            dd[u][2] = __shfl_sync(FULL, dv[u], 2);
        }
        #pragma unroll
        for (int k = 0; k < NH; k++)
            #pragma unroll
            for (int u = 0; u < 4; u++)
                acch[k] += he[u] * __shfl_sync(FULL, at[u], k);
        #pragma unroll
        for (int j = 0; j < 7; j++) {
            #pragma unroll
            for (int u = 0; u < 4; u++) {
                float xm = g_xmix[(p + u) * NC + lane + 32 * j];
                cb0[j] += dd[u][0] * xm;
                cb1[j] += dd[u][1] * xm;
                cb2[j] += dd[u][2] * xm;
            }
        }
    }
    for (; p < e; p++) {
        float he0 = g_hedgeR[p * FD + lane];
        float at0 = (lane < NH) ? g_att[p * NH + lane] : 0.0f;
        float dv0 = (lane < 3) ? g_dir[p * 3 + lane] : 0.0f;
        float d00 = __shfl_sync(FULL, dv0, 0), d01 = __shfl_sync(FULL, dv0, 1), d02 = __shfl_sync(FULL, dv0, 2);
        #pragma unroll
        for (int k = 0; k < NH; k++)
            acch[k] += he0 * __shfl_sync(FULL, at0, k);
        #pragma unroll
        for (int j = 0; j < 7; j++) {
            float xm0 = g_xmix[p * NC + lane + 32 * j];
            cb0[j] += d00 * xm0;
            cb1[j] += d01 * xm0;
            cb2[j] += d02 * xm0;
        }
    }

    #pragma unroll
    for (int k = 0; k < NH; k++) ws[224 + lane * NH + k] = acch[k];

    float rden = 1.0f / fmaxf((float)(e - s), 1.0f);
    float vp0 = 0, vp1 = 0, vp2 = 0;
    #pragma unroll
    for (int j = 0; j < 7; j++) {
        int c = lane + 32 * j;
        float m0 = cb0[j] * rden, m1 = cb1[j] * rden, m2 = cb2[j] * rden;
        ws[c] = m0*m0 + m1*m1 + m2*m2;
        float wv = __ldg(&w_vmix[c]);
        vp0 += wv * m0; vp1 += wv * m1; vp2 += wv * m2;
    }
    #pragma unroll
    for (int off = 16; off; off >>= 1) {
        vp0 += __shfl_xor_sync(FULL, vp0, off);
        vp1 += __shfl_xor_sync(FULL, vp1, off);
        vp2 += __shfl_xor_sync(FULL, vp2, off);
    }
    __syncwarp();

    float o1 = __ldg(&b_p1[lane]);
    for (int c = 0; c < NC; c++) o1 += ws[c] * __ldg(&w_p1[c * 32 + lane]);
    o1 = siluf(o1);
    float o2 = __ldg(&b_p2[lane]);
    for (int c = 0; c < 32; c++)
        o2 += __shfl_sync(FULL, o1, c) * __ldg(&w_p2[c * 32 + lane]);
    float hspat = siluf(o2);

    float hv = h[node * 32 + lane];
    float n1 = __ldg(&b_n1[lane]);
    for (int c = 0; c < 32; c++)
        n1 += __shfl_sync(FULL, hv, c) * __ldg(&w_n1[c * 32 + lane]);
    for (int c = 0; c < NC; c++)
        n1 += ws[224 + c] * __ldg(&w_n1[(32 + c) * 32 + lane]);
    for (int c = 0; c < 32; c++)
        n1 += __shfl_sync(FULL, hspat, c) * __ldg(&w_n1[(256 + c) * 32 + lane]);
    n1 = siluf(n1);
    float n2 = __ldg(&b_n2[lane]);
    for (int c = 0; c < 32; c++)
        n2 += __shfl_sync(FULL, n1, c) * __ldg(&w_n2[c * 32 + lane]);
    float hup = hv + siluf(n2);
    out[node * 32 + lane] = hup;

    float v1 = __ldg(&b_v1[lane]);
    for (int c = 0; c < 32; c++)
        v1 += __shfl_sync(FULL, hv, c) * __ldg(&w_v1[c * 32 + lane]);
    v1 = siluf(v1);
    float sv = v1 * __ldg(&w_v2[lane]);
    #pragma unroll
    for (int off = 16; off; off >>= 1) sv += __shfl_xor_sync(FULL, sv, off);
    float scale = 2.0f / (1.0f + __expf(-sv));

    if (lane < 3) {
        float dv = (lane == 0) ? vp0 : ((lane == 1) ? vp1 : vp2);
        float vu = scale * v[node * 3 + lane] + dv;
        out[NN * 32 + node * 3 + lane] = x[node * 3 + lane] + vu;
        out[NN * 32 + NN * 3 + node * 3 + lane] = vu;
    }
}

// ---------------- launch ----------------
extern "C" void kernel_launch(void* const* d_in, const int* in_sizes, int n_in,
                              void* d_out, int out_size)
{
    const float* h  = (const float*)d_in[0];
    const float* x  = (const float*)d_in[1];
    const float* v  = (const float*)d_in[2];
    const int*   pl = (const int*)d_in[3];

    int edge_smem = (128 * ACTS + 128 * FBS + 128 + 56 + 32 + 32 + 8) * 4;  // ~66.6 KB
    int gemm_smem = (64 * SEMS + 2048 + 448) * 4;                            // ~68.4 KB
    cudaFuncSetAttribute(edge_kernel, cudaFuncAttributeMaxDynamicSharedMemorySize, edge_smem);
    cudaFuncSetAttribute(gemm_kernel, cudaFuncAttributeMaxDynamicSharedMemorySize, gemm_smem);

    zero_kernel<<<(NN + 255) / 256, 256>>>();
    count_kernel<<<(NP + 255) / 256, 256>>>(pl);
    wsplit_kernel<<<34, 256>>>((const float*)d_in[4], (const float*)d_in[6],
                               (const float*)d_in[8], (const float*)d_in[10]);
    scan1_kernel<<<40, 256>>>();
    scan2_kernel<<<1, 64>>>();
    scan3_kernel<<<40, 256>>>();
    scatter_kernel<<<(NP + 255) / 256, 256>>>(pl);
    edge_kernel<<<NP / 128, 128, edge_smem>>>(
        h, x, pl,
        (const float*)d_in[5], (const float*)d_in[7],
        (const float*)d_in[9], (const float*)d_in[11]);
    softmax_kernel<<<NN / 8, 256>>>();
    gemm_kernel<<<NP / 64, 256, gemm_smem>>>((const float*)d_in[23]);

    node_kernel<<<NN / 8, 256>>>(
        h, x, v,
        (const float*)d_in[16], (const float*)d_in[17],   // w_p1, b_p1
        (const float*)d_in[18], (const float*)d_in[19],   // w_p2, b_p2
        (const float*)d_in[12], (const float*)d_in[13],   // w_n1, b_n1
        (const float*)d_in[14], (const float*)d_in[15],   // w_n2, b_n2
        (const float*)d_in[20], (const float*)d_in[21],   // w_v1, b_v1
        (const float*)d_in[22], (const float*)d_in[24],   // w_v2, w_vmix
        (float*)d_out);
}

// round 15
// speedup vs baseline: 1.1830x; 1.0418x over previous
#include <cuda_runtime.h>
#include <cuda_fp16.h>
#include <math.h>

#define NP 160000
#define NN 10000
#define FD 32
#define NH 7
#define NC 224
#define NRBF 50

// ---------------- scratch (device globals; all per-edge arrays CSR-ordered) --
__device__ float  g_hedgeR[NP * FD];
__device__ float  g_logits[NP * NH];
__device__ float  g_att[NP * NH];
__device__ float  g_dir[NP * 3];
__device__ __half g_xmixh[NP * NC];       // fp16: tanh outputs in [-1,1]
__device__ int    g_counts[NN];
__device__ int    g_cursor[NN];
__device__ int    g_offsets[NN + 1];
__device__ int    g_order[NP];
__device__ int    g_bsum[40];
__device__ int    g_boff[40];

// pre-split edge weights: float2(hi, lo), tf32-rounded fp32 bit patterns
__device__ float2 g_w1[64 * 56];
__device__ float2 g_w2a[64 * 32];
__device__ float2 g_w2b[56 * 32];
__device__ float2 g_w3[32 * 32];
__device__ float2 g_w4[32 * 8];

__device__ __forceinline__ float siluf(float z) { return z / (1.0f + __expf(-z)); }
__device__ __forceinline__ float ftanh(float z) {
    float e = __expf(2.0f * z);
    return 1.0f - __fdividef(2.0f, e + 1.0f);
}

// tf32 helpers
__device__ __forceinline__ void split_tf32(float f, unsigned& hi, unsigned& lo) {
    asm("cvt.rna.tf32.f32 %0, %1;" : "=r"(hi) : "f"(f));
    float rem = f - __uint_as_float(hi);
    asm("cvt.rna.tf32.f32 %0, %1;" : "=r"(lo) : "f"(rem));
}
__device__ __forceinline__ void mma_tf32(float c[4], const unsigned a[4], const unsigned b[2]) {
    asm("mma.sync.aligned.m16n8k8.row.col.f32.tf32.tf32.f32 "
        "{%0,%1,%2,%3}, {%4,%5,%6,%7}, {%8,%9}, {%0,%1,%2,%3};"
        : "+f"(c[0]), "+f"(c[1]), "+f"(c[2]), "+f"(c[3])
        : "r"(a[0]), "r"(a[1]), "r"(a[2]), "r"(a[3]), "r"(b[0]), "r"(b[1]));
}
__device__ __forceinline__ void load_a_split(const float* base, int stride, int r0,
                                             int kg, int grp, int tg,
                                             unsigned Ah[4], unsigned Al[4]) {
    float a0 = base[(r0 + grp) * stride + kg + tg];
    float a1 = base[(r0 + grp + 8) * stride + kg + tg];
    float a2 = base[(r0 + grp) * stride + kg + tg + 4];
    float a3 = base[(r0 + grp + 8) * stride + kg + tg + 4];
    split_tf32(a0, Ah[0], Al[0]);
    split_tf32(a1, Ah[1], Al[1]);
    split_tf32(a2, Ah[2], Al[2]);
    split_tf32(a3, Ah[3], Al[3]);
}
__device__ __forceinline__ void mma3v(float C[4], const unsigned Ah[4], const unsigned Al[4],
                                      const unsigned Bh[2], const unsigned Bl[2]) {
    mma_tf32(C, Ah, Bh);
    mma_tf32(C, Ah, Bl);
    mma_tf32(C, Al, Bh);
}

// ---------------- weight pre-split prep ----------------
__device__ __forceinline__ float2 sp2(float v) {
    unsigned hi, lo; split_tf32(v, hi, lo);
    return make_float2(__uint_as_float(hi), __uint_as_float(lo));
}
__global__ void wsplit_kernel(const float* __restrict__ wmlp, const float* __restrict__ we1,
                              const float* __restrict__ we2,  const float* __restrict__ watt) {
    int t = blockIdx.x * 256 + threadIdx.x;
    if (t < 3584) {
        int k = t / 56, n = t - k * 56;
        g_w1[t] = sp2((n < NRBF) ? wmlp[k * NRBF + n] : 0.0f);
    } else if (t < 5632) {
        int i = t - 3584;
        g_w2a[i] = sp2(we1[i]);
    } else if (t < 7424) {
        int i = t - 5632;
        int k = i >> 5, n = i & 31;
        float v = (k < NRBF) ? we1[(64 + k) * FD + n]
                : ((k == NRBF) ? we1[114 * FD + n] : 0.0f);
        g_w2b[i] = sp2(v);
    } else if (t < 8448) {
        int i = t - 7424;
        g_w3[i] = sp2(we2[i]);
    } else if (t < 8704) {
        int i = t - 8448;
        int k = i >> 3, n = i & 7;
        g_w4[i] = sp2((n < NH) ? watt[k * NH + n] : 0.0f);
    }
}

// ---------------- CSR build ----------------
__global__ void zero_kernel() {
    int i = blockIdx.x * 256 + threadIdx.x;
    if (i < NN) { g_counts[i] = 0; g_cursor[i] = 0; }
}

__global__ void count_kernel(const int* __restrict__ pl) {
    int p = blockIdx.x * 256 + threadIdx.x;
    if (p < NP) atomicAdd(&g_counts[pl[p]], 1);
}

__global__ void scan1_kernel() {
    __shared__ int sh[256];
    int b = blockIdx.x, t = threadIdx.x, idx = b * 256 + t;
    int v = (idx < NN) ? g_counts[idx] : 0;
    sh[t] = v;
    __syncthreads();
    #pragma unroll
    for (int off = 1; off < 256; off <<= 1) {
        int a = (t >= off) ? sh[t - off] : 0;
        __syncthreads();
        sh[t] += a;
        __syncthreads();
    }
    if (idx < NN) g_offsets[idx + 1] = sh[t];
    if (t == 255) g_bsum[b] = sh[255];
    if (b == 0 && t == 0) g_offsets[0] = 0;
}
__global__ void scan2_kernel() {
    __shared__ int sh[64];
    int t = threadIdx.x;
    int v = (t < 40) ? g_bsum[t] : 0;
    sh[t] = v;
    __syncthreads();
    #pragma unroll
    for (int off = 1; off < 64; off <<= 1) {
        int a = (t >= off) ? sh[t - off] : 0;
        __syncthreads();
        sh[t] += a;
        __syncthreads();
    }
    if (t < 40) g_boff[t] = sh[t] - v;
}
__global__ void scan3_kernel() {
    int b = blockIdx.x, idx = b * 256 + threadIdx.x;
    if (idx < NN) g_offsets[idx + 1] += g_boff[b];
}

__global__ void scatter_kernel(const int* __restrict__ pl) {
    int p = blockIdx.x * 256 + threadIdx.x;
    if (p < NP) {
        int i = pl[p];
        int pos = g_offsets[i] + atomicAdd(&g_cursor[i], 1);
        g_order[pos] = p;
    }
}

// ---------------- edge model (CSR-permuted) ----------
#define ACTS 68
#define FBS  60
__global__ void __launch_bounds__(128, 3) edge_kernel(
    const float* __restrict__ h, const float* __restrict__ x,
    const int* __restrict__ pl,
    const float* __restrict__ bmlp, const float* __restrict__ be1,
    const float* __restrict__ be2,  const float* __restrict__ batt)
{
    extern __shared__ float smem[];
    float* act  = smem;                    // [128][68]
    float* fbuf = act + 128 * ACTS;        // [128][60]
    float* dvec = fbuf + 128 * FBS;        // [128]
    float* s_bm = dvec + 128;              // [56]
    float* s_b1 = s_bm + 56;               // [32]
    float* s_b2 = s_b1 + 32;               // [32]
    float* s_ba = s_b2 + 32;               // [8]

    int tid = threadIdx.x;
    int p0 = blockIdx.x * 128;

    if (tid < 56) s_bm[tid] = (tid < NRBF) ? bmlp[tid] : 0.0f;
    if (tid < 32) { s_b1[tid] = be1[tid]; s_b2[tid] = be2[tid]; }
    if (tid < 8)  s_ba[tid] = (tid < NH) ? batt[tid] : 0.0f;

    // stage h_cat + d + dir at NEW index; pair = g_order[new]
    {
        int m = tid, pnew = p0 + m;
        int porig = g_order[pnew];
        int i = pl[porig], j = pl[NP + porig];
        const float4* si = (const float4*)(h + i * FD);
        const float4* sj = (const float4*)(h + j * FD);
        float4* dst = (float4*)(act + m * ACTS);
        #pragma unroll
        for (int q = 0; q < 8; q++) dst[q] = si[q];
        #pragma unroll
        for (int q = 0; q < 8; q++) dst[8 + q] = sj[q];

        float r0 = x[j*3]   - x[i*3];
        float r1 = x[j*3+1] - x[i*3+1];
        float r2 = x[j*3+2] - x[i*3+2];
        float d = sqrtf(r0*r0 + r1*r1 + r2*r2);
        float inv = 1.0f / (d + 1e-5f);
        g_dir[pnew*3]   = r0 * inv;
        g_dir[pnew*3+1] = r1 * inv;
        g_dir[pnew*3+2] = r2 * inv;
        dvec[m] = d;
    }
    __syncthreads();

    int lane = tid & 31, wid = tid >> 5;
    int grp = lane >> 2, tg = lane & 3;
    int rt0 = wid * 16, rt1 = wid * 16 + 64;
    unsigned Ah[2][4], Al[2][4];

    float C2[2][4][4];
    #pragma unroll
    for (int mt = 0; mt < 2; mt++)
        #pragma unroll
        for (int nt = 0; nt < 4; nt++)
            #pragma unroll
            for (int q = 0; q < 4; q++) C2[mt][nt][q] = 0.0f;

    // ======== fused: C1 = h_cat@w1 and C2 += h_cat@w2a ====
    {
        float C1[2][7][4];
        #pragma unroll
        for (int mt = 0; mt < 2; mt++)
            #pragma unroll
            for (int nt = 0; nt < 7; nt++)
                #pragma unroll
                for (int q = 0; q < 4; q++) C1[mt][nt][q] = 0.0f;
        #pragma unroll
        for (int k8 = 0; k8 < 8; k8++) {
            int kg = k8 * 8;
            load_a_split(act, ACTS, rt0, kg, grp, tg, Ah[0], Al[0]);
            load_a_split(act, ACTS, rt1, kg, grp, tg, Ah[1], Al[1]);
            #pragma unroll
            for (int nt = 0; nt < 7; nt++) {
                float2 b0 = __ldg(&g_w1[(kg + tg) * 56 + nt * 8 + grp]);
                float2 b1 = __ldg(&g_w1[(kg + tg + 4) * 56 + nt * 8 + grp]);
                unsigned Bh[2] = { __float_as_uint(b0.x), __float_as_uint(b1.x) };
                unsigned Bl[2] = { __float_as_uint(b0.y), __float_as_uint(b1.y) };
                mma3v(C1[0][nt], Ah[0], Al[0], Bh, Bl);
                mma3v(C1[1][nt], Ah[1], Al[1], Bh, Bl);
            }
            #pragma unroll
            for (int nt = 0; nt < 4; nt++) {
                float2 b0 = __ldg(&g_w2a[(kg + tg) * 32 + nt * 8 + grp]);
                float2 b1 = __ldg(&g_w2a[(kg + tg + 4) * 32 + nt * 8 + grp]);
                unsigned Bh[2] = { __float_as_uint(b0.x), __float_as_uint(b1.x) };
                unsigned Bl[2] = { __float_as_uint(b0.y), __float_as_uint(b1.y) };
                mma3v(C2[0][nt], Ah[0], Al[0], Bh, Bl);
                mma3v(C2[1][nt], Ah[1], Al[1], Bh, Bl);
            }
        }
        #pragma unroll
        for (int mt = 0; mt < 2; mt++) {
            int rr = (mt == 0) ? rt0 : rt1;
            float dlo = dvec[rr + grp], dhi = dvec[rr + grp + 8];
            #pragma unroll
            for (int nt = 0; nt < 7; nt++) {
                #pragma unroll
                for (int half = 0; half < 2; half++) {
                    int n = nt * 8 + 2 * tg + half;
                    float clo = C1[mt][nt][half], chi = C1[mt][nt][2 + half];
                    float ce = (float)n * (5.0f / 49.0f);
                    float vlo, vhi;
                    if (n < NRBF) {
                        float glo = __expf(-10.0f * (dlo - ce) * (dlo - ce));
                        float ghi = __expf(-10.0f * (dhi - ce) * (dhi - ce));
                        vlo = glo * (clo + s_bm[n]);
                        vhi = ghi * (chi + s_bm[n]);
                    } else if (n == NRBF) { vlo = dlo; vhi = dhi; }
                    else { vlo = 0.0f; vhi = 0.0f; }
                    fbuf[(rr + grp) * FBS + n] = vlo;
                    fbuf[(rr + grp + 8) * FBS + n] = vhi;
                }
            }
        }
    }
    __syncwarp();

    // ======== stage 2b: C2 += fbuf @ w2b ========
    {
        #pragma unroll
        for (int k8 = 0; k8 < 7; k8++) {
            int kg = k8 * 8;
            load_a_split(fbuf, FBS, rt0, kg, grp, tg, Ah[0], Al[0]);
            load_a_split(fbuf, FBS, rt1, kg, grp, tg, Ah[1], Al[1]);
            #pragma unroll
            for (int nt = 0; nt < 4; nt++) {
                float2 b0 = __ldg(&g_w2b[(kg + tg) * 32 + nt * 8 + grp]);
                float2 b1 = __ldg(&g_w2b[(kg + tg + 4) * 32 + nt * 8 + grp]);
                unsigned Bh[2] = { __float_as_uint(b0.x), __float_as_uint(b1.x) };
                unsigned Bl[2] = { __float_as_uint(b0.y), __float_as_uint(b1.y) };
                mma3v(C2[0][nt], Ah[0], Al[0], Bh, Bl);
                mma3v(C2[1][nt], Ah[1], Al[1], Bh, Bl);
            }
        }
        #pragma unroll
        for (int mt = 0; mt < 2; mt++) {
            int rr = (mt == 0) ? rt0 : rt1;
            #pragma unroll
            for (int nt = 0; nt < 4; nt++) {
                #pragma unroll
                for (int half = 0; half < 2; half++) {
                    int n = nt * 8 + 2 * tg + half;
                    act[(rr + grp) * ACTS + n] = siluf(C2[mt][nt][half] + s_b1[n]);
                    act[(rr + grp + 8) * ACTS + n] = siluf(C2[mt][nt][2 + half] + s_b1[n]);
                }
            }
        }
    }
    __syncwarp();

    // ======== stage 3: a3 = act[:,0..31] @ w3 ========
    {
        float C3[2][4][4];
        #pragma unroll
        for (int mt = 0; mt < 2; mt++)
            #pragma unroll
            for (int nt = 0; nt < 4; nt++)
                #pragma unroll
                for (int q = 0; q < 4; q++) C3[mt][nt][q] = 0.0f;
        #pragma unroll
        for (int k8 = 0; k8 < 4; k8++) {
            int kg = k8 * 8;
            load_a_split(act, ACTS, rt0, kg, grp, tg, Ah[0], Al[0]);
            load_a_split(act, ACTS, rt1, kg, grp, tg, Ah[1], Al[1]);
            #pragma unroll
            for (int nt = 0; nt < 4; nt++) {
                float2 b0 = __ldg(&g_w3[(kg + tg) * 32 + nt * 8 + grp]);
                float2 b1 = __ldg(&g_w3[(kg + tg + 4) * 32 + nt * 8 + grp]);
                unsigned Bh[2] = { __float_as_uint(b0.x), __float_as_uint(b1.x) };
                unsigned Bl[2] = { __float_as_uint(b0.y), __float_as_uint(b1.y) };
                mma3v(C3[0][nt], Ah[0], Al[0], Bh, Bl);
                mma3v(C3[1][nt], Ah[1], Al[1], Bh, Bl);
            }
        }
        #pragma unroll
        for (int mt = 0; mt < 2; mt++) {
            int rr = (mt == 0) ? rt0 : rt1;
            int plo = p0 + rr + grp, phi = plo + 8;
            #pragma unroll
            for (int nt = 0; nt < 4; nt++) {
                int n = nt * 8 + 2 * tg;
                float a0 = C3[mt][nt][0] + s_b2[n], a1 = C3[mt][nt][1] + s_b2[n + 1];
                float a2 = C3[mt][nt][2] + s_b2[n], a3v = C3[mt][nt][3] + s_b2[n + 1];
                fbuf[(rr + grp) * FBS + n] = a0;     fbuf[(rr + grp) * FBS + n + 1] = a1;
                fbuf[(rr + grp + 8) * FBS + n] = a2; fbuf[(rr + grp + 8) * FBS + n + 1] = a3v;
                *(float2*)(g_hedgeR + plo * FD + n) = make_float2(a0, a1);
                *(float2*)(g_hedgeR + phi * FD + n) = make_float2(a2, a3v);
            }
        }
    }
    __syncwarp();

    // ======== stage 4: logits = celu(a3 @ w4 + b_att) ========
    {
        float C4[2][4];
        #pragma unroll
        for (int mt = 0; mt < 2; mt++)
            #pragma unroll
            for (int q = 0; q < 4; q++) C4[mt][q] = 0.0f;
        #pragma unroll
        for (int k8 = 0; k8 < 4; k8++) {
            int kg = k8 * 8;
            load_a_split(fbuf, FBS, rt0, kg, grp, tg, Ah[0], Al[0]);
            load_a_split(fbuf, FBS, rt1, kg, grp, tg, Ah[1], Al[1]);
            float2 b0 = __ldg(&g_w4[(kg + tg) * 8 + grp]);
            float2 b1 = __ldg(&g_w4[(kg + tg + 4) * 8 + grp]);
            unsigned Bh[2] = { __float_as_uint(b0.x), __float_as_uint(b1.x) };
            unsigned Bl[2] = { __float_as_uint(b0.y), __float_as_uint(b1.y) };
            mma3v(C4[0], Ah[0], Al[0], Bh, Bl);
            mma3v(C4[1], Ah[1], Al[1], Bh, Bl);
        }
        #pragma unroll
        for (int mt = 0; mt < 2; mt++) {
            int rr = (mt == 0) ? rt0 : rt1;
            int plo = p0 + rr + grp, phi = plo + 8;
            #pragma unroll
            for (int half = 0; half < 2; half++) {
                int n = 2 * tg + half;
                if (n < NH) {
                    float zlo = C4[mt][half] + s_ba[n];
                    float zhi = C4[mt][2 + half] + s_ba[n];
                    g_logits[plo * NH + n] = (zlo > 0.0f) ? zlo : 2.0f * (__expf(0.5f * zlo) - 1.0f);
                    g_logits[phi * NH + n] = (zhi > 0.0f) ? zhi : 2.0f * (__expf(0.5f * zhi) - 1.0f);
                }
            }
        }
    }
}

// ---------------- scatter softmax: contiguous edges -------
__global__ void __launch_bounds__(256) softmax_kernel() {
    int node = blockIdx.x * 8 + (threadIdx.x >> 5);
    int lane = threadIdx.x & 31;
    int s = g_offsets[node], e = g_offsets[node + 1];
    int cnt = e - s;
    const unsigned FULL = 0xffffffffu;

    if (cnt <= 32) {
        if (cnt == 0) return;
        bool have = lane < cnt;
        int p = s + (have ? lane : 0);
        float lg[NH];
        #pragma unroll
        for (int k = 0; k < NH; k++) lg[k] = g_logits[p * NH + k];

        float mx[NH], ex[NH], sm[NH];
        #pragma unroll
        for (int k = 0; k < NH; k++) {
            mx[k] = have ? lg[k] : -1e30f;
            #pragma unroll
            for (int off = 16; off; off >>= 1)
                mx[k] = fmaxf(mx[k], __shfl_xor_sync(FULL, mx[k], off));
            ex[k] = have ? __expf(lg[k] - mx[k]) : 0.0f;
            sm[k] = ex[k];
            #pragma unroll
            for (int off = 16; off; off >>= 1)
                sm[k] += __shfl_xor_sync(FULL, sm[k], off);
        }
        if (have) {
            #pragma unroll
            for (int k = 0; k < NH; k++)
                g_att[p * NH + k] = ex[k] / sm[k];
        }
    } else {
        float mx[NH];
        #pragma unroll
        for (int k = 0; k < NH; k++) mx[k] = -1e30f;
        for (int p = s + lane; p < e; p += 32)
            #pragma unroll
            for (int k = 0; k < NH; k++) mx[k] = fmaxf(mx[k], g_logits[p * NH + k]);
        #pragma unroll
        for (int k = 0; k < NH; k++)
            #pragma unroll
            for (int off = 16; off; off >>= 1)
                mx[k] = fmaxf(mx[k], __shfl_xor_sync(FULL, mx[k], off));

        float sm[NH];
        #pragma unroll
        for (int k = 0; k < NH; k++) sm[k] = 0.0f;
        for (int p = s + lane; p < e; p += 32)
            #pragma unroll
            for (int k = 0; k < NH; k++) sm[k] += __expf(g_logits[p * NH + k] - mx[k]);
        #pragma unroll
        for (int k = 0; k < NH; k++)
            #pragma unroll
            for (int off = 16; off; off >>= 1)
                sm[k] += __shfl_xor_sync(FULL, sm[k], off);

        for (int p = s + lane; p < e; p += 32)
            #pragma unroll
            for (int k = 0; k < NH; k++)
                g_att[p * NH + k] = __expf(g_logits[p * NH + k] - mx[k]) / sm[k];
    }
}

// ---------------- big GEMM via 3xTF32 mma.sync; fp16 output --------------
#define SEMS 228
__global__ void __launch_bounds__(256, 2) gemm_kernel(const float* __restrict__ wx) {
    extern __shared__ float sm[];
    float* sem = sm;               // [64][228]
    float* s_he = sem + 64 * SEMS; // [64][32]
    float* s_att = s_he + 2048;    // 448

    int tid = threadIdx.x;
    int m0 = blockIdx.x * 64;

    {
        int f = tid & 31, mrow = tid >> 5;
        #pragma unroll
        for (int it = 0; it < 8; it++) {
            int m = mrow + 8 * it;
            s_he[m * 32 + f] = g_hedgeR[(m0 + m) * FD + f];
        }
    }
    for (int t = tid; t < 448; t += 256) s_att[t] = g_att[m0 * NH + t];
    __syncthreads();

    for (int idx = tid; idx < 64 * NC; idx += 256) {
        int m = idx / NC, k = idx - m * NC;
        sem[m * SEMS + k] = s_he[m * 32 + k / 7] * s_att[m * 7 + (k % 7)];
    }
    __syncthreads();

    int lane = tid & 31, wid = tid >> 5;
    int wm = wid & 1;
    int wn = wid >> 1;
    int grp = lane >> 2, tg = lane & 3;

    float C[2][7][4];
    #pragma unroll
    for (int mt = 0; mt < 2; mt++)
        #pragma unroll
        for (int nt = 0; nt < 7; nt++)
            #pragma unroll
            for (int q = 0; q < 4; q++) C[mt][nt][q] = 0.0f;

    for (int kt = 0; kt < 4; kt++) {
        #pragma unroll
        for (int k8 = 0; k8 < 7; k8++) {
            int kg = kt * 56 + k8 * 8;

            unsigned Ah[2][4], Al[2][4];
            #pragma unroll
            for (int mt = 0; mt < 2; mt++)
                load_a_split(sem, SEMS, wm * 32 + mt * 16, kg, grp, tg, Ah[mt], Al[mt]);

            #pragma unroll
            for (int nt = 0; nt < 7; nt++) {
                int n0 = wn * 56 + nt * 8;
                float b0 = __ldg(&wx[(kg + tg) * NC + n0 + grp]);
                float b1 = __ldg(&wx[(kg + tg + 4) * NC + n0 + grp]);
                unsigned Bh[2], Bl[2];
                split_tf32(b0, Bh[0], Bl[0]);
                split_tf32(b1, Bh[1], Bl[1]);
                #pragma unroll
                for (int mt = 0; mt < 2; mt++) {
                    mma_tf32(C[mt][nt], Ah[mt], Bh);
                    mma_tf32(C[mt][nt], Ah[mt], Bl);
                    mma_tf32(C[mt][nt], Al[mt], Bh);
                }
            }
        }
    }

    #pragma unroll
    for (int mt = 0; mt < 2; mt++) {
        int rbase = m0 + wm * 32 + mt * 16 + grp;
        #pragma unroll
        for (int nt = 0; nt < 7; nt++) {
            int n0 = wn * 56 + nt * 8 + 2 * tg;
            __half2 lo2 = __floats2half2_rn(ftanh(C[mt][nt][0]), ftanh(C[mt][nt][1]));
            __half2 hi2 = __floats2half2_rn(ftanh(C[mt][nt][2]), ftanh(C[mt][nt][3]));
            *(__half2*)(g_xmixh + rbase * NC + n0) = lo2;
            *(__half2*)(g_xmixh + (rbase + 8) * NC + n0) = hi2;
        }
    }
}

// ---------------- per-node aggregation: contiguous streaming edges --------
__global__ void __launch_bounds__(256) node_kernel(
    const float* __restrict__ h, const float* __restrict__ x, const float* __restrict__ v,
    const float* __restrict__ w_p1, const float* __restrict__ b_p1,
    const float* __restrict__ w_p2, const float* __restrict__ b_p2,
    const float* __restrict__ w_n1, const float* __restrict__ b_n1,
    const float* __restrict__ w_n2, const float* __restrict__ b_n2,
    const float* __restrict__ w_v1, const float* __restrict__ b_v1,
    const float* __restrict__ w_v2, const float* __restrict__ w_vmix,
    float* __restrict__ out)
{
    __shared__ float sh[8 * 448];
    int wid = threadIdx.x >> 5, lane = threadIdx.x & 31;
    float* ws = sh + wid * 448;
    int node = blockIdx.x * 8 + wid;
    int s = g_offsets[node], e = g_offsets[node + 1];

    const unsigned FULL = 0xffffffffu;

    float acch[NH] = {0,0,0,0,0,0,0};
    float cb0[7] = {0,0,0,0,0,0,0};
    float cb1[7] = {0,0,0,0,0,0,0};
    float cb2[7] = {0,0,0,0,0,0,0};

    int p = s;
    for (; p + 3 < e; p += 4) {
        float he[4], at[4], dv[4];
        #pragma unroll
        for (int u = 0; u < 4; u++) {
            he[u] = g_hedgeR[(p + u) * FD + lane];
            at[u] = (lane < NH) ? g_att[(p + u) * NH + lane] : 0.0f;
            dv[u] = (lane < 3) ? g_dir[(p + u) * 3 + lane] : 0.0f;
        }
        float dd[4][3];
        #pragma unroll
        for (int u = 0; u < 4; u++) {
            dd[u][0] = __shfl_sync(FULL, dv[u], 0);
            dd[u][1] = __shfl_sync(FULL, dv[u], 1);
            dd[u][2] = __shfl_sync(FULL, dv[u], 2);
        }
        #pragma unroll
        for (int k = 0; k < NH; k++)
            #pragma unroll
            for (int u = 0; u < 4; u++)
                acch[k] += he[u] * __shfl_sync(FULL, at[u], k);
        #pragma unroll
        for (int j = 0; j < 7; j++) {
            #pragma unroll
            for (int u = 0; u < 4; u++) {
                float xm = __half2float(g_xmixh[(p + u) * NC + lane + 32 * j]);
                cb0[j] += dd[u][0] * xm;
                cb1[j] += dd[u][1] * xm;
                cb2[j] += dd[u][2] * xm;
            }
        }
    }
    for (; p < e; p++) {
        float he0 = g_hedgeR[p * FD + lane];
        float at0 = (lane < NH) ? g_att[p * NH + lane] : 0.0f;
        float dv0 = (lane < 3) ? g_dir[p * 3 + lane] : 0.0f;
        float d00 = __shfl_sync(FULL, dv0, 0), d01 = __shfl_sync(FULL, dv0, 1), d02 = __shfl_sync(FULL, dv0, 2);
        #pragma unroll
        for (int k = 0; k < NH; k++)
            acch[k] += he0 * __shfl_sync(FULL, at0, k);
        #pragma unroll
        for (int j = 0; j < 7; j++) {
            float xm0 = __half2float(g_xmixh[p * NC + lane + 32 * j]);
            cb0[j] += d00 * xm0;
            cb1[j] += d01 * xm0;
            cb2[j] += d02 * xm0;
        }
    }

    #pragma unroll
    for (int k = 0; k < NH; k++) ws[224 + lane * NH + k] = acch[k];

    float rden = 1.0f / fmaxf((float)(e - s), 1.0f);
    float vp0 = 0, vp1 = 0, vp2 = 0;
    #pragma unroll
    for (int j = 0; j < 7; j++) {
        int c = lane + 32 * j;
        float m0 = cb0[j] * rden, m1 = cb1[j] * rden, m2 = cb2[j] * rden;
        ws[c] = m0*m0 + m1*m1 + m2*m2;
        float wv = __ldg(&w_vmix[c]);
        vp0 += wv * m0; vp1 += wv * m1; vp2 += wv * m2;
    }
    #pragma unroll
    for (int off = 16; off; off >>= 1) {
        vp0 += __shfl_xor_sync(FULL, vp0, off);
        vp1 += __shfl_xor_sync(FULL, vp1, off);
        vp2 += __shfl_xor_sync(FULL, vp2, off);
    }
    __syncwarp();

    float o1 = __ldg(&b_p1[lane]);
    for (int c = 0; c < NC; c++) o1 += ws[c] * __ldg(&w_p1[c * 32 + lane]);
    o1 = siluf(o1);
    float o2 = __ldg(&b_p2[lane]);
    for (int c = 0; c < 32; c++)
        o2 += __shfl_sync(FULL, o1, c) * __ldg(&w_p2[c * 32 + lane]);
    float hspat = siluf(o2);

    float hv = h[node * 32 + lane];
    float n1 = __ldg(&b_n1[lane]);
    for (int c = 0; c < 32; c++)
        n1 += __shfl_sync(FULL, hv, c) * __ldg(&w_n1[c * 32 + lane]);
    for (int c = 0; c < NC; c++)
        n1 += ws[224 + c] * __ldg(&w_n1[(32 + c) * 32 + lane]);
    for (int c = 0; c < 32; c++)
        n1 += __shfl_sync(FULL, hspat, c) * __ldg(&w_n1[(256 + c) * 32 + lane]);
    n1 = siluf(n1);
    float n2 = __ldg(&b_n2[lane]);
    for (int c = 0; c < 32; c++)
        n2 += __shfl_sync(FULL, n1, c) * __ldg(&w_n2[c * 32 + lane]);
    float hup = hv + siluf(n2);
    out[node * 32 + lane] = hup;

    float v1 = __ldg(&b_v1[lane]);
    for (int c = 0; c < 32; c++)
        v1 += __shfl_sync(FULL, hv, c) * __ldg(&w_v1[c * 32 + lane]);
    v1 = siluf(v1);
    float sv = v1 * __ldg(&w_v2[lane]);
    #pragma unroll
    for (int off = 16; off; off >>= 1) sv += __shfl_xor_sync(FULL, sv, off);
    float scale = 2.0f / (1.0f + __expf(-sv));

    if (lane < 3) {
        float dv = (lane == 0) ? vp0 : ((lane == 1) ? vp1 : vp2);
        float vu = scale * v[node * 3 + lane] + dv;
        out[NN * 32 + node * 3 + lane] = x[node * 3 + lane] + vu;
        out[NN * 32 + NN * 3 + node * 3 + lane] = vu;
    }
}

// ---------------- launch ----------------
extern "C" void kernel_launch(void* const* d_in, const int* in_sizes, int n_in,
                              void* d_out, int out_size)
{
    const float* h  = (const float*)d_in[0];
    const float* x  = (const float*)d_in[1];
    const float* v  = (const float*)d_in[2];
    const int*   pl = (const int*)d_in[3];

    int edge_smem = (128 * ACTS + 128 * FBS + 128 + 56 + 32 + 32 + 8) * 4;  // ~66.6 KB
    int gemm_smem = (64 * SEMS + 2048 + 448) * 4;                            // ~68.4 KB
    cudaFuncSetAttribute(edge_kernel, cudaFuncAttributeMaxDynamicSharedMemorySize, edge_smem);
    cudaFuncSetAttribute(gemm_kernel, cudaFuncAttributeMaxDynamicSharedMemorySize, gemm_smem);

    zero_kernel<<<(NN + 255) / 256, 256>>>();
    count_kernel<<<(NP + 255) / 256, 256>>>(pl);
    wsplit_kernel<<<34, 256>>>((const float*)d_in[4], (const float*)d_in[6],
                               (const float*)d_in[8], (const float*)d_in[10]);
    scan1_kernel<<<40, 256>>>();
    scan2_kernel<<<1, 64>>>();
    scan3_kernel<<<40, 256>>>();
    scatter_kernel<<<(NP + 255) / 256, 256>>>(pl);
    edge_kernel<<<NP / 128, 128, edge_smem>>>(
        h, x, pl,
        (const float*)d_in[5], (const float*)d_in[7],
        (const float*)d_in[9], (const float*)d_in[11]);
    softmax_kernel<<<NN / 8, 256>>>();
    gemm_kernel<<<NP / 64, 256, gemm_smem>>>((const float*)d_in[23]);

    node_kernel<<<NN / 8, 256>>>(
        h, x, v,
        (const float*)d_in[16], (const float*)d_in[17],   // w_p1, b_p1
        (const float*)d_in[18], (const float*)d_in[19],   // w_p2, b_p2
        (const float*)d_in[12], (const float*)d_in[13],   // w_n1, b_n1
        (const float*)d_in[14], (const float*)d_in[15],   // w_n2, b_n2
        (const float*)d_in[20], (const float*)d_in[21],   // w_v1, b_v1
        (const float*)d_in[22], (const float*)d_in[24],   // w_v2, w_vmix
        (float*)d_out);
}

// round 16
// speedup vs baseline: 1.7316x; 1.4637x over previous
#include <cuda_runtime.h>
#include <cuda_fp16.h>
#include <math.h>

#define NP 160000
#define NN 10000
#define FD 32
#define NH 7
#define NC 224
#define NRBF 50

// ---------------- scratch (device globals; all per-edge arrays CSR-ordered) --
__device__ float  g_hedgeR[NP * FD];
__device__ float  g_logits[NP * NH];
__device__ float  g_att[NP * NH];
__device__ float  g_dir[NP * 3];
__device__ __half g_xmixh[NP * NC];       // fp16: tanh outputs in [-1,1]
__device__ int    g_counts[NN];
__device__ int    g_cursor[NN];
__device__ int    g_offsets[NN + 1];
__device__ int    g_order[NP];
__device__ int    g_bsum[40];
__device__ int    g_boff[40];

// pre-split edge weights: float2(hi, lo), tf32-rounded fp32 bit patterns
__device__ float2 g_w1[64 * 56];
__device__ float2 g_w2a[64 * 32];
__device__ float2 g_w2b[56 * 32];
__device__ float2 g_w3[32 * 32];
__device__ float2 g_w4[32 * 8];
// fp16 k-pair-packed w_xmix for HMMA: [(k/2)][n] = (wx[k][n], wx[k+1][n])
__device__ __half2 g_wxh2[112 * NC];

__device__ __forceinline__ float siluf(float z) { return z / (1.0f + __expf(-z)); }
__device__ __forceinline__ float ftanh(float z) {
    float e = __expf(2.0f * z);
    return 1.0f - __fdividef(2.0f, e + 1.0f);
}

// tf32 helpers
__device__ __forceinline__ void split_tf32(float f, unsigned& hi, unsigned& lo) {
    asm("cvt.rna.tf32.f32 %0, %1;" : "=r"(hi) : "f"(f));
    float rem = f - __uint_as_float(hi);
    asm("cvt.rna.tf32.f32 %0, %1;" : "=r"(lo) : "f"(rem));
}
__device__ __forceinline__ void mma_tf32(float c[4], const unsigned a[4], const unsigned b[2]) {
    asm("mma.sync.aligned.m16n8k8.row.col.f32.tf32.tf32.f32 "
        "{%0,%1,%2,%3}, {%4,%5,%6,%7}, {%8,%9}, {%0,%1,%2,%3};"
        : "+f"(c[0]), "+f"(c[1]), "+f"(c[2]), "+f"(c[3])
        : "r"(a[0]), "r"(a[1]), "r"(a[2]), "r"(a[3]), "r"(b[0]), "r"(b[1]));
}
// fp16 HMMA m16n8k16, fp32 accumulate
__device__ __forceinline__ void mma_f16(float c[4], const unsigned a[4], const unsigned b[2]) {
    asm("mma.sync.aligned.m16n8k16.row.col.f32.f16.f16.f32 "
        "{%0,%1,%2,%3}, {%4,%5,%6,%7}, {%8,%9}, {%0,%1,%2,%3};"
        : "+f"(c[0]), "+f"(c[1]), "+f"(c[2]), "+f"(c[3])
        : "r"(a[0]), "r"(a[1]), "r"(a[2]), "r"(a[3]), "r"(b[0]), "r"(b[1]));
}
__device__ __forceinline__ void load_a_split(const float* base, int stride, int r0,
                                             int kg, int grp, int tg,
                                             unsigned Ah[4], unsigned Al[4]) {
    float a0 = base[(r0 + grp) * stride + kg + tg];
    float a1 = base[(r0 + grp + 8) * stride + kg + tg];
    float a2 = base[(r0 + grp) * stride + kg + tg + 4];
    float a3 = base[(r0 + grp + 8) * stride + kg + tg + 4];
    split_tf32(a0, Ah[0], Al[0]);
    split_tf32(a1, Ah[1], Al[1]);
    split_tf32(a2, Ah[2], Al[2]);
    split_tf32(a3, Ah[3], Al[3]);
}
__device__ __forceinline__ void mma3v(float C[4], const unsigned Ah[4], const unsigned Al[4],
                                      const unsigned Bh[2], const unsigned Bl[2]) {
    mma_tf32(C, Ah, Bh);
    mma_tf32(C, Ah, Bl);
    mma_tf32(C, Al, Bh);
}

// ---------------- weight pre-split / pre-pack prep ----------------
__device__ __forceinline__ float2 sp2(float v) {
    unsigned hi, lo; split_tf32(v, hi, lo);
    return make_float2(__uint_as_float(hi), __uint_as_float(lo));
}
__global__ void wsplit_kernel(const float* __restrict__ wmlp, const float* __restrict__ we1,
                              const float* __restrict__ we2,  const float* __restrict__ watt,
                              const float* __restrict__ wx) {
    int t = blockIdx.x * 256 + threadIdx.x;
    if (t < 3584) {
        int k = t / 56, n = t - k * 56;
        g_w1[t] = sp2((n < NRBF) ? wmlp[k * NRBF + n] : 0.0f);
    } else if (t < 5632) {
        int i = t - 3584;
        g_w2a[i] = sp2(we1[i]);
    } else if (t < 7424) {
        int i = t - 5632;
        int k = i >> 5, n = i & 31;
        float v = (k < NRBF) ? we1[(64 + k) * FD + n]
                : ((k == NRBF) ? we1[114 * FD + n] : 0.0f);
        g_w2b[i] = sp2(v);
    } else if (t < 8448) {
        int i = t - 7424;
        g_w3[i] = sp2(we2[i]);
    } else if (t < 8704) {
        int i = t - 8448;
        int k = i >> 3, n = i & 7;
        g_w4[i] = sp2((n < NH) ? watt[k * NH + n] : 0.0f);
    } else if (t < 8704 + 112 * NC) {
        int i = t - 8704;
        int k2 = i / NC, n = i - k2 * NC;
        g_wxh2[i] = __floats2half2_rn(wx[(2 * k2) * NC + n], wx[(2 * k2 + 1) * NC + n]);
    }
}

// ---------------- CSR build ----------------
__global__ void zero_kernel() {
    int i = blockIdx.x * 256 + threadIdx.x;
    if (i < NN) { g_counts[i] = 0; g_cursor[i] = 0; }
}

__global__ void count_kernel(const int* __restrict__ pl) {
    int p = blockIdx.x * 256 + threadIdx.x;
    if (p < NP) atomicAdd(&g_counts[pl[p]], 1);
}

__global__ void scan1_kernel() {
    __shared__ int sh[256];
    int b = blockIdx.x, t = threadIdx.x, idx = b * 256 + t;
    int v = (idx < NN) ? g_counts[idx] : 0;
    sh[t] = v;
    __syncthreads();
    #pragma unroll
    for (int off = 1; off < 256; off <<= 1) {
        int a = (t >= off) ? sh[t - off] : 0;
        __syncthreads();
        sh[t] += a;
        __syncthreads();
    }
    if (idx < NN) g_offsets[idx + 1] = sh[t];
    if (t == 255) g_bsum[b] = sh[255];
    if (b == 0 && t == 0) g_offsets[0] = 0;
}
__global__ void scan2_kernel() {
    __shared__ int sh[64];
    int t = threadIdx.x;
    int v = (t < 40) ? g_bsum[t] : 0;
    sh[t] = v;
    __syncthreads();
    #pragma unroll
    for (int off = 1; off < 64; off <<= 1) {
        int a = (t >= off) ? sh[t - off] : 0;
        __syncthreads();
        sh[t] += a;
        __syncthreads();
    }
    if (t < 40) g_boff[t] = sh[t] - v;
}
__global__ void scan3_kernel() {
    int b = blockIdx.x, idx = b * 256 + threadIdx.x;
    if (idx < NN) g_offsets[idx + 1] += g_boff[b];
}

__global__ void scatter_kernel(const int* __restrict__ pl) {
    int p = blockIdx.x * 256 + threadIdx.x;
    if (p < NP) {
        int i = pl[p];
        int pos = g_offsets[i] + atomicAdd(&g_cursor[i], 1);
        g_order[pos] = p;
    }
}

// ---------------- edge model (CSR-permuted, 3xTF32) ----------
#define ACTS 68
#define FBS  60
__global__ void __launch_bounds__(128, 3) edge_kernel(
    const float* __restrict__ h, const float* __restrict__ x,
    const int* __restrict__ pl,
    const float* __restrict__ bmlp, const float* __restrict__ be1,
    const float* __restrict__ be2,  const float* __restrict__ batt)
{
    extern __shared__ float smem[];
    float* act  = smem;                    // [128][68]
    float* fbuf = act + 128 * ACTS;        // [128][60]
    float* dvec = fbuf + 128 * FBS;        // [128]
    float* s_bm = dvec + 128;              // [56]
    float* s_b1 = s_bm + 56;               // [32]
    float* s_b2 = s_b1 + 32;               // [32]
    float* s_ba = s_b2 + 32;               // [8]

    int tid = threadIdx.x;
    int p0 = blockIdx.x * 128;

    if (tid < 56) s_bm[tid] = (tid < NRBF) ? bmlp[tid] : 0.0f;
    if (tid < 32) { s_b1[tid] = be1[tid]; s_b2[tid] = be2[tid]; }
    if (tid < 8)  s_ba[tid] = (tid < NH) ? batt[tid] : 0.0f;

    // stage h_cat + d + dir at NEW index; pair = g_order[new]
    {
        int m = tid, pnew = p0 + m;
        int porig = g_order[pnew];
        int i = pl[porig], j = pl[NP + porig];
        const float4* si = (const float4*)(h + i * FD);
        const float4* sj = (const float4*)(h + j * FD);
        float4* dst = (float4*)(act + m * ACTS);
        #pragma unroll
        for (int q = 0; q < 8; q++) dst[q] = si[q];
        #pragma unroll
        for (int q = 0; q < 8; q++) dst[8 + q] = sj[q];

        float r0 = x[j*3]   - x[i*3];
        float r1 = x[j*3+1] - x[i*3+1];
        float r2 = x[j*3+2] - x[i*3+2];
        float d = sqrtf(r0*r0 + r1*r1 + r2*r2);
        float inv = 1.0f / (d + 1e-5f);
        g_dir[pnew*3]   = r0 * inv;
        g_dir[pnew*3+1] = r1 * inv;
        g_dir[pnew*3+2] = r2 * inv;
        dvec[m] = d;
    }
    __syncthreads();

    int lane = tid & 31, wid = tid >> 5;
    int grp = lane >> 2, tg = lane & 3;
    int rt0 = wid * 16, rt1 = wid * 16 + 64;
    unsigned Ah[2][4], Al[2][4];

    float C2[2][4][4];
    #pragma unroll
    for (int mt = 0; mt < 2; mt++)
        #pragma unroll
        for (int nt = 0; nt < 4; nt++)
            #pragma unroll
            for (int q = 0; q < 4; q++) C2[mt][nt][q] = 0.0f;

    // ======== fused: C1 = h_cat@w1 and C2 += h_cat@w2a ====
    {
        float C1[2][7][4];
        #pragma unroll
        for (int mt = 0; mt < 2; mt++)
            #pragma unroll
            for (int nt = 0; nt < 7; nt++)
                #pragma unroll
                for (int q = 0; q < 4; q++) C1[mt][nt][q] = 0.0f;
        #pragma unroll
        for (int k8 = 0; k8 < 8; k8++) {
            int kg = k8 * 8;
            load_a_split(act, ACTS, rt0, kg, grp, tg, Ah[0], Al[0]);
            load_a_split(act, ACTS, rt1, kg, grp, tg, Ah[1], Al[1]);
            #pragma unroll
            for (int nt = 0; nt < 7; nt++) {
                float2 b0 = __ldg(&g_w1[(kg + tg) * 56 + nt * 8 + grp]);
                float2 b1 = __ldg(&g_w1[(kg + tg + 4) * 56 + nt * 8 + grp]);
                unsigned Bh[2] = { __float_as_uint(b0.x), __float_as_uint(b1.x) };
                unsigned Bl[2] = { __float_as_uint(b0.y), __float_as_uint(b1.y) };
                mma3v(C1[0][nt], Ah[0], Al[0], Bh, Bl);
                mma3v(C1[1][nt], Ah[1], Al[1], Bh, Bl);
            }
            #pragma unroll
            for (int nt = 0; nt < 4; nt++) {
                float2 b0 = __ldg(&g_w2a[(kg + tg) * 32 + nt * 8 + grp]);
                float2 b1 = __ldg(&g_w2a[(kg + tg + 4) * 32 + nt * 8 + grp]);
                unsigned Bh[2] = { __float_as_uint(b0.x), __float_as_uint(b1.x) };
                unsigned Bl[2] = { __float_as_uint(b0.y), __float_as_uint(b1.y) };
                mma3v(C2[0][nt], Ah[0], Al[0], Bh, Bl);
                mma3v(C2[1][nt], Ah[1], Al[1], Bh, Bl);
            }
        }
        #pragma unroll
        for (int mt = 0; mt < 2; mt++) {
            int rr = (mt == 0) ? rt0 : rt1;
            float dlo = dvec[rr + grp], dhi = dvec[rr + grp + 8];
            #pragma unroll
            for (int nt = 0; nt < 7; nt++) {
                #pragma unroll
                for (int half = 0; half < 2; half++) {
                    int n = nt * 8 + 2 * tg + half;
                    float clo = C1[mt][nt][half], chi = C1[mt][nt][2 + half];
                    float ce = (float)n * (5.0f / 49.0f);
                    float vlo, vhi;
                    if (n < NRBF) {
                        float glo = __expf(-10.0f * (dlo - ce) * (dlo - ce));
                        float ghi = __expf(-10.0f * (dhi - ce) * (dhi - ce));
                        vlo = glo * (clo + s_bm[n]);
                        vhi = ghi * (chi + s_bm[n]);
                    } else if (n == NRBF) { vlo = dlo; vhi = dhi; }
                    else { vlo = 0.0f; vhi = 0.0f; }
                    fbuf[(rr + grp) * FBS + n] = vlo;
                    fbuf[(rr + grp + 8) * FBS + n] = vhi;
                }
            }
        }
    }
    __syncwarp();

    // ======== stage 2b: C2 += fbuf @ w2b ========
    {
        #pragma unroll
        for (int k8 = 0; k8 < 7; k8++) {
            int kg = k8 * 8;
            load_a_split(fbuf, FBS, rt0, kg, grp, tg, Ah[0], Al[0]);
            load_a_split(fbuf, FBS, rt1, kg, grp, tg, Ah[1], Al[1]);
            #pragma unroll
            for (int nt = 0; nt < 4; nt++) {
                float2 b0 = __ldg(&g_w2b[(kg + tg) * 32 + nt * 8 + grp]);
                float2 b1 = __ldg(&g_w2b[(kg + tg + 4) * 32 + nt * 8 + grp]);
                unsigned Bh[2] = { __float_as_uint(b0.x), __float_as_uint(b1.x) };
                unsigned Bl[2] = { __float_as_uint(b0.y), __float_as_uint(b1.y) };
                mma3v(C2[0][nt], Ah[0], Al[0], Bh, Bl);
                mma3v(C2[1][nt], Ah[1], Al[1], Bh, Bl);
            }
        }
        #pragma unroll
        for (int mt = 0; mt < 2; mt++) {
            int rr = (mt == 0) ? rt0 : rt1;
            #pragma unroll
            for (int nt = 0; nt < 4; nt++) {
                #pragma unroll
                for (int half = 0; half < 2; half++) {
                    int n = nt * 8 + 2 * tg + half;
                    act[(rr + grp) * ACTS + n] = siluf(C2[mt][nt][half] + s_b1[n]);
                    act[(rr + grp + 8) * ACTS + n] = siluf(C2[mt][nt][2 + half] + s_b1[n]);
                }
            }
        }
    }
    __syncwarp();

    // ======== stage 3: a3 = act[:,0..31] @ w3 ========
    {
        float C3[2][4][4];
        #pragma unroll
        for (int mt = 0; mt < 2; mt++)
            #pragma unroll
            for (int nt = 0; nt < 4; nt++)
                #pragma unroll
                for (int q = 0; q < 4; q++) C3[mt][nt][q] = 0.0f;
        #pragma unroll
        for (int k8 = 0; k8 < 4; k8++) {
            int kg = k8 * 8;
            load_a_split(act, ACTS, rt0, kg, grp, tg, Ah[0], Al[0]);
            load_a_split(act, ACTS, rt1, kg, grp, tg, Ah[1], Al[1]);
            #pragma unroll
            for (int nt = 0; nt < 4; nt++) {
                float2 b0 = __ldg(&g_w3[(kg + tg) * 32 + nt * 8 + grp]);
                float2 b1 = __ldg(&g_w3[(kg + tg + 4) * 32 + nt * 8 + grp]);
                unsigned Bh[2] = { __float_as_uint(b0.x), __float_as_uint(b1.x) };
                unsigned Bl[2] = { __float_as_uint(b0.y), __float_as_uint(b1.y) };
                mma3v(C3[0][nt], Ah[0], Al[0], Bh, Bl);
                mma3v(C3[1][nt], Ah[1], Al[1], Bh, Bl);
            }
        }
        #pragma unroll
        for (int mt = 0; mt < 2; mt++) {
            int rr = (mt == 0) ? rt0 : rt1;
            int plo = p0 + rr + grp, phi = plo + 8;
            #pragma unroll
            for (int nt = 0; nt < 4; nt++) {
                int n = nt * 8 + 2 * tg;
                float a0 = C3[mt][nt][0] + s_b2[n], a1 = C3[mt][nt][1] + s_b2[n + 1];
                float a2 = C3[mt][nt][2] + s_b2[n], a3v = C3[mt][nt][3] + s_b2[n + 1];
                fbuf[(rr + grp) * FBS + n] = a0;     fbuf[(rr + grp) * FBS + n + 1] = a1;
                fbuf[(rr + grp + 8) * FBS + n] = a2; fbuf[(rr + grp + 8) * FBS + n + 1] = a3v;
                *(float2*)(g_hedgeR + plo * FD + n) = make_float2(a0, a1);
                *(float2*)(g_hedgeR + phi * FD + n) = make_float2(a2, a3v);
            }
        }
    }
    __syncwarp();

    // ======== stage 4: logits = celu(a3 @ w4 + b_att) ========
    {
        float C4[2][4];
        #pragma unroll
        for (int mt = 0; mt < 2; mt++)
            #pragma unroll
            for (int q = 0; q < 4; q++) C4[mt][q] = 0.0f;
        #pragma unroll
        for (int k8 = 0; k8 < 4; k8++) {
            int kg = k8 * 8;
            load_a_split(fbuf, FBS, rt0, kg, grp, tg, Ah[0], Al[0]);
            load_a_split(fbuf, FBS, rt1, kg, grp, tg, Ah[1], Al[1]);
            float2 b0 = __ldg(&g_w4[(kg + tg) * 8 + grp]);
            float2 b1 = __ldg(&g_w4[(kg + tg + 4) * 8 + grp]);
            unsigned Bh[2] = { __float_as_uint(b0.x), __float_as_uint(b1.x) };
            unsigned Bl[2] = { __float_as_uint(b0.y), __float_as_uint(b1.y) };
            mma3v(C4[0], Ah[0], Al[0], Bh, Bl);
            mma3v(C4[1], Ah[1], Al[1], Bh, Bl);
        }
        #pragma unroll
        for (int mt = 0; mt < 2; mt++) {
            int rr = (mt == 0) ? rt0 : rt1;
            int plo = p0 + rr + grp, phi = plo + 8;
            #pragma unroll
            for (int half = 0; half < 2; half++) {
                int n = 2 * tg + half;
                if (n < NH) {
                    float zlo = C4[mt][half] + s_ba[n];
                    float zhi = C4[mt][2 + half] + s_ba[n];
                    g_logits[plo * NH + n] = (zlo > 0.0f) ? zlo : 2.0f * (__expf(0.5f * zlo) - 1.0f);
                    g_logits[phi * NH + n] = (zhi > 0.0f) ? zhi : 2.0f * (__expf(0.5f * zhi) - 1.0f);
                }
            }
        }
    }
}

// ---------------- scatter softmax: contiguous edges -------
__global__ void __launch_bounds__(256) softmax_kernel() {
    int node = blockIdx.x * 8 + (threadIdx.x >> 5);
    int lane = threadIdx.x & 31;
    int s = g_offsets[node], e = g_offsets[node + 1];
    int cnt = e - s;
    const unsigned FULL = 0xffffffffu;

    if (cnt <= 32) {
        if (cnt == 0) return;
        bool have = lane < cnt;
        int p = s + (have ? lane : 0);
        float lg[NH];
        #pragma unroll
        for (int k = 0; k < NH; k++) lg[k] = g_logits[p * NH + k];

        float mx[NH], ex[NH], sm[NH];
        #pragma unroll
        for (int k = 0; k < NH; k++) {
            mx[k] = have ? lg[k] : -1e30f;
            #pragma unroll
            for (int off = 16; off; off >>= 1)
                mx[k] = fmaxf(mx[k], __shfl_xor_sync(FULL, mx[k], off));
            ex[k] = have ? __expf(lg[k] - mx[k]) : 0.0f;
            sm[k] = ex[k];
            #pragma unroll
            for (int off = 16; off; off >>= 1)
                sm[k] += __shfl_xor_sync(FULL, sm[k], off);
        }
        if (have) {
            #pragma unroll
            for (int k = 0; k < NH; k++)
                g_att[p * NH + k] = ex[k] / sm[k];
        }
    } else {
        float mx[NH];
        #pragma unroll
        for (int k = 0; k < NH; k++) mx[k] = -1e30f;
        for (int p = s + lane; p < e; p += 32)
            #pragma unroll
            for (int k = 0; k < NH; k++) mx[k] = fmaxf(mx[k], g_logits[p * NH + k]);
        #pragma unroll
        for (int k = 0; k < NH; k++)
            #pragma unroll
            for (int off = 16; off; off >>= 1)
                mx[k] = fmaxf(mx[k], __shfl_xor_sync(FULL, mx[k], off));

        float sm[NH];
        #pragma unroll
        for (int k = 0; k < NH; k++) sm[k] = 0.0f;
        for (int p = s + lane; p < e; p += 32)
            #pragma unroll
            for (int k = 0; k < NH; k++) sm[k] += __expf(g_logits[p * NH + k] - mx[k]);
        #pragma unroll
        for (int k = 0; k < NH; k++)
            #pragma unroll
            for (int off = 16; off; off >>= 1)
                sm[k] += __shfl_xor_sync(FULL, sm[k], off);

        for (int p = s + lane; p < e; p += 32)
            #pragma unroll
            for (int k = 0; k < NH; k++)
                g_att[p * NH + k] = __expf(g_logits[p * NH + k] - mx[k]) / sm[k];
    }
}

// ---------------- big GEMM via fp16 HMMA m16n8k16; fp16 in/out -----------
#define SEMH 116   // half2 stride (conflict-free: grp*116+tg distinct mod 32)
__global__ void __launch_bounds__(256, 3) gemm_kernel() {
    extern __shared__ float smf[];
    __half2* semh = (__half2*)smf;            // [64][116] half2
    float* s_he  = smf + 64 * SEMH;           // 2048 floats (half2 == float footprint)
    float* s_att = s_he + 2048;               // 448

    int tid = threadIdx.x;
    int m0 = blockIdx.x * 64;

    {
        int f = tid & 31, mrow = tid >> 5;
        #pragma unroll
        for (int it = 0; it < 8; it++) {
            int m = mrow + 8 * it;
            s_he[m * 32 + f] = g_hedgeR[(m0 + m) * FD + f];
        }
    }
    for (int t = tid; t < 448; t += 256) s_att[t] = g_att[m0 * NH + t];
    __syncthreads();

    // build sem in half2: [m][k2] = (sem[m][2k2], sem[m][2k2+1])
    for (int idx = tid; idx < 64 * 112; idx += 256) {
        int m = idx / 112, k2 = idx - m * 112;
        int k = 2 * k2;
        float v0 = s_he[m * 32 + k / 7] * s_att[m * 7 + (k % 7)];
        float v1 = s_he[m * 32 + (k + 1) / 7] * s_att[m * 7 + ((k + 1) % 7)];
        semh[m * SEMH + k2] = __floats2half2_rn(v0, v1);
    }
    __syncthreads();

    int lane = tid & 31, wid = tid >> 5;
    int wm = wid & 1;
    int wn = wid >> 1;
    int grp = lane >> 2, tg = lane & 3;

    float C[2][7][4];
    #pragma unroll
    for (int mt = 0; mt < 2; mt++)
        #pragma unroll
        for (int nt = 0; nt < 7; nt++)
            #pragma unroll
            for (int q = 0; q < 4; q++) C[mt][nt][q] = 0.0f;

    #pragma unroll 2
    for (int ks = 0; ks < 14; ks++) {       // 14 k16 steps
        int kg2 = ks * 8;                    // half2 units

        unsigned A[2][4];
        #pragma unroll
        for (int mt = 0; mt < 2; mt++) {
            int r = wm * 32 + mt * 16;
            A[mt][0] = *(const unsigned*)&semh[(r + grp) * SEMH + kg2 + tg];
            A[mt][1] = *(const unsigned*)&semh[(r + grp + 8) * SEMH + kg2 + tg];
            A[mt][2] = *(const unsigned*)&semh[(r + grp) * SEMH + kg2 + tg + 4];
            A[mt][3] = *(const unsigned*)&semh[(r + grp + 8) * SEMH + kg2 + tg + 4];
        }

        #pragma unroll
        for (int nt = 0; nt < 7; nt++) {
            int n0 = wn * 56 + nt * 8;
            unsigned B[2];
            B[0] = *(const unsigned*)&g_wxh2[(kg2 + tg) * NC + n0 + grp];
            B[1] = *(const unsigned*)&g_wxh2[(kg2 + tg + 4) * NC + n0 + grp];
            mma_f16(C[0][nt], A[0], B);
            mma_f16(C[1][nt], A[1], B);
        }
    }

    #pragma unroll
    for (int mt = 0; mt < 2; mt++) {
        int rbase = m0 + wm * 32 + mt * 16 + grp;
        #pragma unroll
        for (int nt = 0; nt < 7; nt++) {
            int n0 = wn * 56 + nt * 8 + 2 * tg;
            __half2 lo2 = __floats2half2_rn(ftanh(C[mt][nt][0]), ftanh(C[mt][nt][1]));
            __half2 hi2 = __floats2half2_rn(ftanh(C[mt][nt][2]), ftanh(C[mt][nt][3]));
            *(__half2*)(g_xmixh + rbase * NC + n0) = lo2;
            *(__half2*)(g_xmixh + (rbase + 8) * NC + n0) = hi2;
        }
    }
}

// ---------------- per-node aggregation: contiguous streaming edges --------
__global__ void __launch_bounds__(256) node_kernel(
    const float* __restrict__ h, const float* __restrict__ x, const float* __restrict__ v,
    const float* __restrict__ w_p1, const float* __restrict__ b_p1,
    const float* __restrict__ w_p2, const float* __restrict__ b_p2,
    const float* __restrict__ w_n1, const float* __restrict__ b_n1,
    const float* __restrict__ w_n2, const float* __restrict__ b_n2,
    const float* __restrict__ w_v1, const float* __restrict__ b_v1,
    const float* __restrict__ w_v2, const float* __restrict__ w_vmix,
    float* __restrict__ out)
{
    __shared__ float sh[8 * 448];
    int wid = threadIdx.x >> 5, lane = threadIdx.x & 31;
    float* ws = sh + wid * 448;
    int node = blockIdx.x * 8 + wid;
    int s = g_offsets[node], e = g_offsets[node + 1];

    const unsigned FULL = 0xffffffffu;

    float acch[NH] = {0,0,0,0,0,0,0};
    float cb0[7] = {0,0,0,0,0,0,0};
    float cb1[7] = {0,0,0,0,0,0,0};
    float cb2[7] = {0,0,0,0,0,0,0};

    int p = s;
    for (; p + 3 < e; p += 4) {
        float he[4], at[4], dv[4];
        #pragma unroll
        for (int u = 0; u < 4; u++) {
            he[u] = g_hedgeR[(p + u) * FD + lane];
            at[u] = (lane < NH) ? g_att[(p + u) * NH + lane] : 0.0f;
            dv[u] = (lane < 3) ? g_dir[(p + u) * 3 + lane] : 0.0f;
        }
        float dd[4][3];
        #pragma unroll
        for (int u = 0; u < 4; u++) {
            dd[u][0] = __shfl_sync(FULL, dv[u], 0);
            dd[u][1] = __shfl_sync(FULL, dv[u], 1);
            dd[u][2] = __shfl_sync(FULL, dv[u], 2);
        }
        #pragma unroll
        for (int k = 0; k < NH; k++)
            #pragma unroll
            for (int u = 0; u < 4; u++)
                acch[k] += he[u] * __shfl_sync(FULL, at[u], k);
        #pragma unroll
        for (int j = 0; j < 7; j++) {
            #pragma unroll
            for (int u = 0; u < 4; u++) {
                float xm = __half2float(g_xmixh[(p + u) * NC + lane + 32 * j]);
                cb0[j] += dd[u][0] * xm;
                cb1[j] += dd[u][1] * xm;
                cb2[j] += dd[u][2] * xm;
            }
        }
    }
    for (; p < e; p++) {
        float he0 = g_hedgeR[p * FD + lane];
        float at0 = (lane < NH) ? g_att[p * NH + lane] : 0.0f;
        float dv0 = (lane < 3) ? g_dir[p * 3 + lane] : 0.0f;
        float d00 = __shfl_sync(FULL, dv0, 0), d01 = __shfl_sync(FULL, dv0, 1), d02 = __shfl_sync(FULL, dv0, 2);
        #pragma unroll
        for (int k = 0; k < NH; k++)
            acch[k] += he0 * __shfl_sync(FULL, at0, k);
        #pragma unroll
        for (int j = 0; j < 7; j++) {
            float xm0 = __half2float(g_xmixh[p * NC + lane + 32 * j]);
            cb0[j] += d00 * xm0;
            cb1[j] += d01 * xm0;
            cb2[j] += d02 * xm0;
        }
    }

    #pragma unroll
    for (int k = 0; k < NH; k++) ws[224 + lane * NH + k] = acch[k];

    float rden = 1.0f / fmaxf((float)(e - s), 1.0f);
    float vp0 = 0, vp1 = 0, vp2 = 0;
    #pragma unroll
    for (int j = 0; j < 7; j++) {
        int c = lane + 32 * j;
        float m0 = cb0[j] * rden, m1 = cb1[j] * rden, m2 = cb2[j] * rden;
        ws[c] = m0*m0 + m1*m1 + m2*m2;
        float wv = __ldg(&w_vmix[c]);
        vp0 += wv * m0; vp1 += wv * m1; vp2 += wv * m2;
    }
    #pragma unroll
    for (int off = 16; off; off >>= 1) {
        vp0 += __shfl_xor_sync(FULL, vp0, off);
        vp1 += __shfl_xor_sync(FULL, vp1, off);
        vp2 += __shfl_xor_sync(FULL, vp2, off);
    }
    __syncwarp();

    float o1 = __ldg(&b_p1[lane]);
    for (int c = 0; c < NC; c++) o1 += ws[c] * __ldg(&w_p1[c * 32 + lane]);
    o1 = siluf(o1);
    float o2 = __ldg(&b_p2[lane]);
    for (int c = 0; c < 32; c++)
        o2 += __shfl_sync(FULL, o1, c) * __ldg(&w_p2[c * 32 + lane]);
    float hspat = siluf(o2);

    float hv = h[node * 32 + lane];
    float n1 = __ldg(&b_n1[lane]);
    for (int c = 0; c < 32; c++)
        n1 += __shfl_sync(FULL, hv, c) * __ldg(&w_n1[c * 32 + lane]);
    for (int c = 0; c < NC; c++)
        n1 += ws[224 + c] * __ldg(&w_n1[(32 + c) * 32 + lane]);
    for (int c = 0; c < 32; c++)
        n1 += __shfl_sync(FULL, hspat, c) * __ldg(&w_n1[(256 + c) * 32 + lane]);
    n1 = siluf(n1);
    float n2 = __ldg(&b_n2[lane]);
    for (int c = 0; c < 32; c++)
        n2 += __shfl_sync(FULL, n1, c) * __ldg(&w_n2[c * 32 + lane]);
    float hup = hv + siluf(n2);
    out[node * 32 + lane] = hup;

    float v1 = __ldg(&b_v1[lane]);
    for (int c = 0; c < 32; c++)
        v1 += __shfl_sync(FULL, hv, c) * __ldg(&w_v1[c * 32 + lane]);
    v1 = siluf(v1);
    float sv = v1 * __ldg(&w_v2[lane]);
    #pragma unroll
    for (int off = 16; off; off >>= 1) sv += __shfl_xor_sync(FULL, sv, off);
    float scale = 2.0f / (1.0f + __expf(-sv));

    if (lane < 3) {
        float dv = (lane == 0) ? vp0 : ((lane == 1) ? vp1 : vp2);
        float vu = scale * v[node * 3 + lane] + dv;
        out[NN * 32 + node * 3 + lane] = x[node * 3 + lane] + vu;
        out[NN * 32 + NN * 3 + node * 3 + lane] = vu;
    }
}

// ---------------- launch ----------------
extern "C" void kernel_launch(void* const* d_in, const int* in_sizes, int n_in,
                              void* d_out, int out_size)
{
    const float* h  = (const float*)d_in[0];
    const float* x  = (const float*)d_in[1];
    const float* v  = (const float*)d_in[2];
    const int*   pl = (const int*)d_in[3];

    int edge_smem = (128 * ACTS + 128 * FBS + 128 + 56 + 32 + 32 + 8) * 4;  // ~66.6 KB
    int gemm_smem = (64 * SEMH + 2048 + 448) * 4;                            // ~39.6 KB
    cudaFuncSetAttribute(edge_kernel, cudaFuncAttributeMaxDynamicSharedMemorySize, edge_smem);
    cudaFuncSetAttribute(gemm_kernel, cudaFuncAttributeMaxDynamicSharedMemorySize, gemm_smem);

    zero_kernel<<<(NN + 255) / 256, 256>>>();
    count_kernel<<<(NP + 255) / 256, 256>>>(pl);
    wsplit_kernel<<<(8704 + 112 * NC + 255) / 256, 256>>>(
        (const float*)d_in[4], (const float*)d_in[6],
        (const float*)d_in[8], (const float*)d_in[10],
        (const float*)d_in[23]);
    scan1_kernel<<<40, 256>>>();
    scan2_kernel<<<1, 64>>>();
    scan3_kernel<<<40, 256>>>();
    scatter_kernel<<<(NP + 255) / 256, 256>>>(pl);
    edge_kernel<<<NP / 128, 128, edge_smem>>>(
        h, x, pl,
        (const float*)d_in[5], (const float*)d_in[7],
        (const float*)d_in[9], (const float*)d_in[11]);
    softmax_kernel<<<NN / 8, 256>>>();
    gemm_kernel<<<NP / 64, 256, gemm_smem>>>();

    node_kernel<<<NN / 8, 256>>>(
        h, x, v,
        (const float*)d_in[16], (const float*)d_in[17],   // w_p1, b_p1
        (const float*)d_in[18], (const float*)d_in[19],   // w_p2, b_p2
        (const float*)d_in[12], (const float*)d_in[13],   // w_n1, b_n1
        (const float*)d_in[14], (const float*)d_in[15],   // w_n2, b_n2
        (const float*)d_in[20], (const float*)d_in[21],   // w_v1, b_v1
        (const float*)d_in[22], (const float*)d_in[24],   // w_v2, w_vmix
        (float*)d_out);
}

// round 17
// speedup vs baseline: 1.9946x; 1.1519x over previous
#include <cuda_runtime.h>
#include <cuda_fp16.h>
#include <math.h>

#define NP 160000
#define NN 10000
#define FD 32
#define NH 7
#define NC 224
#define NRBF 50

// ---------------- scratch (device globals; all per-edge arrays CSR-ordered) --
__device__ float  g_hedgeR[NP * FD];
__device__ float  g_logits[NP * NH];
__device__ float  g_att[NP * NH];
__device__ float  g_dir[NP * 3];
__device__ __half g_xmixh[NP * NC];
__device__ int    g_counts[NN];
__device__ int    g_cursor[NN];
__device__ int    g_offsets[NN + 1];
__device__ int    g_order[NP];
__device__ int    g_bsum[40];
__device__ int    g_boff[40];

// fp16 k-pair-packed weights (row = k/2, col = n): half2 = (w[2r][n], w[2r+1][n])
__device__ __half2 g_w1h2[32 * 56];    // stage1: K=64, N=56 (50 used)
__device__ __half2 g_w2ah2[32 * 32];   // stage2 h_cat part: K=64, N=32
__device__ __half2 g_w2bh2[32 * 32];   // stage2 filt part: K=64 (57 used), N=32
__device__ __half2 g_w3h2[16 * 32];    // stage3: K=32, N=32
__device__ __half2 g_w4h2[16 * 8];     // stage4: K=32, N=8 (7 used)
__device__ __half2 g_wxh2[112 * NC];   // xmix GEMM: K=224, N=224

__device__ __forceinline__ float siluf(float z) { return z / (1.0f + __expf(-z)); }
__device__ __forceinline__ float ftanh(float z) {
    float e = __expf(2.0f * z);
    return 1.0f - __fdividef(2.0f, e + 1.0f);
}

// fp16 HMMA m16n8k16, fp32 accumulate
__device__ __forceinline__ void mma_f16(float c[4], const unsigned a[4], const unsigned b[2]) {
    asm("mma.sync.aligned.m16n8k16.row.col.f32.f16.f16.f32 "
        "{%0,%1,%2,%3}, {%4,%5,%6,%7}, {%8,%9}, {%0,%1,%2,%3};"
        : "+f"(c[0]), "+f"(c[1]), "+f"(c[2]), "+f"(c[3])
        : "r"(a[0]), "r"(a[1]), "r"(a[2]), "r"(a[3]), "r"(b[0]), "r"(b[1]));
}
// A fragment from half2 smem array (stride in half2 units)
__device__ __forceinline__ void load_a_h2(const __half2* base, int stride, int r,
                                          int kg2, int grp, int tg, unsigned A[4]) {
    A[0] = *(const unsigned*)&base[(r + grp) * stride + kg2 + tg];
    A[1] = *(const unsigned*)&base[(r + grp + 8) * stride + kg2 + tg];
    A[2] = *(const unsigned*)&base[(r + grp) * stride + kg2 + tg + 4];
    A[3] = *(const unsigned*)&base[(r + grp + 8) * stride + kg2 + tg + 4];
}

// ---------------- weight pre-pack prep ----------------
__global__ void wsplit_kernel(const float* __restrict__ wmlp, const float* __restrict__ we1,
                              const float* __restrict__ we2,  const float* __restrict__ watt,
                              const float* __restrict__ wx) {
    int t = blockIdx.x * 256 + threadIdx.x;
    if (t < 1792) {                                 // w1h2 [32][56]
        int k2 = t / 56, n = t - k2 * 56;
        float a = (n < NRBF) ? wmlp[(2 * k2) * NRBF + n] : 0.0f;
        float b = (n < NRBF) ? wmlp[(2 * k2 + 1) * NRBF + n] : 0.0f;
        g_w1h2[t] = __floats2half2_rn(a, b);
    } else if (t < 2816) {                          // w2ah2 [32][32]
        int i = t - 1792;
        int k2 = i >> 5, n = i & 31;
        g_w2ah2[i] = __floats2half2_rn(we1[(2 * k2) * FD + n], we1[(2 * k2 + 1) * FD + n]);
    } else if (t < 3840) {                          // w2bh2 [32][32]
        int i = t - 2816;
        int k2 = i >> 5, n = i & 31;
        float vals[2];
        #pragma unroll
        for (int u = 0; u < 2; u++) {
            int k = 2 * k2 + u;
            vals[u] = (k < NRBF) ? we1[(64 + k) * FD + n]
                    : ((k == NRBF) ? we1[114 * FD + n] : 0.0f);
        }
        g_w2bh2[i] = __floats2half2_rn(vals[0], vals[1]);
    } else if (t < 4352) {                          // w3h2 [16][32]
        int i = t - 3840;
        int k2 = i >> 5, n = i & 31;
        g_w3h2[i] = __floats2half2_rn(we2[(2 * k2) * FD + n], we2[(2 * k2 + 1) * FD + n]);
    } else if (t < 4480) {                          // w4h2 [16][8]
        int i = t - 4352;
        int k2 = i >> 3, n = i & 7;
        float a = (n < NH) ? watt[(2 * k2) * NH + n] : 0.0f;
        float b = (n < NH) ? watt[(2 * k2 + 1) * NH + n] : 0.0f;
        g_w4h2[i] = __floats2half2_rn(a, b);
    } else if (t < 4480 + 112 * NC) {               // wxh2 [112][224]
        int i = t - 4480;
        int k2 = i / NC, n = i - k2 * NC;
        g_wxh2[i] = __floats2half2_rn(wx[(2 * k2) * NC + n], wx[(2 * k2 + 1) * NC + n]);
    }
}

// ---------------- CSR build ----------------
__global__ void zero_kernel() {
    int i = blockIdx.x * 256 + threadIdx.x;
    if (i < NN) { g_counts[i] = 0; g_cursor[i] = 0; }
}

__global__ void count_kernel(const int* __restrict__ pl) {
    int p = blockIdx.x * 256 + threadIdx.x;
    if (p < NP) atomicAdd(&g_counts[pl[p]], 1);
}

__global__ void scan1_kernel() {
    __shared__ int sh[256];
    int b = blockIdx.x, t = threadIdx.x, idx = b * 256 + t;
    int v = (idx < NN) ? g_counts[idx] : 0;
    sh[t] = v;
    __syncthreads();
    #pragma unroll
    for (int off = 1; off < 256; off <<= 1) {
        int a = (t >= off) ? sh[t - off] : 0;
        __syncthreads();
        sh[t] += a;
        __syncthreads();
    }
    if (idx < NN) g_offsets[idx + 1] = sh[t];
    if (t == 255) g_bsum[b] = sh[255];
    if (b == 0 && t == 0) g_offsets[0] = 0;
}
__global__ void scan2_kernel() {
    __shared__ int sh[64];
    int t = threadIdx.x;
    int v = (t < 40) ? g_bsum[t] : 0;
    sh[t] = v;
    __syncthreads();
    #pragma unroll
    for (int off = 1; off < 64; off <<= 1) {
        int a = (t >= off) ? sh[t - off] : 0;
        __syncthreads();
        sh[t] += a;
        __syncthreads();
    }
    if (t < 40) g_boff[t] = sh[t] - v;
}
__global__ void scan3_kernel() {
    int b = blockIdx.x, idx = b * 256 + threadIdx.x;
    if (idx < NN) g_offsets[idx + 1] += g_boff[b];
}

__global__ void scatter_kernel(const int* __restrict__ pl) {
    int p = blockIdx.x * 256 + threadIdx.x;
    if (p < NP) {
        int i = pl[p];
        int pos = g_offsets[i] + atomicAdd(&g_cursor[i], 1);
        g_order[pos] = p;
    }
}

// ---------------- edge model: all stages fp16 HMMA ----------
#define ACT2 36   // half2 stride; A-frag addrs grp*4+tg distinct mod 32
#define FB2  36
__global__ void __launch_bounds__(128, 3) edge_kernel(
    const float* __restrict__ h, const float* __restrict__ x,
    const int* __restrict__ pl,
    const float* __restrict__ bmlp, const float* __restrict__ be1,
    const float* __restrict__ be2,  const float* __restrict__ batt)
{
    extern __shared__ float smf[];
    __half2* acth  = (__half2*)smf;             // [128][36]
    __half2* fbufh = acth + 128 * ACT2;         // [128][36]
    float* dvec = (float*)(fbufh + 128 * FB2);  // [128]
    float* s_bm = dvec + 128;                   // [56]
    float* s_b1 = s_bm + 56;                    // [32]
    float* s_b2 = s_b1 + 32;                    // [32]
    float* s_ba = s_b2 + 32;                    // [8]

    int tid = threadIdx.x;
    int p0 = blockIdx.x * 128;

    if (tid < 56) s_bm[tid] = (tid < NRBF) ? bmlp[tid] : 0.0f;
    if (tid < 32) { s_b1[tid] = be1[tid]; s_b2[tid] = be2[tid]; }
    if (tid < 8)  s_ba[tid] = (tid < NH) ? batt[tid] : 0.0f;

    // stage h_cat (fp16) + d + dir at NEW index; pair = g_order[new]
    {
        int m = tid, pnew = p0 + m;
        int porig = g_order[pnew];
        int i = pl[porig], j = pl[NP + porig];
        const float4* si = (const float4*)(h + i * FD);
        const float4* sj = (const float4*)(h + j * FD);
        __half2* dst = acth + m * ACT2;
        #pragma unroll
        for (int q = 0; q < 8; q++) {
            float4 a = si[q];
            dst[2 * q]     = __floats2half2_rn(a.x, a.y);
            dst[2 * q + 1] = __floats2half2_rn(a.z, a.w);
        }
        #pragma unroll
        for (int q = 0; q < 8; q++) {
            float4 a = sj[q];
            dst[16 + 2 * q]     = __floats2half2_rn(a.x, a.y);
            dst[16 + 2 * q + 1] = __floats2half2_rn(a.z, a.w);
        }
        // zero fbuf k-pad cols 28..31 (halfs 56..63)
        __half2 z = __floats2half2_rn(0.0f, 0.0f);
        fbufh[m * FB2 + 28] = z; fbufh[m * FB2 + 29] = z;
        fbufh[m * FB2 + 30] = z; fbufh[m * FB2 + 31] = z;

        float r0 = x[j*3]   - x[i*3];
        float r1 = x[j*3+1] - x[i*3+1];
        float r2 = x[j*3+2] - x[i*3+2];
        float d = sqrtf(r0*r0 + r1*r1 + r2*r2);
        float inv = 1.0f / (d + 1e-5f);
        g_dir[pnew*3]   = r0 * inv;
        g_dir[pnew*3+1] = r1 * inv;
        g_dir[pnew*3+2] = r2 * inv;
        dvec[m] = d;
    }
    __syncthreads();

    int lane = tid & 31, wid = tid >> 5;
    int grp = lane >> 2, tg = lane & 3;
    int rt0 = wid * 16, rt1 = wid * 16 + 64;
    unsigned A[2][4];

    float C2a[2][4][4];
    #pragma unroll
    for (int mt = 0; mt < 2; mt++)
        #pragma unroll
        for (int nt = 0; nt < 4; nt++)
            #pragma unroll
            for (int q = 0; q < 4; q++) C2a[mt][nt][q] = 0.0f;

    // ======== fused stage1 (h_cat@w1) + stage2a (h_cat@w2a); K=64 ========
    {
        float C1[2][7][4];
        #pragma unroll
        for (int mt = 0; mt < 2; mt++)
            #pragma unroll
            for (int nt = 0; nt < 7; nt++)
                #pragma unroll
                for (int q = 0; q < 4; q++) C1[mt][nt][q] = 0.0f;
        #pragma unroll
        for (int ks = 0; ks < 4; ks++) {
            int kg2 = ks * 8;
            load_a_h2(acth, ACT2, rt0, kg2, grp, tg, A[0]);
            load_a_h2(acth, ACT2, rt1, kg2, grp, tg, A[1]);
            #pragma unroll
            for (int nt = 0; nt < 7; nt++) {
                unsigned B[2];
                B[0] = *(const unsigned*)&g_w1h2[(kg2 + tg) * 56 + nt * 8 + grp];
                B[1] = *(const unsigned*)&g_w1h2[(kg2 + tg + 4) * 56 + nt * 8 + grp];
                mma_f16(C1[0][nt], A[0], B);
                mma_f16(C1[1][nt], A[1], B);
            }
            #pragma unroll
            for (int nt = 0; nt < 4; nt++) {
                unsigned B[2];
                B[0] = *(const unsigned*)&g_w2ah2[(kg2 + tg) * 32 + nt * 8 + grp];
                B[1] = *(const unsigned*)&g_w2ah2[(kg2 + tg + 4) * 32 + nt * 8 + grp];
                mma_f16(C2a[0][nt], A[0], B);
                mma_f16(C2a[1][nt], A[1], B);
            }
        }
        // stage-1 epilogue (fp32): fbuf = [rbf(d)*(C1+bm) | d | 0]
        #pragma unroll
        for (int mt = 0; mt < 2; mt++) {
            int rr = (mt == 0) ? rt0 : rt1;
            float dlo = dvec[rr + grp], dhi = dvec[rr + grp + 8];
            #pragma unroll
            for (int nt = 0; nt < 7; nt++) {
                float vlo[2], vhi[2];
                #pragma unroll
                for (int half = 0; half < 2; half++) {
                    int n = nt * 8 + 2 * tg + half;
                    float clo = C1[mt][nt][half], chi = C1[mt][nt][2 + half];
                    float ce = (float)n * (5.0f / 49.0f);
                    if (n < NRBF) {
                        float glo = __expf(-10.0f * (dlo - ce) * (dlo - ce));
                        float ghi = __expf(-10.0f * (dhi - ce) * (dhi - ce));
                        vlo[half] = glo * (clo + s_bm[n]);
                        vhi[half] = ghi * (chi + s_bm[n]);
                    } else if (n == NRBF) { vlo[half] = dlo; vhi[half] = dhi; }
                    else { vlo[half] = 0.0f; vhi[half] = 0.0f; }
                }
                fbufh[(rr + grp) * FB2 + nt * 4 + tg] = __floats2half2_rn(vlo[0], vlo[1]);
                fbufh[(rr + grp + 8) * FB2 + nt * 4 + tg] = __floats2half2_rn(vhi[0], vhi[1]);
            }
        }
    }
    __syncwarp();

    // ======== stage 2b: C2a += fbuf @ w2b; K=64 ========
    {
        #pragma unroll
        for (int ks = 0; ks < 4; ks++) {
            int kg2 = ks * 8;
            load_a_h2(fbufh, FB2, rt0, kg2, grp, tg, A[0]);
            load_a_h2(fbufh, FB2, rt1, kg2, grp, tg, A[1]);
            #pragma unroll
            for (int nt = 0; nt < 4; nt++) {
                unsigned B[2];
                B[0] = *(const unsigned*)&g_w2bh2[(kg2 + tg) * 32 + nt * 8 + grp];
                B[1] = *(const unsigned*)&g_w2bh2[(kg2 + tg + 4) * 32 + nt * 8 + grp];
                mma_f16(C2a[0][nt], A[0], B);
                mma_f16(C2a[1][nt], A[1], B);
            }
        }
        // epilogue: silu -> acth cols 0..15 (half2)
        #pragma unroll
        for (int mt = 0; mt < 2; mt++) {
            int rr = (mt == 0) ? rt0 : rt1;
            #pragma unroll
            for (int nt = 0; nt < 4; nt++) {
                int n0 = nt * 8 + 2 * tg;
                acth[(rr + grp) * ACT2 + nt * 4 + tg] =
                    __floats2half2_rn(siluf(C2a[mt][nt][0] + s_b1[n0]),
                                      siluf(C2a[mt][nt][1] + s_b1[n0 + 1]));
                acth[(rr + grp + 8) * ACT2 + nt * 4 + tg] =
                    __floats2half2_rn(siluf(C2a[mt][nt][2] + s_b1[n0]),
                                      siluf(C2a[mt][nt][3] + s_b1[n0 + 1]));
            }
        }
    }
    __syncwarp();

    // ======== stage 3: a3 = act @ w3; K=32 ========
    {
        float C3[2][4][4];
        #pragma unroll
        for (int mt = 0; mt < 2; mt++)
            #pragma unroll
            for (int nt = 0; nt < 4; nt++)
                #pragma unroll
                for (int q = 0; q < 4; q++) C3[mt][nt][q] = 0.0f;
        #pragma unroll
        for (int ks = 0; ks < 2; ks++) {
            int kg2 = ks * 8;
            load_a_h2(acth, ACT2, rt0, kg2, grp, tg, A[0]);
            load_a_h2(acth, ACT2, rt1, kg2, grp, tg, A[1]);
            #pragma unroll
            for (int nt = 0; nt < 4; nt++) {
                unsigned B[2];
                B[0] = *(const unsigned*)&g_w3h2[(kg2 + tg) * 32 + nt * 8 + grp];
                B[1] = *(const unsigned*)&g_w3h2[(kg2 + tg + 4) * 32 + nt * 8 + grp];
                mma_f16(C3[0][nt], A[0], B);
                mma_f16(C3[1][nt], A[1], B);
            }
        }
        #pragma unroll
        for (int mt = 0; mt < 2; mt++) {
            int rr = (mt == 0) ? rt0 : rt1;
            int plo = p0 + rr + grp, phi = plo + 8;
            #pragma unroll
            for (int nt = 0; nt < 4; nt++) {
                int n = nt * 8 + 2 * tg;
                float a0 = C3[mt][nt][0] + s_b2[n], a1 = C3[mt][nt][1] + s_b2[n + 1];
                float a2 = C3[mt][nt][2] + s_b2[n], a3v = C3[mt][nt][3] + s_b2[n + 1];
                fbufh[(rr + grp) * FB2 + nt * 4 + tg] = __floats2half2_rn(a0, a1);
                fbufh[(rr + grp + 8) * FB2 + nt * 4 + tg] = __floats2half2_rn(a2, a3v);
                *(float2*)(g_hedgeR + plo * FD + n) = make_float2(a0, a1);
                *(float2*)(g_hedgeR + phi * FD + n) = make_float2(a2, a3v);
            }
        }
    }
    __syncwarp();

    // ======== stage 4: logits = celu(a3 @ w4 + b_att); K=32, N=8 ========
    {
        float C4[2][4];
        #pragma unroll
        for (int mt = 0; mt < 2; mt++)
            #pragma unroll
            for (int q = 0; q < 4; q++) C4[mt][q] = 0.0f;
        #pragma unroll
        for (int ks = 0; ks < 2; ks++) {
            int kg2 = ks * 8;
            load_a_h2(fbufh, FB2, rt0, kg2, grp, tg, A[0]);
            load_a_h2(fbufh, FB2, rt1, kg2, grp, tg, A[1]);
            unsigned B[2];
            B[0] = *(const unsigned*)&g_w4h2[(kg2 + tg) * 8 + grp];
            B[1] = *(const unsigned*)&g_w4h2[(kg2 + tg + 4) * 8 + grp];
            mma_f16(C4[0], A[0], B);
            mma_f16(C4[1], A[1], B);
        }
        #pragma unroll
        for (int mt = 0; mt < 2; mt++) {
            int rr = (mt == 0) ? rt0 : rt1;
            int plo = p0 + rr + grp, phi = plo + 8;
            #pragma unroll
            for (int half = 0; half < 2; half++) {
                int n = 2 * tg + half;
                if (n < NH) {
                    float zlo = C4[mt][half] + s_ba[n];
                    float zhi = C4[mt][2 + half] + s_ba[n];
                    g_logits[plo * NH + n] = (zlo > 0.0f) ? zlo : 2.0f * (__expf(0.5f * zlo) - 1.0f);
                    g_logits[phi * NH + n] = (zhi > 0.0f) ? zhi : 2.0f * (__expf(0.5f * zhi) - 1.0f);
                }
            }
        }
    }
}

// ---------------- scatter softmax: contiguous edges -------
__global__ void __launch_bounds__(256) softmax_kernel() {
    int node = blockIdx.x * 8 + (threadIdx.x >> 5);
    int lane = threadIdx.x & 31;
    int s = g_offsets[node], e = g_offsets[node + 1];
    int cnt = e - s;
    const unsigned FULL = 0xffffffffu;

    if (cnt <= 32) {
        if (cnt == 0) return;
        bool have = lane < cnt;
        int p = s + (have ? lane : 0);
        float lg[NH];
        #pragma unroll
        for (int k = 0; k < NH; k++) lg[k] = g_logits[p * NH + k];

        float mx[NH], ex[NH], sm[NH];
        #pragma unroll
        for (int k = 0; k < NH; k++) {
            mx[k] = have ? lg[k] : -1e30f;
            #pragma unroll
            for (int off = 16; off; off >>= 1)
                mx[k] = fmaxf(mx[k], __shfl_xor_sync(FULL, mx[k], off));
            ex[k] = have ? __expf(lg[k] - mx[k]) : 0.0f;
            sm[k] = ex[k];
            #pragma unroll
            for (int off = 16; off; off >>= 1)
                sm[k] += __shfl_xor_sync(FULL, sm[k], off);
        }
        if (have) {
            #pragma unroll
            for (int k = 0; k < NH; k++)
                g_att[p * NH + k] = ex[k] / sm[k];
        }
    } else {
        float mx[NH];
        #pragma unroll
        for (int k = 0; k < NH; k++) mx[k] = -1e30f;
        for (int p = s + lane; p < e; p += 32)
            #pragma unroll
            for (int k = 0; k < NH; k++) mx[k] = fmaxf(mx[k], g_logits[p * NH + k]);
        #pragma unroll
        for (int k = 0; k < NH; k++)
            #pragma unroll
            for (int off = 16; off; off >>= 1)
                mx[k] = fmaxf(mx[k], __shfl_xor_sync(FULL, mx[k], off));

        float sm[NH];
        #pragma unroll
        for (int k = 0; k < NH; k++) sm[k] = 0.0f;
        for (int p = s + lane; p < e; p += 32)
            #pragma unroll
            for (int k = 0; k < NH; k++) sm[k] += __expf(g_logits[p * NH + k] - mx[k]);
        #pragma unroll
        for (int k = 0; k < NH; k++)
            #pragma unroll
            for (int off = 16; off; off >>= 1)
                sm[k] += __shfl_xor_sync(FULL, sm[k], off);

        for (int p = s + lane; p < e; p += 32)
            #pragma unroll
            for (int k = 0; k < NH; k++)
                g_att[p * NH + k] = __expf(g_logits[p * NH + k] - mx[k]) / sm[k];
    }
}

// ---------------- big GEMM via fp16 HMMA m16n8k16 -----------
#define SEMH 116
__global__ void __launch_bounds__(256, 3) gemm_kernel() {
    extern __shared__ float smf[];
    __half2* semh = (__half2*)smf;            // [64][116]
    float* s_he  = smf + 64 * SEMH;           // 2048
    float* s_att = s_he + 2048;               // 448

    int tid = threadIdx.x;
    int m0 = blockIdx.x * 64;

    {
        int f = tid & 31, mrow = tid >> 5;
        #pragma unroll
        for (int it = 0; it < 8; it++) {
            int m = mrow + 8 * it;
            s_he[m * 32 + f] = g_hedgeR[(m0 + m) * FD + f];
        }
    }
    for (int t = tid; t < 448; t += 256) s_att[t] = g_att[m0 * NH + t];
    __syncthreads();

    for (int idx = tid; idx < 64 * 112; idx += 256) {
        int m = idx / 112, k2 = idx - m * 112;
        int k = 2 * k2;
        float v0 = s_he[m * 32 + k / 7] * s_att[m * 7 + (k % 7)];
        float v1 = s_he[m * 32 + (k + 1) / 7] * s_att[m * 7 + ((k + 1) % 7)];
        semh[m * SEMH + k2] = __floats2half2_rn(v0, v1);
    }
    __syncthreads();

    int lane = tid & 31, wid = tid >> 5;
    int wm = wid & 1;
    int wn = wid >> 1;
    int grp = lane >> 2, tg = lane & 3;

    float C[2][7][4];
    #pragma unroll
    for (int mt = 0; mt < 2; mt++)
        #pragma unroll
        for (int nt = 0; nt < 7; nt++)
            #pragma unroll
            for (int q = 0; q < 4; q++) C[mt][nt][q] = 0.0f;

    #pragma unroll 2
    for (int ks = 0; ks < 14; ks++) {
        int kg2 = ks * 8;

        unsigned A[2][4];
        #pragma unroll
        for (int mt = 0; mt < 2; mt++)
            load_a_h2(semh, SEMH, wm * 32 + mt * 16, kg2, grp, tg, A[mt]);

        #pragma unroll
        for (int nt = 0; nt < 7; nt++) {
            int n0 = wn * 56 + nt * 8;
            unsigned B[2];
            B[0] = *(const unsigned*)&g_wxh2[(kg2 + tg) * NC + n0 + grp];
            B[1] = *(const unsigned*)&g_wxh2[(kg2 + tg + 4) * NC + n0 + grp];
            mma_f16(C[0][nt], A[0], B);
            mma_f16(C[1][nt], A[1], B);
        }
    }

    #pragma unroll
    for (int mt = 0; mt < 2; mt++) {
        int rbase = m0 + wm * 32 + mt * 16 + grp;
        #pragma unroll
        for (int nt = 0; nt < 7; nt++) {
            int n0 = wn * 56 + nt * 8 + 2 * tg;
            __half2 lo2 = __floats2half2_rn(ftanh(C[mt][nt][0]), ftanh(C[mt][nt][1]));
            __half2 hi2 = __floats2half2_rn(ftanh(C[mt][nt][2]), ftanh(C[mt][nt][3]));
            *(__half2*)(g_xmixh + rbase * NC + n0) = lo2;
            *(__half2*)(g_xmixh + (rbase + 8) * NC + n0) = hi2;
        }
    }
}

// ---------------- per-node aggregation: contiguous streaming edges --------
__global__ void __launch_bounds__(256) node_kernel(
    const float* __restrict__ h, const float* __restrict__ x, const float* __restrict__ v,
    const float* __restrict__ w_p1, const float* __restrict__ b_p1,
    const float* __restrict__ w_p2, const float* __restrict__ b_p2,
    const float* __restrict__ w_n1, const float* __restrict__ b_n1,
    const float* __restrict__ w_n2, const float* __restrict__ b_n2,
    const float* __restrict__ w_v1, const float* __restrict__ b_v1,
    const float* __restrict__ w_v2, const float* __restrict__ w_vmix,
    float* __restrict__ out)
{
    __shared__ float sh[8 * 448];
    int wid = threadIdx.x >> 5, lane = threadIdx.x & 31;
    float* ws = sh + wid * 448;
    int node = blockIdx.x * 8 + wid;
    int s = g_offsets[node], e = g_offsets[node + 1];

    const unsigned FULL = 0xffffffffu;

    float acch[NH] = {0,0,0,0,0,0,0};
    float cb0[7] = {0,0,0,0,0,0,0};
    float cb1[7] = {0,0,0,0,0,0,0};
    float cb2[7] = {0,0,0,0,0,0,0};

    int p = s;
    for (; p + 3 < e; p += 4) {
        float he[4], at[4], dv[4];
        #pragma unroll
        for (int u = 0; u < 4; u++) {
            he[u] = g_hedgeR[(p + u) * FD + lane];
            at[u] = (lane < NH) ? g_att[(p + u) * NH + lane] : 0.0f;
            dv[u] = (lane < 3) ? g_dir[(p + u) * 3 + lane] : 0.0f;
        }
        float dd[4][3];
        #pragma unroll
        for (int u = 0; u < 4; u++) {
            dd[u][0] = __shfl_sync(FULL, dv[u], 0);
            dd[u][1] = __shfl_sync(FULL, dv[u], 1);
            dd[u][2] = __shfl_sync(FULL, dv[u], 2);
        }
        #pragma unroll
        for (int k = 0; k < NH; k++)
            #pragma unroll
            for (int u = 0; u < 4; u++)
                acch[k] += he[u] * __shfl_sync(FULL, at[u], k);
        #pragma unroll
        for (int j = 0; j < 7; j++) {
            #pragma unroll
            for (int u = 0; u < 4; u++) {
                float xm = __half2float(g_xmixh[(p + u) * NC + lane + 32 * j]);
                cb0[j] += dd[u][0] * xm;
                cb1[j] += dd[u][1] * xm;
                cb2[j] += dd[u][2] * xm;
            }
        }
    }
    for (; p < e; p++) {
        float he0 = g_hedgeR[p * FD + lane];
        float at0 = (lane < NH) ? g_att[p * NH + lane] : 0.0f;
        float dv0 = (lane < 3) ? g_dir[p * 3 + lane] : 0.0f;
        float d00 = __shfl_sync(FULL, dv0, 0), d01 = __shfl_sync(FULL, dv0, 1), d02 = __shfl_sync(FULL, dv0, 2);
        #pragma unroll
        for (int k = 0; k < NH; k++)
            acch[k] += he0 * __shfl_sync(FULL, at0, k);
        #pragma unroll
        for (int j = 0; j < 7; j++) {
            float xm0 = __half2float(g_xmixh[p * NC + lane + 32 * j]);
            cb0[j] += d00 * xm0;
            cb1[j] += d01 * xm0;
            cb2[j] += d02 * xm0;
        }
    }

    #pragma unroll
    for (int k = 0; k < NH; k++) ws[224 + lane * NH + k] = acch[k];

    float rden = 1.0f / fmaxf((float)(e - s), 1.0f);
    float vp0 = 0, vp1 = 0, vp2 = 0;
    #pragma unroll
    for (int j = 0; j < 7; j++) {
        int c = lane + 32 * j;
        float m0 = cb0[j] * rden, m1 = cb1[j] * rden, m2 = cb2[j] * rden;
        ws[c] = m0*m0 + m1*m1 + m2*m2;
        float wv = __ldg(&w_vmix[c]);
        vp0 += wv * m0; vp1 += wv * m1; vp2 += wv * m2;
    }
    #pragma unroll
    for (int off = 16; off; off >>= 1) {
        vp0 += __shfl_xor_sync(FULL, vp0, off);
        vp1 += __shfl_xor_sync(FULL, vp1, off);
        vp2 += __shfl_xor_sync(FULL, vp2, off);
    }
    __syncwarp();

    float o1 = __ldg(&b_p1[lane]);
    for (int c = 0; c < NC; c++) o1 += ws[c] * __ldg(&w_p1[c * 32 + lane]);
    o1 = siluf(o1);
    float o2 = __ldg(&b_p2[lane]);
    for (int c = 0; c < 32; c++)
        o2 += __shfl_sync(FULL, o1, c) * __ldg(&w_p2[c * 32 + lane]);
    float hspat = siluf(o2);

    float hv = h[node * 32 + lane];
    float n1 = __ldg(&b_n1[lane]);
    for (int c = 0; c < 32; c++)
        n1 += __shfl_sync(FULL, hv, c) * __ldg(&w_n1[c * 32 + lane]);
    for (int c = 0; c < NC; c++)
        n1 += ws[224 + c] * __ldg(&w_n1[(32 + c) * 32 + lane]);
    for (int c = 0; c < 32; c++)
        n1 += __shfl_sync(FULL, hspat, c) * __ldg(&w_n1[(256 + c) * 32 + lane]);
    n1 = siluf(n1);
    float n2 = __ldg(&b_n2[lane]);
    for (int c = 0; c < 32; c++)
        n2 += __shfl_sync(FULL, n1, c) * __ldg(&w_n2[c * 32 + lane]);
    float hup = hv + siluf(n2);
    out[node * 32 + lane] = hup;

    float v1 = __ldg(&b_v1[lane]);
    for (int c = 0; c < 32; c++)
        v1 += __shfl_sync(FULL, hv, c) * __ldg(&w_v1[c * 32 + lane]);
    v1 = siluf(v1);
    float sv = v1 * __ldg(&w_v2[lane]);
    #pragma unroll
    for (int off = 16; off; off >>= 1) sv += __shfl_xor_sync(FULL, sv, off);
    float scale = 2.0f / (1.0f + __expf(-sv));

    if (lane < 3) {
        float dv = (lane == 0) ? vp0 : ((lane == 1) ? vp1 : vp2);
        float vu = scale * v[node * 3 + lane] + dv;
        out[NN * 32 + node * 3 + lane] = x[node * 3 + lane] + vu;
        out[NN * 32 + NN * 3 + node * 3 + lane] = vu;
    }
}

// ---------------- launch ----------------
extern "C" void kernel_launch(void* const* d_in, const int* in_sizes, int n_in,
                              void* d_out, int out_size)
{
    const float* h  = (const float*)d_in[0];
    const float* x  = (const float*)d_in[1];
    const float* v  = (const float*)d_in[2];
    const int*   pl = (const int*)d_in[3];

    int edge_smem = (128 * ACT2 + 128 * FB2) * 4 + (128 + 56 + 32 + 32 + 8) * 4;  // ~37.9 KB
    int gemm_smem = (64 * SEMH + 2048 + 448) * 4;                                  // ~39.6 KB
    cudaFuncSetAttribute(edge_kernel, cudaFuncAttributeMaxDynamicSharedMemorySize, edge_smem);
    cudaFuncSetAttribute(gemm_kernel, cudaFuncAttributeMaxDynamicSharedMemorySize, gemm_smem);

    zero_kernel<<<(NN + 255) / 256, 256>>>();
    count_kernel<<<(NP + 255) / 256, 256>>>(pl);
    wsplit_kernel<<<(4480 + 112 * NC + 255) / 256, 256>>>(
        (const float*)d_in[4], (const float*)d_in[6],
        (const float*)d_in[8], (const float*)d_in[10],
        (const float*)d_in[23]);
    scan1_kernel<<<40, 256>>>();
    scan2_kernel<<<1, 64>>>();
    scan3_kernel<<<40, 256>>>();
    scatter_kernel<<<(NP + 255) / 256, 256>>>(pl);
    edge_kernel<<<NP / 128, 128, edge_smem>>>(
        h, x, pl,
        (const float*)d_in[5], (const float*)d_in[7],
        (const float*)d_in[9], (const float*)d_in[11]);
    softmax_kernel<<<NN / 8, 256>>>();
    gemm_kernel<<<NP / 64, 256, gemm_smem>>>();

    node_kernel<<<NN / 8, 256>>>(
        h, x, v,
        (const float*)d_in[16], (const float*)d_in[17],   // w_p1, b_p1
        (const float*)d_in[18], (const float*)d_in[19],   // w_p2, b_p2
        (const float*)d_in[12], (const float*)d_in[13],   // w_n1, b_n1
        (const float*)d_in[14], (const float*)d_in[15],   // w_n2, b_n2
        (const float*)d_in[20], (const float*)d_in[21],   // w_v1, b_v1
        (const float*)d_in[22], (const float*)d_in[24],   // w_v2, w_vmix
        (float*)d_out);
}